// round 6
// baseline (speedup 1.0000x reference)
#include <cuda_runtime.h>
#include <cuda_bf16.h>
#include <math.h>
#include <stdint.h>

#define T_TOK   4096
#define D_MODEL 2048
#define FF      8192
#define NE      8
#define PM      40          // padded 128-row blocks
#define MAXT    40
#define KT1Q    16          // GEMM1 int8 k-blocks (D/128)
#define KT2     128         // GEMM2 k-tiles (FF/64)
#define NT2     16          // GEMM2 n-tiles (D/128)
#define BLKB    32768       // bf16 operand block: hi 16KB + lo 16KB (128 rows x 128B)
#define QBLK_A  32768       // int8 A block: slice0 16KB + slice1 16KB (128 rows x 128B)
#define QBLK_B  16384       // int8 B block: slice0 8KB + slice1 8KB (64 rows x 128B)

// ---------------- scratch ----------------
__device__ int   g_idx[T_TOK];
__device__ float g_w[T_TOK];
__device__ int   g_order[T_TOK];
__device__ int   g_off[NE + 1];
__device__ int   g_ptok[PM * 128];
__device__ int   g_tile_e[MAXT];
__device__ int   g_tile_gt[MAXT];
__device__ int   g_tile_m64[MAXT];
__device__ int   g_ntiles;
__device__ float g_sa[PM * 128];
__device__ float g_sb1[NE * FF];

__device__ __align__(128) char g_A  [(size_t)PM * KT1Q * QBLK_A];             // 21 MB int8
__device__ __align__(128) char g_B1q[(size_t)NE * (FF/64) * KT1Q * QBLK_B];   // 268 MB int8
__device__ __align__(128) char g_B2 [(size_t)NE * NT2 * KT2 * BLKB];          // 537 MB bf16
__device__ __align__(128) char g_H  [(size_t)PM * KT2 * BLKB];                // 168 MB bf16

// ---------------- helpers ----------------
__device__ __forceinline__ uint32_t s2u(const void* p) {
    uint32_t a;
    asm("{ .reg .u64 t; cvta.to.shared.u64 t, %1; cvt.u32.u64 %0, t; }" : "=r"(a) : "l"(p));
    return a;
}
__device__ __forceinline__ uint32_t pack2(float a, float b) {
    __nv_bfloat162 t = __floats2bfloat162_rn(a, b);
    return *(uint32_t*)&t;
}
__device__ __forceinline__ void split1(float v, float& hi, float& lo) {
    __nv_bfloat16 h = __float2bfloat16_rn(v);
    hi = __bfloat162float(h);
    lo = v - hi;
}
__device__ __forceinline__ float gelu_exact(float v) {
    return 0.5f * v * (1.0f + erff(v * 0.70710678118654752440f));
}
__device__ __forceinline__ void mbar_init(uint32_t m, uint32_t c) {
    asm volatile("mbarrier.init.shared::cta.b64 [%0], %1;" :: "r"(m), "r"(c) : "memory");
}
__device__ __forceinline__ void mbar_arrive(uint32_t m) {
    asm volatile("mbarrier.arrive.shared::cta.b64 _, [%0];" :: "r"(m) : "memory");
}
__device__ __forceinline__ void mbar_expect_tx(uint32_t m, uint32_t b) {
    asm volatile("mbarrier.arrive.expect_tx.shared::cta.b64 _, [%0], %1;"
                 :: "r"(m), "r"(b) : "memory");
}
__device__ __forceinline__ void mbar_wait(uint32_t m, uint32_t ph) {
    asm volatile(
        "{\n\t.reg .pred P;\n"
        "W_%=:\n\t"
        "mbarrier.try_wait.parity.acquire.cta.shared::cta.b64 P, [%0], %1, 0x989680;\n\t"
        "@P bra.uni D_%=;\n\t"
        "bra.uni W_%=;\n"
        "D_%=:\n\t}"
        :: "r"(m), "r"(ph) : "memory");
}
__device__ __forceinline__ void bulk_g2s(uint32_t dst, const void* src, uint32_t bytes,
                                         uint32_t mbar) {
    asm volatile(
        "cp.async.bulk.shared::cta.global.mbarrier::complete_tx::bytes [%0], [%1], %2, [%3];"
        :: "r"(dst), "l"(src), "r"(bytes), "r"(mbar) : "memory");
}
__device__ __forceinline__ void ldsm4(uint32_t& r0, uint32_t& r1, uint32_t& r2, uint32_t& r3,
                                      uint32_t a) {
    asm volatile("ldmatrix.sync.aligned.m8n8.x4.shared.b16 {%0,%1,%2,%3}, [%4];"
                 : "=r"(r0), "=r"(r1), "=r"(r2), "=r"(r3) : "r"(a));
}
__device__ __forceinline__ void mma_bf16(float* d, const uint32_t* a, const uint32_t* b) {
    asm volatile(
        "mma.sync.aligned.m16n8k16.row.col.f32.bf16.bf16.f32 "
        "{%0,%1,%2,%3}, {%4,%5,%6,%7}, {%8,%9}, {%0,%1,%2,%3};"
        : "+f"(d[0]), "+f"(d[1]), "+f"(d[2]), "+f"(d[3])
        : "r"(a[0]), "r"(a[1]), "r"(a[2]), "r"(a[3]), "r"(b[0]), "r"(b[1]));
}
__device__ __forceinline__ void mma_s8(int* d, const uint32_t* a, const uint32_t* b) {
    asm volatile(
        "mma.sync.aligned.m16n8k32.row.col.s32.s8.s8.s32 "
        "{%0,%1,%2,%3}, {%4,%5,%6,%7}, {%8,%9}, {%0,%1,%2,%3};"
        : "+r"(d[0]), "+r"(d[1]), "+r"(d[2]), "+r"(d[3])
        : "r"(a[0]), "r"(a[1]), "r"(a[2]), "r"(a[3]), "r"(b[0]), "r"(b[1]));
}
__device__ __forceinline__ void quant2(float v, float rs, int& q0, int& q1) {
    float t = v * rs;
    q0 = __float2int_rn(t);
    int r = __float2int_rn((t - (float)q0) * 256.0f);
    q1 = max(-127, min(127, r));
}

// ---------------- router ----------------
__global__ void router_kernel(const float* __restrict__ x, const float* __restrict__ Wr) {
    __shared__ float sx[D_MODEL];
    __shared__ float slog[NE];
    const int t = blockIdx.x, tid = threadIdx.x;
    const float* xr = x + (size_t)t * D_MODEL;
    for (int i = tid * 4; i < D_MODEL; i += 256 * 4)
        *(float4*)(sx + i) = *(const float4*)(xr + i);
    __syncthreads();
    const int w = tid >> 5, lane = tid & 31;
    const float* wr = Wr + (size_t)w * D_MODEL;
    float s = 0.f;
    for (int i = lane; i < D_MODEL; i += 32) s += sx[i] * wr[i];
    #pragma unroll
    for (int o = 16; o; o >>= 1) s += __shfl_xor_sync(0xffffffffu, s, o);
    if (lane == 0) slog[w] = s;
    __syncthreads();
    if (tid == 0) {
        float mx = slog[0]; int mi = 0;
        #pragma unroll
        for (int e = 1; e < NE; e++) if (slog[e] > mx) { mx = slog[e]; mi = e; }
        float sum = 0.f;
        #pragma unroll
        for (int e = 0; e < NE; e++) sum += expf(slog[e] - mx);
        g_idx[t] = mi;
        g_w[t] = 1.0f / sum;
    }
}

// ---------------- bucket + tile table + padded token map ----------------
__global__ void bucket_kernel() {
    __shared__ int cnt[NE], off[NE], soff[NE], spo[NE + 1];
    const int tid = threadIdx.x;
    if (tid < NE) cnt[tid] = 0;
    __syncthreads();
    for (int t = tid; t < T_TOK; t += blockDim.x) atomicAdd(&cnt[g_idx[t]], 1);
    __syncthreads();
    if (tid == 0) {
        int acc = 0, pacc = 0, nt = 0;
        #pragma unroll
        for (int e = 0; e < NE; e++) {
            off[e] = acc; soff[e] = acc; g_off[e] = acc;
            spo[e] = pacc;
            int tiles = (cnt[e] + 127) >> 7;
            for (int i = 0; i < tiles; i++) {
                g_tile_e[nt] = e;
                g_tile_gt[nt] = (pacc >> 7) + i;
                g_tile_m64[nt] = (cnt[e] - i * 128) <= 64;
                nt++;
            }
            acc += cnt[e];
            pacc += tiles << 7;
        }
        g_off[NE] = acc;
        spo[NE] = pacc;
        g_ntiles = nt;
    }
    __syncthreads();
    for (int t = tid; t < T_TOK; t += blockDim.x) {
        int p = atomicAdd(&off[g_idx[t]], 1);
        g_order[p] = t;
    }
    __syncthreads();
    for (int p = tid; p < PM * 128; p += blockDim.x) {
        int tk = -1;
        #pragma unroll
        for (int e = 0; e < NE; e++)
            if (p >= spo[e] && p < spo[e] + cnt[e])
                tk = g_order[soff[e] + (p - spo[e])];
        g_ptok[p] = tk;
    }
}

// ---------------- quantize x: gather rows -> int8 2-slice blocks + row scales --------
__global__ void __launch_bounds__(256) quant_x(const float* __restrict__ x) {
    const int gt = blockIdx.x;
    const int tid = threadIdx.x;
    const int r = tid >> 1, half = tid & 1;
    const int tok = g_ptok[gt * 128 + r];
    const float* xr = (tok >= 0) ? (x + (size_t)tok * D_MODEL) : nullptr;

    float m = 0.f;
    if (xr) {
        for (int i = half * 1024; i < half * 1024 + 1024; i += 4) {
            float4 v = *(const float4*)(xr + i);
            m = fmaxf(m, fmaxf(fmaxf(fabsf(v.x), fabsf(v.y)), fmaxf(fabsf(v.z), fabsf(v.w))));
        }
    }
    m = fmaxf(m, __shfl_xor_sync(0xffffffffu, m, 1));
    const float s = fmaxf(m, 1e-20f) * (1.0f / 126.5f);
    const float rs = 126.5f / fmaxf(m, 1e-20f);
    if (half == 0) g_sa[gt * 128 + r] = s;

    for (int kt = half * 8; kt < half * 8 + 8; kt++) {
        char* blk = g_A + (size_t)(gt * KT1Q + kt) * QBLK_A;
        #pragma unroll
        for (int ch = 0; ch < 8; ch++) {
            uint8_t q0b[16], q1b[16];
            if (xr) {
                #pragma unroll
                for (int j4 = 0; j4 < 4; j4++) {
                    float4 v = *(const float4*)(xr + kt * 128 + ch * 16 + j4 * 4);
                    float vv[4] = {v.x, v.y, v.z, v.w};
                    #pragma unroll
                    for (int j = 0; j < 4; j++) {
                        int a0, a1;
                        quant2(vv[j], rs, a0, a1);
                        q0b[j4 * 4 + j] = (uint8_t)a0;
                        q1b[j4 * 4 + j] = (uint8_t)a1;
                    }
                }
            } else {
                #pragma unroll
                for (int j = 0; j < 16; j++) { q0b[j] = 0; q1b[j] = 0; }
            }
            uint32_t off = (uint32_t)(r * 128) + (uint32_t)((ch ^ (r & 7)) << 4);
            *(uint4*)(blk + off)         = *(const uint4*)q0b;
            *(uint4*)(blk + 16384 + off) = *(const uint4*)q1b;
        }
    }
}

// ---------------- quantize + transpose W1: [E][D][F] -> int8 blocks + col scales -----
#define WQ_SMEM (128 * 132 * 4)
__global__ void __launch_bounds__(256) w1_quant(const float* __restrict__ W1) {
    extern __shared__ float s[];                 // 128 x 132
    __shared__ float m2[2][128];
    __shared__ float srs[128];
    const int f0 = blockIdx.x * 128;
    const int e = blockIdx.y;
    const int tid = threadIdx.x;
    const float* wp = W1 + (size_t)e * D_MODEL * FF;

    // pass 1: column max over D
    {
        const int c = tid & 127, seg = tid >> 7;
        float m = 0.f;
        const float* p = wp + (size_t)(seg * 1024) * FF + f0 + c;
        for (int d = 0; d < 1024; d++) m = fmaxf(m, fabsf(p[(size_t)d * FF]));
        m2[seg][c] = m;
    }
    __syncthreads();
    if (tid < 128) {
        float m = fmaxf(fmaxf(m2[0][tid], m2[1][tid]), 1e-20f);
        g_sb1[e * FF + f0 + tid] = m * (1.0f / 126.5f);
        srs[tid] = 126.5f / m;
    }
    __syncthreads();

    // pass 2: per k128 block: load tile, transpose-quantize
    for (int kt = 0; kt < KT1Q; kt++) {
        #pragma unroll
        for (int i = 0; i < 16; i++) {
            int q = i * 256 + tid;
            int k = q >> 5, c4 = q & 31;
            *(float4*)(s + k * 132 + c4 * 4) =
                *(const float4*)(wp + (size_t)(kt * 128 + k) * FF + f0 + c4 * 4);
        }
        __syncthreads();
        const int n = tid >> 1, half = tid & 1;
        const float rs = srs[n];
        char* blk = g_B1q + (size_t)((e * (FF/64) + (f0 >> 6) + (n >> 6)) * KT1Q + kt) * QBLK_B;
        const int nr = n & 63;
        #pragma unroll
        for (int ch = half * 4; ch < half * 4 + 4; ch++) {
            uint8_t q0b[16], q1b[16];
            #pragma unroll
            for (int j = 0; j < 16; j++) {
                int b0, b1;
                quant2(s[(ch * 16 + j) * 132 + n], rs, b0, b1);
                q0b[j] = (uint8_t)b0;
                q1b[j] = (uint8_t)b1;
            }
            uint32_t off = (uint32_t)(nr * 128) + (uint32_t)((ch ^ (nr & 7)) << 4);
            *(uint4*)(blk + off)        = *(const uint4*)q0b;
            *(uint4*)(blk + 8192 + off) = *(const uint4*)q1b;
        }
        __syncthreads();
    }
}

// ---------------- transpose + convert W2 -> swizzled bf16 hi/lo blocks ----------------
__global__ void __launch_bounds__(256) transconv2_kernel(const float* __restrict__ src) {
    __shared__ float s[64 * 132];
    const int nt = blockIdx.x, kt = blockIdx.y, e = blockIdx.z;
    const int tid = threadIdx.x;
    const float* sp = src + (size_t)e * FF * D_MODEL + (size_t)(kt * 64) * D_MODEL + nt * 128;
    #pragma unroll
    for (int i = 0; i < 8; i++) {
        int q = i * 256 + tid;
        int k = q >> 5, c4 = q & 31;
        *(float4*)(s + k * 132 + c4 * 4) = *(const float4*)(sp + (size_t)k * D_MODEL + c4 * 4);
    }
    __syncthreads();
    const int n = tid >> 1, half = tid & 1;
    uint32_t hw[16], lw[16];
    #pragma unroll
    for (int jw = 0; jw < 16; jw++) {
        float v0 = s[(half * 32 + jw * 2) * 132 + n];
        float v1 = s[(half * 32 + jw * 2 + 1) * 132 + n];
        float h0, l0, h1, l1;
        split1(v0, h0, l0); split1(v1, h1, l1);
        hw[jw] = pack2(h0, h1);
        lw[jw] = pack2(l0, l1);
    }
    char* dst = g_B2 + (((size_t)e * NT2 + nt) * KT2 + kt) * BLKB;
    #pragma unroll
    for (int c = 0; c < 4; c++) {
        int ch = half * 4 + c;
        uint32_t off = (uint32_t)(n * 128) + (uint32_t)((ch ^ (n & 7)) << 4);
        *(uint4*)(dst + off)         = ((uint4*)hw)[c];
        *(uint4*)(dst + 16384 + off) = ((uint4*)lw)[c];
    }
}

// ---------------- GEMM1 int8: H = gelu(x @ W1), BM=128, BN=64, k128/iter -------------
#define ST1       49152u     // A 32KB + B 16KB
#define SM1_TOK   147456
#define SM1_SA    147968
#define SM1_SB    148480
#define SM1_MBR   148736
#define SMEM1     148800

__global__ void __launch_bounds__(288, 1) gemm1_i8() {
    const int tix = blockIdx.y;
    if (tix >= g_ntiles) return;
    const int e = g_tile_e[tix];
    const int gt = g_tile_gt[tix];
    const int m64 = g_tile_m64[tix];
    const int nt = blockIdx.x;                  // 0..127 (64-col tiles of F)

    extern __shared__ char smem[];
    const uint32_t sb = s2u(smem);
    int* s_tok = (int*)(smem + SM1_TOK);
    float* s_sa = (float*)(smem + SM1_SA);
    float* s_sb = (float*)(smem + SM1_SB);
    const uint32_t mfull = sb + SM1_MBR;
    const uint32_t mempty = sb + SM1_MBR + 24;

    const int tid = threadIdx.x;
    const int wid = tid >> 5, lane = tid & 31;

    if (tid < 128) {
        s_tok[tid] = g_ptok[gt * 128 + tid];
        s_sa[tid] = g_sa[gt * 128 + tid];
    }
    if (tid < 64) s_sb[tid] = g_sb1[e * FF + nt * 64 + tid];
    if (tid == 0) {
        #pragma unroll
        for (int i = 0; i < 3; i++) { mbar_init(mfull + i * 8, 1); mbar_init(mempty + i * 8, 8); }
    }
    __syncthreads();

    if (wid == 8) {
        if (lane == 0) {
            const char* srcA = g_A + (size_t)gt * KT1Q * QBLK_A;
            const char* srcB = g_B1q + (size_t)(e * (FF/64) + nt) * KT1Q * QBLK_B;
            int s = 0, r = 0;
            for (int kt = 0; kt < KT1Q; kt++) {
                if (r > 0) mbar_wait(mempty + s * 8, (r - 1) & 1);
                mbar_expect_tx(mfull + s * 8, ST1);
                uint32_t dst = sb + (uint32_t)s * ST1;
                bulk_g2s(dst,          srcA + (size_t)kt * QBLK_A, QBLK_A, mfull + s * 8);
                bulk_g2s(dst + 32768u, srcB + (size_t)kt * QBLK_B, QBLK_B, mfull + s * 8);
                if (++s == 3) { s = 0; r++; }
            }
        }
        return;
    }

    // consumers: 8 warps, warp tile 32M x 32N: wm 0..3, wn 0..1
    const int wm = wid >> 1, wn = wid & 1;
    const bool skipw = (m64 && wm >= 2);

    const int lrA = (lane & 7) + ((lane >> 3) & 1) * 8;
    const int cA0 = lane >> 4;
    uint32_t a_off[2]; int a_rs[2];
    #pragma unroll
    for (int mf = 0; mf < 2; mf++) {
        int rr = wm * 32 + mf * 16 + lrA;
        a_off[mf] = (uint32_t)(rr * 128);
        a_rs[mf] = rr & 7;
    }
    const int lrB = (lane & 7) + ((lane >> 4) << 3);
    const int cB0 = (lane >> 3) & 1;
    uint32_t b_off[2]; int b_rs[2];
    #pragma unroll
    for (int p = 0; p < 2; p++) {
        int rr = wn * 32 + p * 16 + lrB;
        b_off[p] = (uint32_t)(rr * 128);
        b_rs[p] = rr & 7;
    }

    int am[2][4][4], ac[2][4][4], a2[2][4][4];
    #pragma unroll
    for (int i = 0; i < 2; i++)
        #pragma unroll
        for (int j = 0; j < 4; j++)
            #pragma unroll
            for (int q = 0; q < 4; q++) { am[i][j][q] = 0; ac[i][j][q] = 0; a2[i][j][q] = 0; }

    int s = 0, r = 0;
    for (int kt = 0; kt < KT1Q; kt++) {
        mbar_wait(mfull + s * 8, r & 1);
        if (!skipw) {
            const uint32_t stA = sb + (uint32_t)s * ST1;
            const uint32_t stB = stA + 32768u;
            #pragma unroll
            for (int ks = 0; ks < 4; ks++) {
                uint32_t a0f[2][4], a1f[2][4];
                const int cA = cA0 + ks * 2;
                #pragma unroll
                for (int mf = 0; mf < 2; mf++) {
                    uint32_t o = a_off[mf] + (uint32_t)((cA ^ a_rs[mf]) << 4);
                    ldsm4(a0f[mf][0], a0f[mf][1], a0f[mf][2], a0f[mf][3], stA + o);
                    ldsm4(a1f[mf][0], a1f[mf][1], a1f[mf][2], a1f[mf][3], stA + 16384u + o);
                }
                const int cB = cB0 + ks * 2;
                #pragma unroll
                for (int p = 0; p < 2; p++) {
                    uint32_t b0f[4], b1f[4];
                    uint32_t o = b_off[p] + (uint32_t)((cB ^ b_rs[p]) << 4);
                    ldsm4(b0f[0], b0f[1], b0f[2], b0f[3], stB + o);
                    ldsm4(b1f[0], b1f[1], b1f[2], b1f[3], stB + 8192u + o);
                    #pragma unroll
                    for (int mf = 0; mf < 2; mf++)
                        #pragma unroll
                        for (int sub = 0; sub < 2; sub++) {
                            const int nf = p * 2 + sub;
                            mma_s8(am[mf][nf], a0f[mf], &b0f[sub * 2]);
                            mma_s8(ac[mf][nf], a1f[mf], &b0f[sub * 2]);
                            mma_s8(ac[mf][nf], a0f[mf], &b1f[sub * 2]);
                            mma_s8(a2[mf][nf], a1f[mf], &b1f[sub * 2]);
                        }
                }
            }
        }
        if (lane == 0) mbar_arrive(mempty + s * 8);
        if (++s == 3) { s = 0; r++; }
    }

    if (skipw) return;

    // epilogue: dequant -> gelu -> bf16 hi/lo -> H block (gt, nt)
    char* blk = g_H + ((size_t)gt * KT2 + nt) * BLKB;
    #pragma unroll
    for (int mf = 0; mf < 2; mf++)
        #pragma unroll
        for (int nf = 0; nf < 4; nf++) {
            const int rbase = wm * 32 + mf * 16 + (lane >> 2);
            const int ncl = wn * 32 + nf * 8 + (lane & 3) * 2;
            const float sb0 = s_sb[ncl], sb1v = s_sb[ncl + 1];
            #pragma unroll
            for (int hh = 0; hh < 2; hh++) {
                const int rl = rbase + hh * 8;
                if (s_tok[rl] < 0) continue;
                const float sa = s_sa[rl];
                float v0 = sa * sb0 * ((float)am[mf][nf][hh * 2] +
                           (float)ac[mf][nf][hh * 2] * 0.00390625f +
                           (float)a2[mf][nf][hh * 2] * 1.52587890625e-05f);
                float v1 = sa * sb1v * ((float)am[mf][nf][hh * 2 + 1] +
                           (float)ac[mf][nf][hh * 2 + 1] * 0.00390625f +
                           (float)a2[mf][nf][hh * 2 + 1] * 1.52587890625e-05f);
                v0 = gelu_exact(v0);
                v1 = gelu_exact(v1);
                float h0, l0, h1, l1;
                split1(v0, h0, l0); split1(v1, h1, l1);
                uint32_t off = (uint32_t)(rl * 128)
                             + (uint32_t)((((ncl >> 3) ^ (rl & 7)) << 4) + (ncl & 7) * 2);
                *(uint32_t*)(blk + off)          = pack2(h0, h1);
                *(uint32_t*)(blk + 16384u + off) = pack2(l0, l1);
            }
        }
}

// ---------------- GEMM2 bf16 3-term (unchanged from R5) ----------------
#define ST_BYTES   65536u
#define SM_TOKOFF  196608
#define SM_WVOFF   197120
#define SM_MBROFF  197632
#define SMEM_TOT   197696

__global__ void __launch_bounds__(288, 1) moe_gemm2(float* __restrict__ out) {
    const int tix = blockIdx.y;
    if (tix >= g_ntiles) return;
    const int e = g_tile_e[tix];
    const int gt = g_tile_gt[tix];
    const int m64 = g_tile_m64[tix];
    const int nt = blockIdx.x;

    extern __shared__ char smem[];
    const uint32_t sb = s2u(smem);
    int* s_tok = (int*)(smem + SM_TOKOFF);
    float* s_wv = (float*)(smem + SM_WVOFF);
    const uint32_t mfull = sb + SM_MBROFF;
    const uint32_t mempty = sb + SM_MBROFF + 24;

    const int tid = threadIdx.x;
    const int wid = tid >> 5, lane = tid & 31;

    if (tid < 128) {
        int tk = g_ptok[gt * 128 + tid];
        s_tok[tid] = tk;
        s_wv[tid] = (tk >= 0) ? g_w[tk] : 0.f;
    }
    if (tid == 0) {
        #pragma unroll
        for (int i = 0; i < 3; i++) { mbar_init(mfull + i * 8, 1); mbar_init(mempty + i * 8, 8); }
    }
    __syncthreads();

    if (wid == 8) {
        if (lane == 0) {
            const char* srcA = g_H + (size_t)gt * KT2 * BLKB;
            const char* srcB = g_B2 + ((size_t)(e * NT2 + nt)) * KT2 * BLKB;
            int s = 0, r = 0;
            for (int kt = 0; kt < KT2; kt++) {
                if (r > 0) mbar_wait(mempty + s * 8, (r - 1) & 1);
                mbar_expect_tx(mfull + s * 8, ST_BYTES);
                uint32_t dst = sb + (uint32_t)s * ST_BYTES;
                bulk_g2s(dst,          srcA + (size_t)kt * BLKB, BLKB, mfull + s * 8);
                bulk_g2s(dst + 32768u, srcB + (size_t)kt * BLKB, BLKB, mfull + s * 8);
                if (++s == 3) { s = 0; r++; }
            }
        }
        return;
    }

    const int wm = wid >> 2, wn = wid & 3;
    const bool skipw = (m64 && wm == 1);

    const int lrA = (lane & 7) + ((lane >> 3) & 1) * 8;
    const int cA0 = lane >> 4;
    uint32_t a_off[4]; int a_rs[4];
    #pragma unroll
    for (int mf = 0; mf < 4; mf++) {
        int rr = wm * 64 + mf * 16 + lrA;
        a_off[mf] = (uint32_t)(rr * 128);
        a_rs[mf] = rr & 7;
    }
    const int lrB = (lane & 7) + ((lane >> 4) << 3);
    const int cB0 = (lane >> 3) & 1;
    uint32_t b_off[2]; int b_rs[2];
    #pragma unroll
    for (int p = 0; p < 2; p++) {
        int rr = wn * 32 + p * 16 + lrB;
        b_off[p] = (uint32_t)(rr * 128);
        b_rs[p] = rr & 7;
    }

    float acc[4][4][4];
    #pragma unroll
    for (int i = 0; i < 4; i++)
        #pragma unroll
        for (int j = 0; j < 4; j++)
            #pragma unroll
            for (int q = 0; q < 4; q++) acc[i][j][q] = 0.f;

    int s = 0, r = 0;
    for (int kt = 0; kt < KT2; kt++) {
        mbar_wait(mfull + s * 8, r & 1);
        if (!skipw) {
            const uint32_t stA = sb + (uint32_t)s * ST_BYTES;
            const uint32_t stB = stA + 32768u;
            #pragma unroll
            for (int ks = 0; ks < 4; ks++) {
                uint32_t ah[16], al[16], bh[8], bl[8];
                const int cA = cA0 + ks * 2;
                #pragma unroll
                for (int mf = 0; mf < 4; mf++) {
                    uint32_t o = a_off[mf] + (uint32_t)((cA ^ a_rs[mf]) << 4);
                    ldsm4(ah[mf*4], ah[mf*4+1], ah[mf*4+2], ah[mf*4+3], stA + o);
                    ldsm4(al[mf*4], al[mf*4+1], al[mf*4+2], al[mf*4+3], stA + 16384u + o);
                }
                const int cB = cB0 + ks * 2;
                #pragma unroll
                for (int p = 0; p < 2; p++) {
                    uint32_t o = b_off[p] + (uint32_t)((cB ^ b_rs[p]) << 4);
                    ldsm4(bh[p*4], bh[p*4+1], bh[p*4+2], bh[p*4+3], stB + o);
                    ldsm4(bl[p*4], bl[p*4+1], bl[p*4+2], bl[p*4+3], stB + 16384u + o);
                }
                #pragma unroll
                for (int mf = 0; mf < 4; mf++)
                    #pragma unroll
                    for (int nf = 0; nf < 4; nf++)
                        mma_bf16(acc[mf][nf], &ah[mf * 4], &bh[(nf >> 1) * 4 + (nf & 1) * 2]);
                #pragma unroll
                for (int mf = 0; mf < 4; mf++)
                    #pragma unroll
                    for (int nf = 0; nf < 4; nf++)
                        mma_bf16(acc[mf][nf], &al[mf * 4], &bh[(nf >> 1) * 4 + (nf & 1) * 2]);
                #pragma unroll
                for (int mf = 0; mf < 4; mf++)
                    #pragma unroll
                    for (int nf = 0; nf < 4; nf++)
                        mma_bf16(acc[mf][nf], &ah[mf * 4], &bl[(nf >> 1) * 4 + (nf & 1) * 2]);
            }
        }
        if (lane == 0) mbar_arrive(mempty + s * 8);
        if (++s == 3) { s = 0; r++; }
    }

    if (skipw) return;

    #pragma unroll
    for (int mf = 0; mf < 4; mf++)
        #pragma unroll
        for (int nf = 0; nf < 4; nf++) {
            const float* c = acc[mf][nf];
            const int rbase = wm * 64 + mf * 16 + (lane >> 2);
            const int ncol = nt * 128 + wn * 32 + nf * 8 + (lane & 3) * 2;
            #pragma unroll
            for (int hh = 0; hh < 2; hh++) {
                const int rl = rbase + hh * 8;
                const int tk = s_tok[rl];
                if (tk < 0) continue;
                const float wv = s_wv[rl];
                float2 o = make_float2(c[hh * 2] * wv, c[hh * 2 + 1] * wv);
                *(float2*)(out + (size_t)tk * D_MODEL + ncol) = o;
            }
        }
}

// ---------------- launch ----------------
extern "C" void kernel_launch(void* const* d_in, const int* in_sizes, int n_in,
                              void* d_out, int out_size) {
    const float* x  = (const float*)d_in[0];
    const float* Wr = (const float*)d_in[1];
    const float* W1 = (const float*)d_in[2];
    const float* W2 = (const float*)d_in[3];
    float* out = (float*)d_out;

    cudaFuncSetAttribute(gemm1_i8, cudaFuncAttributeMaxDynamicSharedMemorySize, SMEM1);
    cudaFuncSetAttribute(moe_gemm2, cudaFuncAttributeMaxDynamicSharedMemorySize, SMEM_TOT);
    cudaFuncSetAttribute(w1_quant, cudaFuncAttributeMaxDynamicSharedMemorySize, WQ_SMEM);

    router_kernel<<<T_TOK, 256>>>(x, Wr);
    bucket_kernel<<<1, 1024>>>();
    quant_x<<<PM, 256>>>(x);
    w1_quant<<<dim3(FF / 128, NE), 256, WQ_SMEM>>>(W1);
    transconv2_kernel<<<dim3(NT2, KT2, NE), 256>>>(W2);
    gemm1_i8<<<dim3(FF / 64, MAXT), 288, SMEM1>>>();
    moe_gemm2<<<dim3(NT2, MAXT), 288, SMEM_TOT>>>(out);
}

// round 7
// speedup vs baseline: 2.1604x; 2.1604x over previous
#include <cuda_runtime.h>
#include <cuda_bf16.h>
#include <math.h>
#include <stdint.h>

#define T_TOK   4096
#define D_MODEL 2048
#define FF      8192
#define NE      8
#define PM      40
#define MAXT    40
#define KT2     128
#define BLKB    32768       // g_H block: hi 16KB + lo 16KB (128 rows x 128B)

// ---------------- scratch ----------------
__device__ int   g_idx[T_TOK];
__device__ float g_w[T_TOK];
__device__ int   g_order[T_TOK];
__device__ int   g_off[NE + 1];
__device__ int   g_ptok[PM * 128];
__device__ int   g_tile_e[MAXT];
__device__ int   g_tile_gt[MAXT];
__device__ int   g_tile_m64[MAXT];
__device__ int   g_ntiles;
__device__ __align__(128) char g_H[(size_t)PM * KT2 * BLKB];   // 168 MB bf16 hi/lo

// ---------------- helpers ----------------
__device__ __forceinline__ uint32_t s2u(const void* p) {
    uint32_t a;
    asm("{ .reg .u64 t; cvta.to.shared.u64 t, %1; cvt.u32.u64 %0, t; }" : "=r"(a) : "l"(p));
    return a;
}
__device__ __forceinline__ uint32_t pack2(float a, float b) {
    __nv_bfloat162 t = __floats2bfloat162_rn(a, b);
    return *(uint32_t*)&t;
}
__device__ __forceinline__ void split1(float v, float& hi, float& lo) {
    __nv_bfloat16 h = __float2bfloat16_rn(v);
    hi = __bfloat162float(h);
    lo = v - hi;
}
__device__ __forceinline__ float gelu_exact(float v) {
    return 0.5f * v * (1.0f + erff(v * 0.70710678118654752440f));
}
__device__ __forceinline__ void mbar_init(uint32_t m, uint32_t c) {
    asm volatile("mbarrier.init.shared::cta.b64 [%0], %1;" :: "r"(m), "r"(c) : "memory");
}
__device__ __forceinline__ void mbar_arrive(uint32_t m) {
    asm volatile("mbarrier.arrive.shared::cta.b64 _, [%0];" :: "r"(m) : "memory");
}
__device__ __forceinline__ void mbar_expect_tx(uint32_t m, uint32_t b) {
    asm volatile("mbarrier.arrive.expect_tx.shared::cta.b64 _, [%0], %1;"
                 :: "r"(m), "r"(b) : "memory");
}
__device__ __forceinline__ void mbar_wait(uint32_t m, uint32_t ph) {
    asm volatile(
        "{\n\t.reg .pred P;\n"
        "W_%=:\n\t"
        "mbarrier.try_wait.parity.acquire.cta.shared::cta.b64 P, [%0], %1, 0x989680;\n\t"
        "@P bra.uni D_%=;\n\t"
        "bra.uni W_%=;\n"
        "D_%=:\n\t}"
        :: "r"(m), "r"(ph) : "memory");
}
__device__ __forceinline__ void bulk_g2s(uint32_t dst, const void* src, uint32_t bytes,
                                         uint32_t mbar) {
    asm volatile(
        "cp.async.bulk.shared::cta.global.mbarrier::complete_tx::bytes [%0], [%1], %2, [%3];"
        :: "r"(dst), "l"(src), "r"(bytes), "r"(mbar) : "memory");
}
__device__ __forceinline__ void ldsm4(uint32_t& r0, uint32_t& r1, uint32_t& r2, uint32_t& r3,
                                      uint32_t a) {
    asm volatile("ldmatrix.sync.aligned.m8n8.x4.shared.b16 {%0,%1,%2,%3}, [%4];"
                 : "=r"(r0), "=r"(r1), "=r"(r2), "=r"(r3) : "r"(a));
}
__device__ __forceinline__ void ldsm4t(uint32_t* r, uint32_t a) {
    asm volatile("ldmatrix.sync.aligned.m8n8.x4.trans.shared.b16 {%0,%1,%2,%3}, [%4];"
                 : "=r"(r[0]), "=r"(r[1]), "=r"(r[2]), "=r"(r[3]) : "r"(a));
}
__device__ __forceinline__ void mma_bf16(float* d, const uint32_t* a, const uint32_t* b) {
    asm volatile(
        "mma.sync.aligned.m16n8k16.row.col.f32.bf16.bf16.f32 "
        "{%0,%1,%2,%3}, {%4,%5,%6,%7}, {%8,%9}, {%0,%1,%2,%3};"
        : "+f"(d[0]), "+f"(d[1]), "+f"(d[2]), "+f"(d[3])
        : "r"(a[0]), "r"(a[1]), "r"(a[2]), "r"(a[3]), "r"(b[0]), "r"(b[1]));
}
// 16 fp32 -> 8 hi-u32 + 8 lo-u32 (16 bf16 each)
__device__ __forceinline__ void cvt16(const float4* sp, uint32_t* h, uint32_t* l) {
    #pragma unroll
    for (int q = 0; q < 4; q++) {
        float4 v = sp[q];
        float h0, l0, h1, l1, h2, l2, h3, l3;
        split1(v.x, h0, l0); split1(v.y, h1, l1);
        split1(v.z, h2, l2); split1(v.w, h3, l3);
        h[q * 2] = pack2(h0, h1); h[q * 2 + 1] = pack2(h2, h3);
        l[q * 2] = pack2(l0, l1); l[q * 2 + 1] = pack2(l2, l3);
    }
}

// ---------------- router ----------------
__global__ void router_kernel(const float* __restrict__ x, const float* __restrict__ Wr) {
    __shared__ float sx[D_MODEL];
    __shared__ float slog[NE];
    const int t = blockIdx.x, tid = threadIdx.x;
    const float* xr = x + (size_t)t * D_MODEL;
    for (int i = tid * 4; i < D_MODEL; i += 256 * 4)
        *(float4*)(sx + i) = *(const float4*)(xr + i);
    __syncthreads();
    const int w = tid >> 5, lane = tid & 31;
    const float* wr = Wr + (size_t)w * D_MODEL;
    float s = 0.f;
    for (int i = lane; i < D_MODEL; i += 32) s += sx[i] * wr[i];
    #pragma unroll
    for (int o = 16; o; o >>= 1) s += __shfl_xor_sync(0xffffffffu, s, o);
    if (lane == 0) slog[w] = s;
    __syncthreads();
    if (tid == 0) {
        float mx = slog[0]; int mi = 0;
        #pragma unroll
        for (int e = 1; e < NE; e++) if (slog[e] > mx) { mx = slog[e]; mi = e; }
        float sum = 0.f;
        #pragma unroll
        for (int e = 0; e < NE; e++) sum += expf(slog[e] - mx);
        g_idx[t] = mi;
        g_w[t] = 1.0f / sum;
    }
}

// ---------------- bucket + tile table + padded token map ----------------
__global__ void bucket_kernel() {
    __shared__ int cnt[NE], off[NE], soff[NE], spo[NE + 1];
    const int tid = threadIdx.x;
    if (tid < NE) cnt[tid] = 0;
    __syncthreads();
    for (int t = tid; t < T_TOK; t += blockDim.x) atomicAdd(&cnt[g_idx[t]], 1);
    __syncthreads();
    if (tid == 0) {
        int acc = 0, pacc = 0, nt = 0;
        #pragma unroll
        for (int e = 0; e < NE; e++) {
            off[e] = acc; soff[e] = acc; g_off[e] = acc;
            spo[e] = pacc;
            int tiles = (cnt[e] + 127) >> 7;
            for (int i = 0; i < tiles; i++) {
                g_tile_e[nt] = e;
                g_tile_gt[nt] = (pacc >> 7) + i;
                g_tile_m64[nt] = (cnt[e] - i * 128) <= 64;
                nt++;
            }
            acc += cnt[e];
            pacc += tiles << 7;
        }
        g_off[NE] = acc;
        spo[NE] = pacc;
        g_ntiles = nt;
    }
    __syncthreads();
    for (int t = tid; t < T_TOK; t += blockDim.x) {
        int p = atomicAdd(&off[g_idx[t]], 1);
        g_order[p] = t;
    }
    __syncthreads();
    for (int p = tid; p < PM * 128; p += blockDim.x) {
        int tk = -1;
        #pragma unroll
        for (int e = 0; e < NE; e++)
            if (p >= spo[e] && p < spo[e] + cnt[e])
                tk = g_order[soff[e] + (p - spo[e])];
        g_ptok[p] = tk;
    }
}

// ---------------- fused GEMM: producer converts fp32 weights on the fly ----------------
// 384 threads: 8 consumer warps (wm x wn = 2x4, 64x32 warp tile), 4 producer warps.
// Stage (64KB): [A hi 16KB][A lo 16KB][B hi 16KB][B lo 16KB], 3 stages.
// A: 128 m-rows x 128B k-major (swizzled).  B: 64 k-rows x 256B n-contig (swizzled),
// consumed via ldmatrix.trans.
#define ST_BYTES   65536u
#define SM_TOKOFF  196608
#define SM_WVOFF   197120
#define SM_MBROFF  197632
#define SMEM_TOT   197696

template <int PHASE>
__global__ void __launch_bounds__(384, 1)
moe_gemm(const float* __restrict__ x, const float* __restrict__ W,
         float* __restrict__ out) {
    constexpr int KT  = (PHASE == 1) ? 32 : KT2;     // k64 tiles
    constexpr int LDB = (PHASE == 1) ? FF : D_MODEL; // weight row stride (n-contig)
    const int tix = blockIdx.y;
    if (tix >= g_ntiles) return;
    const int e = g_tile_e[tix];
    const int gt = g_tile_gt[tix];
    const int m64 = g_tile_m64[tix];
    const int nt = blockIdx.x;
    const int n0 = nt * 128;

    extern __shared__ char smem[];
    const uint32_t sb = s2u(smem);
    int* s_tok = (int*)(smem + SM_TOKOFF);
    float* s_wv = (float*)(smem + SM_WVOFF);
    const uint32_t mfull = sb + SM_MBROFF;
    const uint32_t mempty = sb + SM_MBROFF + 24;

    const int tid = threadIdx.x;
    const int wid = tid >> 5, lane = tid & 31;

    if (tid < 128) {
        int tk = g_ptok[gt * 128 + tid];
        s_tok[tid] = tk;
        s_wv[tid] = (tk >= 0) ? g_w[tk] : 0.f;
    }
    if (tid == 0) {
        #pragma unroll
        for (int i = 0; i < 3; i++) {
            mbar_init(mfull + i * 8, (PHASE == 1) ? 128 : 129);
            mbar_init(mempty + i * 8, 8);
        }
    }
    __syncthreads();

    if (wid >= 8) {
        // ---------------- producer: 4 warps = 128 threads ----------------
        const int pt = tid - 256;
        const float* Bsrc = W + (size_t)e * D_MODEL * FF;
        const char* srcA2 = g_H + (size_t)gt * KT2 * BLKB;   // PHASE 2 A
        int s = 0, rr = 0;
        for (int kt = 0; kt < KT; kt++) {
            if (rr > 0) mbar_wait(mempty + s * 8, (rr - 1) & 1);
            char* stg = smem + (size_t)s * ST_BYTES;
            if (PHASE == 2) {
                if (pt == 0) {
                    mbar_expect_tx(mfull + s * 8, 32768u);
                    bulk_g2s(sb + s * ST_BYTES, srcA2 + (size_t)kt * BLKB, 32768u,
                             mfull + s * 8);
                }
            } else {
                // A gather + convert: 128 rows x 4 chunks (16 k = 64B fp32)
                float4 va[4][4];
                int rowv[4], chv[4];
                #pragma unroll
                for (int p = 0; p < 4; p++) {
                    int pos = p * 128 + pt;
                    rowv[p] = pos >> 2; chv[p] = pos & 3;
                    int tok = s_tok[rowv[p]];
                    if (tok >= 0) {
                        const float4* sp = (const float4*)(x + (size_t)tok * D_MODEL
                                                           + kt * 64 + chv[p] * 16);
                        #pragma unroll
                        for (int q = 0; q < 4; q++) va[p][q] = sp[q];
                    } else {
                        #pragma unroll
                        for (int q = 0; q < 4; q++) va[p][q] = make_float4(0.f,0.f,0.f,0.f);
                    }
                }
                #pragma unroll
                for (int p = 0; p < 4; p++) {
                    uint32_t h[8], l[8];
                    cvt16(va[p], h, l);
                    const int row = rowv[p];
                    const uint32_t c2 = (uint32_t)(chv[p] * 2);
                    uint32_t o1 = (uint32_t)(row * 128) + (((c2    ) ^ (row & 7)) << 4);
                    uint32_t o2 = (uint32_t)(row * 128) + (((c2 + 1) ^ (row & 7)) << 4);
                    *(uint4*)(stg + o1) = *(uint4*)(h);
                    *(uint4*)(stg + o2) = *(uint4*)(h + 4);
                    *(uint4*)(stg + 16384 + o1) = *(uint4*)(l);
                    *(uint4*)(stg + 16384 + o2) = *(uint4*)(l + 4);
                }
            }
            // B convert: 64 k-rows x 8 chunks (16 n = 64B fp32)
            {
                float4 vb[4][4];
                int rowv[4], chv[4];
                #pragma unroll
                for (int p = 0; p < 4; p++) {
                    int pos = p * 128 + pt;
                    rowv[p] = pos >> 3; chv[p] = pos & 7;
                    const float4* sp = (const float4*)(Bsrc
                        + (size_t)(kt * 64 + rowv[p]) * LDB + n0 + chv[p] * 16);
                    #pragma unroll
                    for (int q = 0; q < 4; q++) vb[p][q] = sp[q];
                }
                #pragma unroll
                for (int p = 0; p < 4; p++) {
                    uint32_t h[8], l[8];
                    cvt16(vb[p], h, l);
                    const int row = rowv[p];
                    const uint32_t c2 = (uint32_t)(chv[p] * 2);
                    uint32_t o1 = (uint32_t)(row * 256) + (((c2    ) ^ (row & 7)) << 4);
                    uint32_t o2 = (uint32_t)(row * 256) + (((c2 + 1) ^ (row & 7)) << 4);
                    *(uint4*)(stg + 32768 + o1) = *(uint4*)(h);
                    *(uint4*)(stg + 32768 + o2) = *(uint4*)(h + 4);
                    *(uint4*)(stg + 49152 + o1) = *(uint4*)(l);
                    *(uint4*)(stg + 49152 + o2) = *(uint4*)(l + 4);
                }
            }
            mbar_arrive(mfull + s * 8);
            if (++s == 3) { s = 0; rr++; }
        }
        return;
    }

    // ---------------- consumers: wm in [0,2), wn in [0,4) ----------------
    const int wm = wid >> 2, wn = wid & 3;
    const bool skipw = (m64 && wm == 1);

    // A fragments (non-trans, 128B k-major rows)
    const int lrA = (lane & 7) + ((lane >> 3) & 1) * 8;
    const int cA0 = lane >> 4;
    uint32_t a_off[4]; int a_rs[4];
    #pragma unroll
    for (int mf = 0; mf < 4; mf++) {
        int rr2 = wm * 64 + mf * 16 + lrA;
        a_off[mf] = (uint32_t)(rr2 * 128);
        a_rs[mf] = rr2 & 7;
    }
    // B fragments (trans, 256B n-contig rows)
    const int kr = (lane & 7) + ((lane >> 3) & 1) * 8;
    uint32_t bo[2];
    #pragma unroll
    for (int p = 0; p < 2; p++) {
        int cb = wn * 4 + p * 2 + (lane >> 4);
        bo[p] = (uint32_t)(kr * 256) + (uint32_t)(((cb ^ (kr & 7)) & 15) << 4);
    }

    float acc[4][4][4];
    #pragma unroll
    for (int i = 0; i < 4; i++)
        #pragma unroll
        for (int j = 0; j < 4; j++)
            #pragma unroll
            for (int q = 0; q < 4; q++) acc[i][j][q] = 0.f;

    int s = 0, r = 0;
    for (int kt = 0; kt < KT; kt++) {
        mbar_wait(mfull + s * 8, r & 1);
        if (!skipw) {
            const uint32_t stA = sb + (uint32_t)s * ST_BYTES;
            const uint32_t stB = stA + 32768u;
            #pragma unroll
            for (int ks = 0; ks < 4; ks++) {
                uint32_t ah[16], al[16], bh[2][4], bl[2][4];
                const int cA = cA0 + ks * 2;
                #pragma unroll
                for (int mf = 0; mf < 4; mf++) {
                    uint32_t o = a_off[mf] + (uint32_t)((cA ^ a_rs[mf]) << 4);
                    ldsm4(ah[mf*4], ah[mf*4+1], ah[mf*4+2], ah[mf*4+3], stA + o);
                    ldsm4(al[mf*4], al[mf*4+1], al[mf*4+2], al[mf*4+3], stA + 16384u + o);
                }
                const uint32_t kb = stB + (uint32_t)(ks * 4096);
                #pragma unroll
                for (int p = 0; p < 2; p++) {
                    ldsm4t(bh[p], kb + bo[p]);
                    ldsm4t(bl[p], kb + 16384u + bo[p]);
                }
                #pragma unroll
                for (int mf = 0; mf < 4; mf++)
                    #pragma unroll
                    for (int nf = 0; nf < 4; nf++)
                        mma_bf16(acc[mf][nf], &ah[mf * 4], &bh[nf >> 1][(nf & 1) * 2]);
                #pragma unroll
                for (int mf = 0; mf < 4; mf++)
                    #pragma unroll
                    for (int nf = 0; nf < 4; nf++)
                        mma_bf16(acc[mf][nf], &al[mf * 4], &bh[nf >> 1][(nf & 1) * 2]);
                #pragma unroll
                for (int mf = 0; mf < 4; mf++)
                    #pragma unroll
                    for (int nf = 0; nf < 4; nf++)
                        mma_bf16(acc[mf][nf], &ah[mf * 4], &bl[nf >> 1][(nf & 1) * 2]);
            }
        }
        if (lane == 0) mbar_arrive(mempty + s * 8);
        if (++s == 3) { s = 0; r++; }
    }

    if (skipw) return;

    // ---------------- epilogue ----------------
    #pragma unroll
    for (int mf = 0; mf < 4; mf++)
        #pragma unroll
        for (int nf = 0; nf < 4; nf++) {
            const float* c = acc[mf][nf];
            const int rbase = wm * 64 + mf * 16 + (lane >> 2);
            const int ncol = n0 + wn * 32 + nf * 8 + (lane & 3) * 2;
            #pragma unroll
            for (int hh = 0; hh < 2; hh++) {
                const int rl = rbase + hh * 8;
                if (PHASE == 1) {
                    if (s_tok[rl] < 0) continue;
                    float v0 = gelu_exact(c[hh * 2]);
                    float v1 = gelu_exact(c[hh * 2 + 1]);
                    float h0, l0, h1, l1;
                    split1(v0, h0, l0); split1(v1, h1, l1);
                    const int kt2 = ncol >> 6, kl = ncol & 63;
                    char* blk = g_H + ((size_t)gt * KT2 + kt2) * BLKB;
                    uint32_t off = (uint32_t)(rl * 128)
                                 + (uint32_t)((((kl >> 3) ^ (rl & 7)) << 4) + (kl & 7) * 2);
                    *(uint32_t*)(blk + off)          = pack2(h0, h1);
                    *(uint32_t*)(blk + 16384u + off) = pack2(l0, l1);
                } else {
                    const int tk = s_tok[rl];
                    if (tk < 0) continue;
                    const float wv = s_wv[rl];
                    float2 o = make_float2(c[hh * 2] * wv, c[hh * 2 + 1] * wv);
                    *(float2*)(out + (size_t)tk * D_MODEL + ncol) = o;
                }
            }
        }
}

// ---------------- launch ----------------
extern "C" void kernel_launch(void* const* d_in, const int* in_sizes, int n_in,
                              void* d_out, int out_size) {
    const float* x  = (const float*)d_in[0];
    const float* Wr = (const float*)d_in[1];
    const float* W1 = (const float*)d_in[2];
    const float* W2 = (const float*)d_in[3];
    float* out = (float*)d_out;

    cudaFuncSetAttribute(moe_gemm<1>, cudaFuncAttributeMaxDynamicSharedMemorySize, SMEM_TOT);
    cudaFuncSetAttribute(moe_gemm<2>, cudaFuncAttributeMaxDynamicSharedMemorySize, SMEM_TOT);

    router_kernel<<<T_TOK, 256>>>(x, Wr);
    bucket_kernel<<<1, 1024>>>();
    moe_gemm<1><<<dim3(FF / 128,      MAXT), 384, SMEM_TOT>>>(x, W1, nullptr);
    moe_gemm<2><<<dim3(D_MODEL / 128, MAXT), 384, SMEM_TOT>>>(x, W2, out);
}

// round 8
// speedup vs baseline: 2.2882x; 1.0591x over previous
#include <cuda_runtime.h>
#include <cuda_bf16.h>
#include <cuda_fp16.h>
#include <math.h>
#include <stdint.h>

#define T_TOK   4096
#define D_MODEL 2048
#define FF      8192
#define NE      8
#define PM      40
#define MAXT    40
#define KT1     32
#define NT1     64
#define KT2     128
#define NT2     16
#define BLKB    32768   // block: hi(bf16) 16KB + lo(fp16) 16KB (128 rows x 128B)

// ---------------- scratch ----------------
__device__ int   g_idx[T_TOK];
__device__ float g_w[T_TOK];
__device__ int   g_order[T_TOK];
__device__ int   g_off[NE + 1];
__device__ int   g_ptok[PM * 128];
__device__ int   g_tile_e[MAXT];
__device__ int   g_tile_gt[MAXT];
__device__ int   g_tile_m64[MAXT];
__device__ int   g_ntiles;

__device__ __align__(128) char g_A [(size_t)PM * KT1 * BLKB];
__device__ __align__(128) char g_B1[(size_t)NE * NT1 * KT1 * BLKB];
__device__ __align__(128) char g_B2[(size_t)NE * NT2 * KT2 * BLKB];
__device__ __align__(128) char g_H [(size_t)PM * KT2 * BLKB];

// ---------------- helpers ----------------
__device__ __forceinline__ uint32_t s2u(const void* p) {
    uint32_t a;
    asm("{ .reg .u64 t; cvta.to.shared.u64 t, %1; cvt.u32.u64 %0, t; }" : "=r"(a) : "l"(p));
    return a;
}
__device__ __forceinline__ uint32_t pack2(float a, float b) {
    __nv_bfloat162 t = __floats2bfloat162_rn(a, b);
    return *(uint32_t*)&t;
}
__device__ __forceinline__ uint32_t pack2h(float a, float b) {
    __half2 t = __floats2half2_rn(a, b);
    return *(uint32_t*)&t;
}
__device__ __forceinline__ void split1(float v, float& hi, float& lo) {
    __nv_bfloat16 h = __float2bfloat16_rn(v);
    hi = __bfloat162float(h);
    lo = v - hi;
}
__device__ __forceinline__ float gelu_exact(float v) {
    return 0.5f * v * (1.0f + erff(v * 0.70710678118654752440f));
}
// packed bf16x2 -> packed fp16x2 (exact: bf16 values are fp16-representable here)
__device__ __forceinline__ uint32_t bf2fp(uint32_t v) {
    float flo = __uint_as_float(v << 16);
    float fhi = __uint_as_float(v & 0xffff0000u);
    uint32_t r;
    asm("cvt.rn.f16x2.f32 %0, %1, %2;" : "=r"(r) : "f"(fhi), "f"(flo));
    return r;
}
__device__ __forceinline__ void mbar_init(uint32_t m, uint32_t c) {
    asm volatile("mbarrier.init.shared::cta.b64 [%0], %1;" :: "r"(m), "r"(c) : "memory");
}
__device__ __forceinline__ void mbar_arrive(uint32_t m) {
    asm volatile("mbarrier.arrive.shared::cta.b64 _, [%0];" :: "r"(m) : "memory");
}
__device__ __forceinline__ void mbar_expect_tx(uint32_t m, uint32_t b) {
    asm volatile("mbarrier.arrive.expect_tx.shared::cta.b64 _, [%0], %1;"
                 :: "r"(m), "r"(b) : "memory");
}
__device__ __forceinline__ void mbar_wait(uint32_t m, uint32_t ph) {
    asm volatile(
        "{\n\t.reg .pred P;\n"
        "W_%=:\n\t"
        "mbarrier.try_wait.parity.acquire.cta.shared::cta.b64 P, [%0], %1, 0x989680;\n\t"
        "@P bra.uni D_%=;\n\t"
        "bra.uni W_%=;\n"
        "D_%=:\n\t}"
        :: "r"(m), "r"(ph) : "memory");
}
__device__ __forceinline__ void bulk_g2s(uint32_t dst, const void* src, uint32_t bytes,
                                         uint32_t mbar) {
    asm volatile(
        "cp.async.bulk.shared::cta.global.mbarrier::complete_tx::bytes [%0], [%1], %2, [%3];"
        :: "r"(dst), "l"(src), "r"(bytes), "r"(mbar) : "memory");
}
__device__ __forceinline__ void ldsm4(uint32_t& r0, uint32_t& r1, uint32_t& r2, uint32_t& r3,
                                      uint32_t a) {
    asm volatile("ldmatrix.sync.aligned.m8n8.x4.shared.b16 {%0,%1,%2,%3}, [%4];"
                 : "=r"(r0), "=r"(r1), "=r"(r2), "=r"(r3) : "r"(a));
}
__device__ __forceinline__ void mma_bf16(float* d, const uint32_t* a, const uint32_t* b) {
    asm volatile(
        "mma.sync.aligned.m16n8k16.row.col.f32.bf16.bf16.f32 "
        "{%0,%1,%2,%3}, {%4,%5,%6,%7}, {%8,%9}, {%0,%1,%2,%3};"
        : "+f"(d[0]), "+f"(d[1]), "+f"(d[2]), "+f"(d[3])
        : "r"(a[0]), "r"(a[1]), "r"(a[2]), "r"(a[3]), "r"(b[0]), "r"(b[1]));
}
__device__ __forceinline__ void mma_f16(uint32_t* d, const uint32_t* a, const uint32_t* b) {
    asm volatile(
        "mma.sync.aligned.m16n8k16.row.col.f16.f16.f16.f16 "
        "{%0,%1}, {%2,%3,%4,%5}, {%6,%7}, {%0,%1};"
        : "+r"(d[0]), "+r"(d[1])
        : "r"(a[0]), "r"(a[1]), "r"(a[2]), "r"(a[3]), "r"(b[0]), "r"(b[1]));
}

// ---------------- router ----------------
__global__ void router_kernel(const float* __restrict__ x, const float* __restrict__ Wr) {
    __shared__ float sx[D_MODEL];
    __shared__ float slog[NE];
    const int t = blockIdx.x, tid = threadIdx.x;
    const float* xr = x + (size_t)t * D_MODEL;
    for (int i = tid * 4; i < D_MODEL; i += 256 * 4)
        *(float4*)(sx + i) = *(const float4*)(xr + i);
    __syncthreads();
    const int w = tid >> 5, lane = tid & 31;
    const float* wr = Wr + (size_t)w * D_MODEL;
    float s = 0.f;
    for (int i = lane; i < D_MODEL; i += 32) s += sx[i] * wr[i];
    #pragma unroll
    for (int o = 16; o; o >>= 1) s += __shfl_xor_sync(0xffffffffu, s, o);
    if (lane == 0) slog[w] = s;
    __syncthreads();
    if (tid == 0) {
        float mx = slog[0]; int mi = 0;
        #pragma unroll
        for (int e = 1; e < NE; e++) if (slog[e] > mx) { mx = slog[e]; mi = e; }
        float sum = 0.f;
        #pragma unroll
        for (int e = 0; e < NE; e++) sum += expf(slog[e] - mx);
        g_idx[t] = mi;
        g_w[t] = 1.0f / sum;
    }
}

// ---------------- bucket + tile table + padded token map ----------------
__global__ void bucket_kernel() {
    __shared__ int cnt[NE], off[NE], soff[NE], spo[NE + 1];
    const int tid = threadIdx.x;
    if (tid < NE) cnt[tid] = 0;
    __syncthreads();
    for (int t = tid; t < T_TOK; t += blockDim.x) atomicAdd(&cnt[g_idx[t]], 1);
    __syncthreads();
    if (tid == 0) {
        int acc = 0, pacc = 0, nt = 0;
        #pragma unroll
        for (int e = 0; e < NE; e++) {
            off[e] = acc; soff[e] = acc; g_off[e] = acc;
            spo[e] = pacc;
            int tiles = (cnt[e] + 127) >> 7;
            for (int i = 0; i < tiles; i++) {
                g_tile_e[nt] = e;
                g_tile_gt[nt] = (pacc >> 7) + i;
                g_tile_m64[nt] = (cnt[e] - i * 128) <= 64;
                nt++;
            }
            acc += cnt[e];
            pacc += tiles << 7;
        }
        g_off[NE] = acc;
        spo[NE] = pacc;
        g_ntiles = nt;
    }
    __syncthreads();
    for (int t = tid; t < T_TOK; t += blockDim.x) {
        int p = atomicAdd(&off[g_idx[t]], 1);
        g_order[p] = t;
    }
    __syncthreads();
    for (int p = tid; p < PM * 128; p += blockDim.x) {
        int tk = -1;
        #pragma unroll
        for (int e = 0; e < NE; e++)
            if (p >= spo[e] && p < spo[e] + cnt[e])
                tk = g_order[soff[e] + (p - spo[e])];
        g_ptok[p] = tk;
    }
}

// ---------------- prepass: gather x rows -> swizzled blocks (hi bf16, lo fp16) -------
__global__ void __launch_bounds__(256) gather_a_kernel(const float* __restrict__ x) {
    const int gt = blockIdx.x, kt = blockIdx.y;
    const int tid = threadIdx.x;
    const int r = tid >> 1, half = tid & 1;
    const int tok = g_ptok[gt * 128 + r];
    uint32_t hw[16], lw[16];
    if (tok >= 0) {
        const float4* src = (const float4*)(x + (size_t)tok * D_MODEL + kt * 64 + half * 32);
        #pragma unroll
        for (int q = 0; q < 8; q++) {
            float4 v = src[q];
            float h0, l0, h1, l1, h2, l2, h3, l3;
            split1(v.x, h0, l0); split1(v.y, h1, l1);
            split1(v.z, h2, l2); split1(v.w, h3, l3);
            hw[q * 2]     = pack2(h0, h1);  hw[q * 2 + 1] = pack2(h2, h3);
            lw[q * 2]     = pack2h(l0, l1); lw[q * 2 + 1] = pack2h(l2, l3);
        }
    } else {
        #pragma unroll
        for (int q = 0; q < 16; q++) { hw[q] = 0; lw[q] = 0; }
    }
    char* blk = g_A + ((size_t)gt * KT1 + kt) * BLKB;
    #pragma unroll
    for (int c = 0; c < 4; c++) {
        int ch = half * 4 + c;
        uint32_t off = (uint32_t)(r * 128) + (uint32_t)((ch ^ (r & 7)) << 4);
        *(uint4*)(blk + off)         = ((uint4*)hw)[c];
        *(uint4*)(blk + 16384 + off) = ((uint4*)lw)[c];
    }
}

// ---------------- prepass: transpose + convert weights (hi bf16, lo fp16) ------------
template <int W>
__global__ void __launch_bounds__(256) transconv_kernel(const float* __restrict__ src) {
    constexpr int Cn = (W == 1) ? FF : D_MODEL;
    constexpr int Rk = (W == 1) ? D_MODEL : FF;
    constexpr int NT = (W == 1) ? NT1 : NT2;
    constexpr int KT = (W == 1) ? KT1 : KT2;
    __shared__ float s[64 * 132];
    const int nt = blockIdx.x, kt = blockIdx.y, e = blockIdx.z;
    const int tid = threadIdx.x;
    const float* sp = src + (size_t)e * Rk * Cn + (size_t)(kt * 64) * Cn + nt * 128;
    #pragma unroll
    for (int i = 0; i < 8; i++) {
        int q = i * 256 + tid;
        int k = q >> 5, c4 = q & 31;
        *(float4*)(s + k * 132 + c4 * 4) = *(const float4*)(sp + (size_t)k * Cn + c4 * 4);
    }
    __syncthreads();
    const int n = tid >> 1, half = tid & 1;
    uint32_t hw[16], lw[16];
    #pragma unroll
    for (int jw = 0; jw < 16; jw++) {
        float v0 = s[(half * 32 + jw * 2) * 132 + n];
        float v1 = s[(half * 32 + jw * 2 + 1) * 132 + n];
        float h0, l0, h1, l1;
        split1(v0, h0, l0); split1(v1, h1, l1);
        hw[jw] = pack2(h0, h1);
        lw[jw] = pack2h(l0, l1);
    }
    char* dst = ((W == 1) ? g_B1 : g_B2) + (((size_t)e * NT + nt) * KT + kt) * BLKB;
    #pragma unroll
    for (int c = 0; c < 4; c++) {
        int ch = half * 4 + c;
        uint32_t off = (uint32_t)(n * 128) + (uint32_t)((ch ^ (n & 7)) << 4);
        *(uint4*)(dst + off)         = ((uint4*)hw)[c];
        *(uint4*)(dst + 16384 + off) = ((uint4*)lw)[c];
    }
}

// ---------------- warp-MMA grouped GEMM: f32-acc main + f16-acc corrections ----------
#define ST_BYTES   65536u
#define SM_TOKOFF  196608
#define SM_WVOFF   197120
#define SM_MBROFF  197632
#define SMEM_TOT   197696

template <int PHASE>
__global__ void __launch_bounds__(288, 1) moe_gemm(float* __restrict__ out) {
    constexpr int KT = (PHASE == 1) ? KT1 : KT2;
    const int tix = blockIdx.y;
    if (tix >= g_ntiles) return;
    const int e = g_tile_e[tix];
    const int gt = g_tile_gt[tix];
    const int m64 = g_tile_m64[tix];
    const int nt = blockIdx.x;

    extern __shared__ char smem[];
    const uint32_t sb = s2u(smem);
    int* s_tok = (int*)(smem + SM_TOKOFF);
    float* s_wv = (float*)(smem + SM_WVOFF);
    const uint32_t mfull = sb + SM_MBROFF;
    const uint32_t mempty = sb + SM_MBROFF + 24;

    const int tid = threadIdx.x;
    const int wid = tid >> 5, lane = tid & 31;

    if (tid < 128) {
        int tk = g_ptok[gt * 128 + tid];
        s_tok[tid] = tk;
        s_wv[tid] = (tk >= 0) ? g_w[tk] : 0.f;
    }
    if (tid == 0) {
        #pragma unroll
        for (int i = 0; i < 3; i++) { mbar_init(mfull + i * 8, 1); mbar_init(mempty + i * 8, 8); }
    }
    __syncthreads();

    if (wid == 8) {
        if (lane == 0) {
            const char* srcA = (PHASE == 1) ? (g_A + (size_t)gt * KT1 * BLKB)
                                            : (g_H + (size_t)gt * KT2 * BLKB);
            const char* srcB = (PHASE == 1)
                ? (g_B1 + ((size_t)(e * NT1 + nt)) * KT1 * BLKB)
                : (g_B2 + ((size_t)(e * NT2 + nt)) * KT2 * BLKB);
            int s = 0, r = 0;
            for (int kt = 0; kt < KT; kt++) {
                if (r > 0) mbar_wait(mempty + s * 8, (r - 1) & 1);
                mbar_expect_tx(mfull + s * 8, ST_BYTES);
                uint32_t dst = sb + (uint32_t)s * ST_BYTES;
                bulk_g2s(dst,          srcA + (size_t)kt * BLKB, BLKB, mfull + s * 8);
                bulk_g2s(dst + 32768u, srcB + (size_t)kt * BLKB, BLKB, mfull + s * 8);
                if (++s == 3) { s = 0; r++; }
            }
        }
        return;
    }

    // consumers: wm in [0,2) (64 M-rows), wn in [0,4) (32 N-cols)
    const int wm = wid >> 2, wn = wid & 3;
    const bool skipw = (m64 && wm == 1);

    const int lrA = (lane & 7) + ((lane >> 3) & 1) * 8;
    const int cA0 = lane >> 4;
    uint32_t a_off[4]; int a_rs[4];
    #pragma unroll
    for (int mf = 0; mf < 4; mf++) {
        int rr = wm * 64 + mf * 16 + lrA;
        a_off[mf] = (uint32_t)(rr * 128);
        a_rs[mf] = rr & 7;
    }
    const int lrB = (lane & 7) + ((lane >> 4) << 3);
    const int cB0 = (lane >> 3) & 1;
    uint32_t b_off[2]; int b_rs[2];
    #pragma unroll
    for (int p = 0; p < 2; p++) {
        int rr = wn * 32 + p * 16 + lrB;
        b_off[p] = (uint32_t)(rr * 128);
        b_rs[p] = rr & 7;
    }

    float acc[4][4][4];
    uint32_t hac[4][4][2];
    #pragma unroll
    for (int i = 0; i < 4; i++)
        #pragma unroll
        for (int j = 0; j < 4; j++) {
            #pragma unroll
            for (int q = 0; q < 4; q++) acc[i][j][q] = 0.f;
            hac[i][j][0] = 0; hac[i][j][1] = 0;
        }

    int s = 0, r = 0;
    for (int kt = 0; kt < KT; kt++) {
        mbar_wait(mfull + s * 8, r & 1);
        if (!skipw) {
            const uint32_t stA = sb + (uint32_t)s * ST_BYTES;
            const uint32_t stB = stA + 32768u;
            #pragma unroll
            for (int ks = 0; ks < 4; ks++) {
                uint32_t ah[16], alf[16], bh[8], blf[8];
                const int cA = cA0 + ks * 2;
                #pragma unroll
                for (int mf = 0; mf < 4; mf++) {
                    uint32_t o = a_off[mf] + (uint32_t)((cA ^ a_rs[mf]) << 4);
                    ldsm4(ah[mf*4], ah[mf*4+1], ah[mf*4+2], ah[mf*4+3], stA + o);
                    ldsm4(alf[mf*4], alf[mf*4+1], alf[mf*4+2], alf[mf*4+3], stA + 16384u + o);
                }
                const int cB = cB0 + ks * 2;
                #pragma unroll
                for (int p = 0; p < 2; p++) {
                    uint32_t o = b_off[p] + (uint32_t)((cB ^ b_rs[p]) << 4);
                    ldsm4(bh[p*4], bh[p*4+1], bh[p*4+2], bh[p*4+3], stB + o);
                    ldsm4(blf[p*4], blf[p*4+1], blf[p*4+2], blf[p*4+3], stB + 16384u + o);
                }
                // fp16 copies of the bf16 hi fragments (exact conversion)
                uint32_t ahf[16], bhf[8];
                #pragma unroll
                for (int i = 0; i < 16; i++) ahf[i] = bf2fp(ah[i]);
                #pragma unroll
                for (int i = 0; i < 8; i++)  bhf[i] = bf2fp(bh[i]);
                // pass 1: hi*hi, fp32 accumulate
                #pragma unroll
                for (int mf = 0; mf < 4; mf++)
                    #pragma unroll
                    for (int nf = 0; nf < 4; nf++)
                        mma_bf16(acc[mf][nf], &ah[mf * 4], &bh[(nf >> 1) * 4 + (nf & 1) * 2]);
                // pass 2: lo_a*hi_b, fp16 accumulate
                #pragma unroll
                for (int mf = 0; mf < 4; mf++)
                    #pragma unroll
                    for (int nf = 0; nf < 4; nf++)
                        mma_f16(hac[mf][nf], &alf[mf * 4], &bhf[(nf >> 1) * 4 + (nf & 1) * 2]);
                // pass 3: hi_a*lo_b, fp16 accumulate (shared accumulators)
                #pragma unroll
                for (int mf = 0; mf < 4; mf++)
                    #pragma unroll
                    for (int nf = 0; nf < 4; nf++)
                        mma_f16(hac[mf][nf], &ahf[mf * 4], &blf[(nf >> 1) * 4 + (nf & 1) * 2]);
            }
        }
        if (lane == 0) mbar_arrive(mempty + s * 8);
        if (++s == 3) { s = 0; r++; }
    }

    if (skipw) return;

    // ---------------- epilogue: merge f16 corrections, then store ----------------
    #pragma unroll
    for (int mf = 0; mf < 4; mf++)
        #pragma unroll
        for (int nf = 0; nf < 4; nf++) {
            const float* c = acc[mf][nf];
            const int rbase = wm * 64 + mf * 16 + (lane >> 2);
            const int ncol = nt * 128 + wn * 32 + nf * 8 + (lane & 3) * 2;
            #pragma unroll
            for (int hh = 0; hh < 2; hh++) {
                const int rl = rbase + hh * 8;
                float2 cor = __half22float2(*(__half2*)&hac[mf][nf][hh]);
                float v0 = c[hh * 2]     + cor.x;
                float v1 = c[hh * 2 + 1] + cor.y;
                if (PHASE == 1) {
                    if (s_tok[rl] < 0) continue;
                    v0 = gelu_exact(v0);
                    v1 = gelu_exact(v1);
                    float h0, l0, h1, l1;
                    split1(v0, h0, l0); split1(v1, h1, l1);
                    const int kt2 = ncol >> 6, kl = ncol & 63;
                    char* blk = g_H + ((size_t)gt * KT2 + kt2) * BLKB;
                    uint32_t off = (uint32_t)(rl * 128)
                                 + (uint32_t)((((kl >> 3) ^ (rl & 7)) << 4) + (kl & 7) * 2);
                    *(uint32_t*)(blk + off)          = pack2(h0, h1);
                    *(uint32_t*)(blk + 16384u + off) = pack2h(l0, l1);
                } else {
                    const int tk = s_tok[rl];
                    if (tk < 0) continue;
                    const float wv = s_wv[rl];
                    float2 o = make_float2(v0 * wv, v1 * wv);
                    *(float2*)(out + (size_t)tk * D_MODEL + ncol) = o;
                }
            }
        }
}

// ---------------- launch ----------------
extern "C" void kernel_launch(void* const* d_in, const int* in_sizes, int n_in,
                              void* d_out, int out_size) {
    const float* x  = (const float*)d_in[0];
    const float* Wr = (const float*)d_in[1];
    const float* W1 = (const float*)d_in[2];
    const float* W2 = (const float*)d_in[3];
    float* out = (float*)d_out;

    cudaFuncSetAttribute(moe_gemm<1>, cudaFuncAttributeMaxDynamicSharedMemorySize, SMEM_TOT);
    cudaFuncSetAttribute(moe_gemm<2>, cudaFuncAttributeMaxDynamicSharedMemorySize, SMEM_TOT);

    router_kernel<<<T_TOK, 256>>>(x, Wr);
    bucket_kernel<<<1, 1024>>>();
    gather_a_kernel<<<dim3(PM, KT1), 256>>>(x);
    transconv_kernel<1><<<dim3(NT1, KT1, NE), 256>>>(W1);
    transconv_kernel<2><<<dim3(NT2, KT2, NE), 256>>>(W2);
    moe_gemm<1><<<dim3(NT1, MAXT), 288, SMEM_TOT>>>(nullptr);
    moe_gemm<2><<<dim3(NT2, MAXT), 288, SMEM_TOT>>>(out);
}

// round 10
// speedup vs baseline: 2.5908x; 1.1323x over previous
#include <cuda_runtime.h>
#include <cuda_bf16.h>
#include <math.h>
#include <stdint.h>

#define T_TOK   4096
#define D_MODEL 2048
#define FF      8192
#define NE      8
#define PM      40
#define MAXT    40
#define KT1     32
#define NT1     64
#define KT2     128
#define NT2     16
#define BLKB    32768   // operand block: hi 16KB + lo 16KB (128 rows x 128B)

// ---------------- scratch ----------------
__device__ int   g_idx[T_TOK];
__device__ float g_w[T_TOK];
__device__ int   g_order[T_TOK];
__device__ int   g_off[NE + 1];
__device__ int   g_ptok[PM * 128];
__device__ int   g_tile_e[MAXT];
__device__ int   g_tile_gt[MAXT];
__device__ int   g_tile_m64[MAXT];
__device__ int   g_ntiles;

__device__ __align__(128) char g_A [(size_t)PM * KT1 * BLKB];
__device__ __align__(128) char g_B1[(size_t)NE * NT1 * KT1 * BLKB];
__device__ __align__(128) char g_B2[(size_t)NE * NT2 * KT2 * BLKB];
__device__ __align__(128) char g_H [(size_t)PM * KT2 * BLKB];

// ---------------- helpers ----------------
__device__ __forceinline__ uint32_t s2u(const void* p) {
    uint32_t a;
    asm("{ .reg .u64 t; cvta.to.shared.u64 t, %1; cvt.u32.u64 %0, t; }" : "=r"(a) : "l"(p));
    return a;
}
__device__ __forceinline__ uint32_t pack2(float a, float b) {
    __nv_bfloat162 t = __floats2bfloat162_rn(a, b);
    return *(uint32_t*)&t;
}
__device__ __forceinline__ void split1(float v, float& hi, float& lo) {
    __nv_bfloat16 h = __float2bfloat16_rn(v);
    hi = __bfloat162float(h);
    lo = v - hi;
}
__device__ __forceinline__ float gelu_exact(float v) {
    return 0.5f * v * (1.0f + erff(v * 0.70710678118654752440f));
}
__device__ __forceinline__ void mbar_init(uint32_t m, uint32_t c) {
    asm volatile("mbarrier.init.shared::cta.b64 [%0], %1;" :: "r"(m), "r"(c) : "memory");
}
__device__ __forceinline__ void mbar_arrive(uint32_t m) {
    asm volatile("mbarrier.arrive.shared::cta.b64 _, [%0];" :: "r"(m) : "memory");
}
__device__ __forceinline__ void mbar_expect_tx(uint32_t m, uint32_t b) {
    asm volatile("mbarrier.arrive.expect_tx.shared::cta.b64 _, [%0], %1;"
                 :: "r"(m), "r"(b) : "memory");
}
__device__ __forceinline__ void mbar_wait(uint32_t m, uint32_t ph) {
    asm volatile(
        "{\n\t.reg .pred P;\n"
        "W_%=:\n\t"
        "mbarrier.try_wait.parity.acquire.cta.shared::cta.b64 P, [%0], %1, 0x989680;\n\t"
        "@P bra.uni D_%=;\n\t"
        "bra.uni W_%=;\n"
        "D_%=:\n\t}"
        :: "r"(m), "r"(ph) : "memory");
}
__device__ __forceinline__ void bulk_g2s(uint32_t dst, const void* src, uint32_t bytes,
                                         uint32_t mbar) {
    asm volatile(
        "cp.async.bulk.shared::cta.global.mbarrier::complete_tx::bytes [%0], [%1], %2, [%3];"
        :: "r"(dst), "l"(src), "r"(bytes), "r"(mbar) : "memory");
}
__device__ __forceinline__ void ldsm4(uint32_t& r0, uint32_t& r1, uint32_t& r2, uint32_t& r3,
                                      uint32_t a) {
    asm volatile("ldmatrix.sync.aligned.m8n8.x4.shared.b16 {%0,%1,%2,%3}, [%4];"
                 : "=r"(r0), "=r"(r1), "=r"(r2), "=r"(r3) : "r"(a));
}
__device__ __forceinline__ void mma_bf16(float* d, const uint32_t* a, const uint32_t* b) {
    asm volatile(
        "mma.sync.aligned.m16n8k16.row.col.f32.bf16.bf16.f32 "
        "{%0,%1,%2,%3}, {%4,%5,%6,%7}, {%8,%9}, {%0,%1,%2,%3};"
        : "+f"(d[0]), "+f"(d[1]), "+f"(d[2]), "+f"(d[3])
        : "r"(a[0]), "r"(a[1]), "r"(a[2]), "r"(a[3]), "r"(b[0]), "r"(b[1]));
}

// ---------------- router ----------------
__global__ void router_kernel(const float* __restrict__ x, const float* __restrict__ Wr) {
    __shared__ float sx[D_MODEL];
    __shared__ float slog[NE];
    const int t = blockIdx.x, tid = threadIdx.x;
    const float* xr = x + (size_t)t * D_MODEL;
    for (int i = tid * 4; i < D_MODEL; i += 256 * 4)
        *(float4*)(sx + i) = *(const float4*)(xr + i);
    __syncthreads();
    const int w = tid >> 5, lane = tid & 31;
    const float* wr = Wr + (size_t)w * D_MODEL;
    float s = 0.f;
    for (int i = lane; i < D_MODEL; i += 32) s += sx[i] * wr[i];
    #pragma unroll
    for (int o = 16; o; o >>= 1) s += __shfl_xor_sync(0xffffffffu, s, o);
    if (lane == 0) slog[w] = s;
    __syncthreads();
    if (tid == 0) {
        float mx = slog[0]; int mi = 0;
        #pragma unroll
        for (int e = 1; e < NE; e++) if (slog[e] > mx) { mx = slog[e]; mi = e; }
        float sum = 0.f;
        #pragma unroll
        for (int e = 0; e < NE; e++) sum += expf(slog[e] - mx);
        g_idx[t] = mi;
        g_w[t] = 1.0f / sum;
    }
}

// ---------------- bucket + tile table + padded token map ----------------
__global__ void bucket_kernel() {
    __shared__ int cnt[NE], off[NE], soff[NE], spo[NE + 1];
    const int tid = threadIdx.x;
    if (tid < NE) cnt[tid] = 0;
    __syncthreads();
    for (int t = tid; t < T_TOK; t += blockDim.x) atomicAdd(&cnt[g_idx[t]], 1);
    __syncthreads();
    if (tid == 0) {
        int acc = 0, pacc = 0, nt = 0;
        #pragma unroll
        for (int e = 0; e < NE; e++) {
            off[e] = acc; soff[e] = acc; g_off[e] = acc;
            spo[e] = pacc;
            int tiles = (cnt[e] + 127) >> 7;
            for (int i = 0; i < tiles; i++) {
                g_tile_e[nt] = e;
                g_tile_gt[nt] = (pacc >> 7) + i;
                g_tile_m64[nt] = (cnt[e] - i * 128) <= 64;
                nt++;
            }
            acc += cnt[e];
            pacc += tiles << 7;
        }
        g_off[NE] = acc;
        spo[NE] = pacc;
        g_ntiles = nt;
    }
    __syncthreads();
    for (int t = tid; t < T_TOK; t += blockDim.x) {
        int p = atomicAdd(&off[g_idx[t]], 1);
        g_order[p] = t;
    }
    __syncthreads();
    for (int p = tid; p < PM * 128; p += blockDim.x) {
        int tk = -1;
        #pragma unroll
        for (int e = 0; e < NE; e++)
            if (p >= spo[e] && p < spo[e] + cnt[e])
                tk = g_order[soff[e] + (p - spo[e])];
        g_ptok[p] = tk;
    }
}

// ---------------- prepass: gather x rows -> swizzled bf16 hi/lo blocks ----------------
__global__ void __launch_bounds__(256) gather_a_kernel(const float* __restrict__ x) {
    const int gt = blockIdx.x, kt = blockIdx.y;
    const int tid = threadIdx.x;
    const int r = tid >> 1, half = tid & 1;
    const int tok = g_ptok[gt * 128 + r];
    uint32_t hw[16], lw[16];
    if (tok >= 0) {
        const float4* src = (const float4*)(x + (size_t)tok * D_MODEL + kt * 64 + half * 32);
        #pragma unroll
        for (int q = 0; q < 8; q++) {
            float4 v = src[q];
            float h0, l0, h1, l1, h2, l2, h3, l3;
            split1(v.x, h0, l0); split1(v.y, h1, l1);
            split1(v.z, h2, l2); split1(v.w, h3, l3);
            hw[q * 2]     = pack2(h0, h1); hw[q * 2 + 1] = pack2(h2, h3);
            lw[q * 2]     = pack2(l0, l1); lw[q * 2 + 1] = pack2(l2, l3);
        }
    } else {
        #pragma unroll
        for (int q = 0; q < 16; q++) { hw[q] = 0; lw[q] = 0; }
    }
    char* blk = g_A + ((size_t)gt * KT1 + kt) * BLKB;
    #pragma unroll
    for (int c = 0; c < 4; c++) {
        int ch = half * 4 + c;
        uint32_t off = (uint32_t)(r * 128) + (uint32_t)((ch ^ (r & 7)) << 4);
        *(uint4*)(blk + off)         = ((uint4*)hw)[c];
        *(uint4*)(blk + 16384 + off) = ((uint4*)lw)[c];
    }
}

// ---------------- prepass: transpose + convert W1 only ----------------
__global__ void __launch_bounds__(256) transconv1_kernel(const float* __restrict__ src) {
    __shared__ float s[64 * 132];
    const int nt = blockIdx.x, kt = blockIdx.y, e = blockIdx.z;
    const int tid = threadIdx.x;
    const float* sp = src + (size_t)e * D_MODEL * FF + (size_t)(kt * 64) * FF + nt * 128;
    #pragma unroll
    for (int i = 0; i < 8; i++) {
        int q = i * 256 + tid;
        int k = q >> 5, c4 = q & 31;
        *(float4*)(s + k * 132 + c4 * 4) = *(const float4*)(sp + (size_t)k * FF + c4 * 4);
    }
    __syncthreads();
    const int n = tid >> 1, half = tid & 1;
    uint32_t hw[16], lw[16];
    #pragma unroll
    for (int jw = 0; jw < 16; jw++) {
        float v0 = s[(half * 32 + jw * 2) * 132 + n];
        float v1 = s[(half * 32 + jw * 2 + 1) * 132 + n];
        float h0, l0, h1, l1;
        split1(v0, h0, l0); split1(v1, h1, l1);
        hw[jw] = pack2(h0, h1);
        lw[jw] = pack2(l0, l1);
    }
    char* dst = g_B1 + (((size_t)e * NT1 + nt) * KT1 + kt) * BLKB;
    #pragma unroll
    for (int c = 0; c < 4; c++) {
        int ch = half * 4 + c;
        uint32_t off = (uint32_t)(n * 128) + (uint32_t)((ch ^ (n & 7)) << 4);
        *(uint4*)(dst + off)         = ((uint4*)hw)[c];
        *(uint4*)(dst + 16384 + off) = ((uint4*)lw)[c];
    }
}

// ---------------- warp-MMA grouped GEMM + tc2 helper warps --------------------------
// 352 threads: warps 0-7 consumers, warp 8 producer, warps 9-10 (64 thr) tc2 helpers.
#define ST_BYTES   65536u
#define SM_TOKOFF  196608
#define SM_WVOFF   197120
#define SM_MBROFF  197632
#define SM_TC      197696          // 32 x 132 fp32 transpose buffer (16,896 B)
#define SMEM_TOT   214592

template <int PHASE>
__global__ void __launch_bounds__(352, 1)
moe_gemm(const float* __restrict__ W2, float* __restrict__ out) {
    constexpr int KT = (PHASE == 1) ? KT1 : KT2;
    const int tix = blockIdx.y;
    const int nt = blockIdx.x;
    const int tid = threadIdx.x;
    const int wid = tid >> 5, lane = tid & 31;

    extern __shared__ char smem[];
    const uint32_t sb = s2u(smem);
    int* s_tok = (int*)(smem + SM_TOKOFF);
    float* s_wv = (float*)(smem + SM_WVOFF);
    const uint32_t mfull = sb + SM_MBROFF;
    const uint32_t mempty = sb + SM_MBROFF + 24;

    // ---------- tc2 helper warps (warps 9,10 = 64 threads) ----------
    if (wid >= 9) {
        if (PHASE == 1 && tix < 32) {
            float* tb = (float*)(smem + SM_TC);
            const int hl = tid - 288;                  // 0..63
            const int bi = nt * 32 + tix;              // 0..2047
            for (int u = 0; u < 8; u++) {
                const int unit = bi * 8 + u;           // 0..16383
                const int e2 = unit >> 11;             // / (NT2*KT2)
                const int rem = unit & 2047;
                const int nt2 = rem >> 7;
                const int kt2 = rem & 127;
                const float* src = W2 + (size_t)e2 * FF * D_MODEL
                                 + (size_t)(kt2 * 64) * D_MODEL + nt2 * 128;
                char* dst = g_B2 + (((size_t)e2 * NT2 + nt2) * KT2 + kt2) * BLKB;
                #pragma unroll
                for (int half = 0; half < 2; half++) {
                    #pragma unroll
                    for (int i = 0; i < 16; i++) {
                        int q = i * 64 + hl;
                        int r = q >> 5, c4 = q & 31;
                        *(float4*)(tb + r * 132 + c4 * 4) =
                            *(const float4*)(src + (size_t)(half * 32 + r) * D_MODEL + c4 * 4);
                    }
                    asm volatile("bar.sync 1, 64;" ::: "memory");
                    #pragma unroll
                    for (int nn = 0; nn < 2; nn++) {
                        const int n = hl * 2 + nn;
                        uint32_t hw[16], lw[16];
                        #pragma unroll
                        for (int j = 0; j < 16; j++) {
                            float v0 = tb[(j * 2) * 132 + n];
                            float v1 = tb[(j * 2 + 1) * 132 + n];
                            float h0, l0, h1, l1;
                            split1(v0, h0, l0); split1(v1, h1, l1);
                            hw[j] = pack2(h0, h1);
                            lw[j] = pack2(l0, l1);
                        }
                        #pragma unroll
                        for (int c = 0; c < 4; c++) {
                            int ch = half * 4 + c;
                            uint32_t off = (uint32_t)(n * 128)
                                         + (uint32_t)((ch ^ (n & 7)) << 4);
                            *(uint4*)(dst + off)         = ((uint4*)hw)[c];
                            *(uint4*)(dst + 16384 + off) = ((uint4*)lw)[c];
                        }
                    }
                    asm volatile("bar.sync 1, 64;" ::: "memory");
                }
            }
        }
        return;
    }

    if (tix >= g_ntiles) return;
    const int e = g_tile_e[tix];
    const int gt = g_tile_gt[tix];
    const int m64 = g_tile_m64[tix];

    if (tid < 128) {
        int tk = g_ptok[gt * 128 + tid];
        s_tok[tid] = tk;
        s_wv[tid] = (tk >= 0) ? g_w[tk] : 0.f;
    }
    if (tid == 0) {
        #pragma unroll
        for (int i = 0; i < 3; i++) { mbar_init(mfull + i * 8, 1); mbar_init(mempty + i * 8, 8); }
    }
    asm volatile("bar.sync 2, 288;" ::: "memory");   // warps 0-8 only

    if (wid == 8) {
        if (lane == 0) {
            const char* srcA = (PHASE == 1) ? (g_A + (size_t)gt * KT1 * BLKB)
                                            : (g_H + (size_t)gt * KT2 * BLKB);
            const char* srcB = (PHASE == 1)
                ? (g_B1 + ((size_t)(e * NT1 + nt)) * KT1 * BLKB)
                : (g_B2 + ((size_t)(e * NT2 + nt)) * KT2 * BLKB);
            int s = 0, r = 0;
            for (int kt = 0; kt < KT; kt++) {
                if (r > 0) mbar_wait(mempty + s * 8, (r - 1) & 1);
                mbar_expect_tx(mfull + s * 8, ST_BYTES);
                uint32_t dst = sb + (uint32_t)s * ST_BYTES;
                bulk_g2s(dst,          srcA + (size_t)kt * BLKB, BLKB, mfull + s * 8);
                bulk_g2s(dst + 32768u, srcB + (size_t)kt * BLKB, BLKB, mfull + s * 8);
                if (++s == 3) { s = 0; r++; }
            }
        }
        return;
    }

    // consumers: wm in [0,2) (64 M-rows), wn in [0,4) (32 N-cols)
    const int wm = wid >> 2, wn = wid & 3;
    const bool skipw = (m64 && wm == 1);

    const int lrA = (lane & 7) + ((lane >> 3) & 1) * 8;
    const int cA0 = lane >> 4;
    uint32_t a_off[4]; int a_rs[4];
    #pragma unroll
    for (int mf = 0; mf < 4; mf++) {
        int rr = wm * 64 + mf * 16 + lrA;
        a_off[mf] = (uint32_t)(rr * 128);
        a_rs[mf] = rr & 7;
    }
    const int lrB = (lane & 7) + ((lane >> 4) << 3);
    const int cB0 = (lane >> 3) & 1;
    uint32_t b_off[2]; int b_rs[2];
    #pragma unroll
    for (int p = 0; p < 2; p++) {
        int rr = wn * 32 + p * 16 + lrB;
        b_off[p] = (uint32_t)(rr * 128);
        b_rs[p] = rr & 7;
    }

    float acc[4][4][4];
    #pragma unroll
    for (int i = 0; i < 4; i++)
        #pragma unroll
        for (int j = 0; j < 4; j++)
            #pragma unroll
            for (int q = 0; q < 4; q++) acc[i][j][q] = 0.f;

    int s = 0, r = 0;
    for (int kt = 0; kt < KT; kt++) {
        mbar_wait(mfull + s * 8, r & 1);
        if (!skipw) {
            const uint32_t stA = sb + (uint32_t)s * ST_BYTES;
            const uint32_t stB = stA + 32768u;
            #pragma unroll
            for (int ks = 0; ks < 4; ks++) {
                uint32_t ah[16], al[16], bh[8], bl[8];
                const int cA = cA0 + ks * 2;
                #pragma unroll
                for (int mf = 0; mf < 4; mf++) {
                    uint32_t o = a_off[mf] + (uint32_t)((cA ^ a_rs[mf]) << 4);
                    ldsm4(ah[mf*4], ah[mf*4+1], ah[mf*4+2], ah[mf*4+3], stA + o);
                    ldsm4(al[mf*4], al[mf*4+1], al[mf*4+2], al[mf*4+3], stA + 16384u + o);
                }
                const int cB = cB0 + ks * 2;
                #pragma unroll
                for (int p = 0; p < 2; p++) {
                    uint32_t o = b_off[p] + (uint32_t)((cB ^ b_rs[p]) << 4);
                    ldsm4(bh[p*4], bh[p*4+1], bh[p*4+2], bh[p*4+3], stB + o);
                    ldsm4(bl[p*4], bl[p*4+1], bl[p*4+2], bl[p*4+3], stB + 16384u + o);
                }
                #pragma unroll
                for (int mf = 0; mf < 4; mf++)
                    #pragma unroll
                    for (int nf = 0; nf < 4; nf++)
                        mma_bf16(acc[mf][nf], &ah[mf * 4], &bh[(nf >> 1) * 4 + (nf & 1) * 2]);
                #pragma unroll
                for (int mf = 0; mf < 4; mf++)
                    #pragma unroll
                    for (int nf = 0; nf < 4; nf++)
                        mma_bf16(acc[mf][nf], &al[mf * 4], &bh[(nf >> 1) * 4 + (nf & 1) * 2]);
                #pragma unroll
                for (int mf = 0; mf < 4; mf++)
                    #pragma unroll
                    for (int nf = 0; nf < 4; nf++)
                        mma_bf16(acc[mf][nf], &ah[mf * 4], &bl[(nf >> 1) * 4 + (nf & 1) * 2]);
            }
        }
        if (lane == 0) mbar_arrive(mempty + s * 8);
        if (++s == 3) { s = 0; r++; }
    }

    if (skipw) return;

    // ---------------- epilogue ----------------
    #pragma unroll
    for (int mf = 0; mf < 4; mf++)
        #pragma unroll
        for (int nf = 0; nf < 4; nf++) {
            const float* c = acc[mf][nf];
            const int rbase = wm * 64 + mf * 16 + (lane >> 2);
            const int ncol = nt * 128 + wn * 32 + nf * 8 + (lane & 3) * 2;
            #pragma unroll
            for (int hh = 0; hh < 2; hh++) {
                const int rl = rbase + hh * 8;
                if (PHASE == 1) {
                    if (s_tok[rl] < 0) continue;
                    float v0 = gelu_exact(c[hh * 2]);
                    float v1 = gelu_exact(c[hh * 2 + 1]);
                    float h0, l0, h1, l1;
                    split1(v0, h0, l0); split1(v1, h1, l1);
                    const int kt2 = ncol >> 6, kl = ncol & 63;
                    char* blk = g_H + ((size_t)gt * KT2 + kt2) * BLKB;
                    uint32_t off = (uint32_t)(rl * 128)
                                 + (uint32_t)((((kl >> 3) ^ (rl & 7)) << 4) + (kl & 7) * 2);
                    *(uint32_t*)(blk + off)          = pack2(h0, h1);
                    *(uint32_t*)(blk + 16384u + off) = pack2(l0, l1);
                } else {
                    const int tk = s_tok[rl];
                    if (tk < 0) continue;
                    const float wv = s_wv[rl];
                    float2 o = make_float2(c[hh * 2] * wv, c[hh * 2 + 1] * wv);
                    *(float2*)(out + (size_t)tk * D_MODEL + ncol) = o;
                }
            }
        }
}

// ---------------- launch ----------------
extern "C" void kernel_launch(void* const* d_in, const int* in_sizes, int n_in,
                              void* d_out, int out_size) {
    const float* x  = (const float*)d_in[0];
    const float* Wr = (const float*)d_in[1];
    const float* W1 = (const float*)d_in[2];
    const float* W2 = (const float*)d_in[3];
    float* out = (float*)d_out;

    cudaFuncSetAttribute(moe_gemm<1>, cudaFuncAttributeMaxDynamicSharedMemorySize, SMEM_TOT);
    cudaFuncSetAttribute(moe_gemm<2>, cudaFuncAttributeMaxDynamicSharedMemorySize, SMEM_TOT);

    router_kernel<<<T_TOK, 256>>>(x, Wr);
    bucket_kernel<<<1, 1024>>>();
    gather_a_kernel<<<dim3(PM, KT1), 256>>>(x);
    transconv1_kernel<<<dim3(NT1, KT1, NE), 256>>>(W1);
    moe_gemm<1><<<dim3(NT1, MAXT), 352, SMEM_TOT>>>(W2, nullptr);   // tc2 fused in helpers
    moe_gemm<2><<<dim3(NT2, MAXT), 352, SMEM_TOT>>>(W2, out);
}

// round 12
// speedup vs baseline: 3.5901x; 1.3857x over previous
#include <cuda_runtime.h>
#include <cuda_bf16.h>
#include <cuda_fp16.h>
#include <math.h>
#include <stdint.h>

#define T_TOK   4096
#define D_MODEL 2048
#define FF      8192
#define NE      8
#define PM      40
#define MAXT    40
#define KT1     32
#define NT1     64
#define KT2     128
#define NT2     16
#define BLKA    16384   // A/H block: single fp16 plane, 128 rows x 128B
#define BLKB    32768   // weight block: fp16 hi 16KB + fp16 lo 16KB

// ---------------- scratch ----------------
__device__ int   g_idx[T_TOK];
__device__ float g_w[T_TOK];
__device__ int   g_order[T_TOK];
__device__ int   g_off[NE + 1];
__device__ int   g_ptok[PM * 128];
__device__ int   g_tile_e[MAXT];
__device__ int   g_tile_gt[MAXT];
__device__ int   g_tile_m64[MAXT];
__device__ int   g_ntiles;

__device__ __align__(128) char g_A [(size_t)PM * KT1 * BLKA];
__device__ __align__(128) char g_B1[(size_t)NE * NT1 * KT1 * BLKB];
__device__ __align__(128) char g_B2[(size_t)NE * NT2 * KT2 * BLKB];
__device__ __align__(128) char g_H [(size_t)PM * KT2 * BLKA];

// ---------------- helpers ----------------
__device__ __forceinline__ uint32_t s2u(const void* p) {
    uint32_t a;
    asm("{ .reg .u64 t; cvta.to.shared.u64 t, %1; cvt.u32.u64 %0, t; }" : "=r"(a) : "l"(p));
    return a;
}
__device__ __forceinline__ uint32_t pack2h(float a, float b) {
    __half2 t = __floats2half2_rn(a, b);
    return *(uint32_t*)&t;
}
__device__ __forceinline__ void split1h(float v, float& hi, float& lo) {
    __half h = __float2half_rn(v);
    hi = __half2float(h);
    lo = v - hi;
}
__device__ __forceinline__ float gelu_exact(float v) {
    return 0.5f * v * (1.0f + erff(v * 0.70710678118654752440f));
}
__device__ __forceinline__ void mbar_init(uint32_t m, uint32_t c) {
    asm volatile("mbarrier.init.shared::cta.b64 [%0], %1;" :: "r"(m), "r"(c) : "memory");
}
__device__ __forceinline__ void mbar_arrive(uint32_t m) {
    asm volatile("mbarrier.arrive.shared::cta.b64 _, [%0];" :: "r"(m) : "memory");
}
__device__ __forceinline__ void mbar_expect_tx(uint32_t m, uint32_t b) {
    asm volatile("mbarrier.arrive.expect_tx.shared::cta.b64 _, [%0], %1;"
                 :: "r"(m), "r"(b) : "memory");
}
__device__ __forceinline__ void mbar_wait(uint32_t m, uint32_t ph) {
    asm volatile(
        "{\n\t.reg .pred P;\n"
        "W_%=:\n\t"
        "mbarrier.try_wait.parity.acquire.cta.shared::cta.b64 P, [%0], %1, 0x989680;\n\t"
        "@P bra.uni D_%=;\n\t"
        "bra.uni W_%=;\n"
        "D_%=:\n\t}"
        :: "r"(m), "r"(ph) : "memory");
}
__device__ __forceinline__ void bulk_g2s(uint32_t dst, const void* src, uint32_t bytes,
                                         uint32_t mbar) {
    asm volatile(
        "cp.async.bulk.shared::cta.global.mbarrier::complete_tx::bytes [%0], [%1], %2, [%3];"
        :: "r"(dst), "l"(src), "r"(bytes), "r"(mbar) : "memory");
}
__device__ __forceinline__ void ldsm4(uint32_t& r0, uint32_t& r1, uint32_t& r2, uint32_t& r3,
                                      uint32_t a) {
    asm volatile("ldmatrix.sync.aligned.m8n8.x4.shared.b16 {%0,%1,%2,%3}, [%4];"
                 : "=r"(r0), "=r"(r1), "=r"(r2), "=r"(r3) : "r"(a));
}
__device__ __forceinline__ void mma_f16f32(float* d, const uint32_t* a, const uint32_t* b) {
    asm volatile(
        "mma.sync.aligned.m16n8k16.row.col.f32.f16.f16.f32 "
        "{%0,%1,%2,%3}, {%4,%5,%6,%7}, {%8,%9}, {%0,%1,%2,%3};"
        : "+f"(d[0]), "+f"(d[1]), "+f"(d[2]), "+f"(d[3])
        : "r"(a[0]), "r"(a[1]), "r"(a[2]), "r"(a[3]), "r"(b[0]), "r"(b[1]));
}

// ---------------- router ----------------
__global__ void router_kernel(const float* __restrict__ x, const float* __restrict__ Wr) {
    __shared__ float sx[D_MODEL];
    __shared__ float slog[NE];
    const int t = blockIdx.x, tid = threadIdx.x;
    const float* xr = x + (size_t)t * D_MODEL;
    for (int i = tid * 4; i < D_MODEL; i += 256 * 4)
        *(float4*)(sx + i) = *(const float4*)(xr + i);
    __syncthreads();
    const int w = tid >> 5, lane = tid & 31;
    const float* wr = Wr + (size_t)w * D_MODEL;
    float s = 0.f;
    for (int i = lane; i < D_MODEL; i += 32) s += sx[i] * wr[i];
    #pragma unroll
    for (int o = 16; o; o >>= 1) s += __shfl_xor_sync(0xffffffffu, s, o);
    if (lane == 0) slog[w] = s;
    __syncthreads();
    if (tid == 0) {
        float mx = slog[0]; int mi = 0;
        #pragma unroll
        for (int e = 1; e < NE; e++) if (slog[e] > mx) { mx = slog[e]; mi = e; }
        float sum = 0.f;
        #pragma unroll
        for (int e = 0; e < NE; e++) sum += expf(slog[e] - mx);
        g_idx[t] = mi;
        g_w[t] = 1.0f / sum;
    }
}

// ---------------- bucket + tile table + padded token map ----------------
__global__ void bucket_kernel() {
    __shared__ int cnt[NE], off[NE], soff[NE], spo[NE + 1];
    const int tid = threadIdx.x;
    if (tid < NE) cnt[tid] = 0;
    __syncthreads();
    for (int t = tid; t < T_TOK; t += blockDim.x) atomicAdd(&cnt[g_idx[t]], 1);
    __syncthreads();
    if (tid == 0) {
        int acc = 0, pacc = 0, nt = 0;
        #pragma unroll
        for (int e = 0; e < NE; e++) {
            off[e] = acc; soff[e] = acc; g_off[e] = acc;
            spo[e] = pacc;
            int tiles = (cnt[e] + 127) >> 7;
            for (int i = 0; i < tiles; i++) {
                g_tile_e[nt] = e;
                g_tile_gt[nt] = (pacc >> 7) + i;
                g_tile_m64[nt] = (cnt[e] - i * 128) <= 64;
                nt++;
            }
            acc += cnt[e];
            pacc += tiles << 7;
        }
        g_off[NE] = acc;
        spo[NE] = pacc;
        g_ntiles = nt;
    }
    __syncthreads();
    for (int t = tid; t < T_TOK; t += blockDim.x) {
        int p = atomicAdd(&off[g_idx[t]], 1);
        g_order[p] = t;
    }
    __syncthreads();
    for (int p = tid; p < PM * 128; p += blockDim.x) {
        int tk = -1;
        #pragma unroll
        for (int e = 0; e < NE; e++)
            if (p >= spo[e] && p < spo[e] + cnt[e])
                tk = g_order[soff[e] + (p - spo[e])];
        g_ptok[p] = tk;
    }
}

// ---------------- prepass: gather x rows -> swizzled fp16 blocks (single plane) ------
__global__ void __launch_bounds__(256) gather_a_kernel(const float* __restrict__ x) {
    const int gt = blockIdx.x, kt = blockIdx.y;
    const int tid = threadIdx.x;
    const int r = tid >> 1, half = tid & 1;
    const int tok = g_ptok[gt * 128 + r];
    uint32_t fw[16];
    if (tok >= 0) {
        const float4* src = (const float4*)(x + (size_t)tok * D_MODEL + kt * 64 + half * 32);
        #pragma unroll
        for (int q = 0; q < 8; q++) {
            float4 v = src[q];
            fw[q * 2]     = pack2h(v.x, v.y);
            fw[q * 2 + 1] = pack2h(v.z, v.w);
        }
    } else {
        #pragma unroll
        for (int q = 0; q < 16; q++) fw[q] = 0;
    }
    char* blk = g_A + ((size_t)gt * KT1 + kt) * BLKA;
    #pragma unroll
    for (int c = 0; c < 4; c++) {
        int ch = half * 4 + c;
        uint32_t off = (uint32_t)(r * 128) + (uint32_t)((ch ^ (r & 7)) << 4);
        *(uint4*)(blk + off) = ((uint4*)fw)[c];
    }
}

// ---------------- prepass: transpose + convert W1 (fp16 hi/lo planes) ----------------
__global__ void __launch_bounds__(256) transconv1_kernel(const float* __restrict__ src) {
    __shared__ float s[64 * 132];
    const int nt = blockIdx.x, kt = blockIdx.y, e = blockIdx.z;
    const int tid = threadIdx.x;
    const float* sp = src + (size_t)e * D_MODEL * FF + (size_t)(kt * 64) * FF + nt * 128;
    #pragma unroll
    for (int i = 0; i < 8; i++) {
        int q = i * 256 + tid;
        int k = q >> 5, c4 = q & 31;
        *(float4*)(s + k * 132 + c4 * 4) = *(const float4*)(sp + (size_t)k * FF + c4 * 4);
    }
    __syncthreads();
    const int n = tid >> 1, half = tid & 1;
    uint32_t hw[16], lw[16];
    #pragma unroll
    for (int jw = 0; jw < 16; jw++) {
        float v0 = s[(half * 32 + jw * 2) * 132 + n];
        float v1 = s[(half * 32 + jw * 2 + 1) * 132 + n];
        float h0, l0, h1, l1;
        split1h(v0, h0, l0); split1h(v1, h1, l1);
        hw[jw] = pack2h(h0, h1);
        lw[jw] = pack2h(l0, l1);
    }
    char* dst = g_B1 + (((size_t)e * NT1 + nt) * KT1 + kt) * BLKB;
    #pragma unroll
    for (int c = 0; c < 4; c++) {
        int ch = half * 4 + c;
        uint32_t off = (uint32_t)(n * 128) + (uint32_t)((ch ^ (n & 7)) << 4);
        *(uint4*)(dst + off)         = ((uint4*)hw)[c];
        *(uint4*)(dst + 16384 + off) = ((uint4*)lw)[c];
    }
}

// ---------------- warp-MMA grouped GEMM (fp16 2-term) + tc2 helper warps -------------
// 352 threads: warps 0-7 consumers, warp 8 producer, warps 9-10 (64 thr) tc2 helpers.
// Stage (48KB): [A fp16 16KB][B hi 16KB][B lo 16KB], 3 stages.
#define ST_BYTES   49152u
#define SM_TOKOFF  147456
#define SM_WVOFF   147968
#define SM_MBROFF  148480
#define SM_TC      148544          // 32 x 132 fp32 transpose buffer (16,896 B)
#define SMEM_TOT   165440

template <int PHASE>
__global__ void __launch_bounds__(352, 1)
moe_gemm(const float* __restrict__ W2, float* __restrict__ out) {
    constexpr int KT = (PHASE == 1) ? KT1 : KT2;
    const int tix = blockIdx.y;
    const int nt = blockIdx.x;
    const int tid = threadIdx.x;
    const int wid = tid >> 5, lane = tid & 31;

    extern __shared__ char smem[];
    const uint32_t sb = s2u(smem);
    int* s_tok = (int*)(smem + SM_TOKOFF);
    float* s_wv = (float*)(smem + SM_WVOFF);
    const uint32_t mfull = sb + SM_MBROFF;
    const uint32_t mempty = sb + SM_MBROFF + 24;

    // ---------- tc2 helper warps (warps 9,10 = 64 threads) ----------
    if (wid >= 9) {
        if (PHASE == 1 && tix < 32) {
            float* tb = (float*)(smem + SM_TC);
            const int hl = tid - 288;                  // 0..63
            const int bi = nt * 32 + tix;              // 0..2047
            for (int u = 0; u < 8; u++) {
                const int unit = bi * 8 + u;           // 0..16383
                const int e2 = unit >> 11;
                const int rem = unit & 2047;
                const int nt2 = rem >> 7;
                const int kt2 = rem & 127;
                const float* src = W2 + (size_t)e2 * FF * D_MODEL
                                 + (size_t)(kt2 * 64) * D_MODEL + nt2 * 128;
                char* dst = g_B2 + (((size_t)e2 * NT2 + nt2) * KT2 + kt2) * BLKB;
                #pragma unroll
                for (int half = 0; half < 2; half++) {
                    #pragma unroll
                    for (int i = 0; i < 16; i++) {
                        int q = i * 64 + hl;
                        int r = q >> 5, c4 = q & 31;
                        *(float4*)(tb + r * 132 + c4 * 4) =
                            *(const float4*)(src + (size_t)(half * 32 + r) * D_MODEL + c4 * 4);
                    }
                    asm volatile("bar.sync 1, 64;" ::: "memory");
                    #pragma unroll
                    for (int nn = 0; nn < 2; nn++) {
                        const int n = hl * 2 + nn;
                        uint32_t hw[16], lw[16];
                        #pragma unroll
                        for (int j = 0; j < 16; j++) {
                            float v0 = tb[(j * 2) * 132 + n];
                            float v1 = tb[(j * 2 + 1) * 132 + n];
                            float h0, l0, h1, l1;
                            split1h(v0, h0, l0); split1h(v1, h1, l1);
                            hw[j] = pack2h(h0, h1);
                            lw[j] = pack2h(l0, l1);
                        }
                        #pragma unroll
                        for (int c = 0; c < 4; c++) {
                            int ch = half * 4 + c;
                            uint32_t off = (uint32_t)(n * 128)
                                         + (uint32_t)((ch ^ (n & 7)) << 4);
                            *(uint4*)(dst + off)         = ((uint4*)hw)[c];
                            *(uint4*)(dst + 16384 + off) = ((uint4*)lw)[c];
                        }
                    }
                    asm volatile("bar.sync 1, 64;" ::: "memory");
                }
            }
        }
        return;
    }

    if (tix >= g_ntiles) return;
    const int e = g_tile_e[tix];
    const int gt = g_tile_gt[tix];
    const int m64 = g_tile_m64[tix];

    if (tid < 128) {
        int tk = g_ptok[gt * 128 + tid];
        s_tok[tid] = tk;
        s_wv[tid] = (tk >= 0) ? g_w[tk] : 0.f;
    }
    if (tid == 0) {
        #pragma unroll
        for (int i = 0; i < 3; i++) { mbar_init(mfull + i * 8, 1); mbar_init(mempty + i * 8, 8); }
    }
    asm volatile("bar.sync 2, 288;" ::: "memory");   // warps 0-8 only

    if (wid == 8) {
        if (lane == 0) {
            const char* srcA = (PHASE == 1) ? (g_A + (size_t)gt * KT1 * BLKA)
                                            : (g_H + (size_t)gt * KT2 * BLKA);
            const char* srcB = (PHASE == 1)
                ? (g_B1 + ((size_t)(e * NT1 + nt)) * KT1 * BLKB)
                : (g_B2 + ((size_t)(e * NT2 + nt)) * KT2 * BLKB);
            int s = 0, r = 0;
            for (int kt = 0; kt < KT; kt++) {
                if (r > 0) mbar_wait(mempty + s * 8, (r - 1) & 1);
                mbar_expect_tx(mfull + s * 8, ST_BYTES);
                uint32_t dst = sb + (uint32_t)s * ST_BYTES;
                bulk_g2s(dst,          srcA + (size_t)kt * BLKA, BLKA, mfull + s * 8);
                bulk_g2s(dst + 16384u, srcB + (size_t)kt * BLKB, BLKB, mfull + s * 8);
                if (++s == 3) { s = 0; r++; }
            }
        }
        return;
    }

    // consumers: wm in [0,2) (64 M-rows), wn in [0,4) (32 N-cols)
    const int wm = wid >> 2, wn = wid & 3;
    const bool skipw = (m64 && wm == 1);

    const int lrA = (lane & 7) + ((lane >> 3) & 1) * 8;
    const int cA0 = lane >> 4;
    uint32_t a_off[4]; int a_rs[4];
    #pragma unroll
    for (int mf = 0; mf < 4; mf++) {
        int rr = wm * 64 + mf * 16 + lrA;
        a_off[mf] = (uint32_t)(rr * 128);
        a_rs[mf] = rr & 7;
    }
    const int lrB = (lane & 7) + ((lane >> 4) << 3);
    const int cB0 = (lane >> 3) & 1;
    uint32_t b_off[2]; int b_rs[2];
    #pragma unroll
    for (int p = 0; p < 2; p++) {
        int rr = wn * 32 + p * 16 + lrB;
        b_off[p] = (uint32_t)(rr * 128);
        b_rs[p] = rr & 7;
    }

    float acc[4][4][4];
    #pragma unroll
    for (int i = 0; i < 4; i++)
        #pragma unroll
        for (int j = 0; j < 4; j++)
            #pragma unroll
            for (int q = 0; q < 4; q++) acc[i][j][q] = 0.f;

    int s = 0, r = 0;
    for (int kt = 0; kt < KT; kt++) {
        mbar_wait(mfull + s * 8, r & 1);
        if (!skipw) {
            const uint32_t stA = sb + (uint32_t)s * ST_BYTES;
            const uint32_t stB = stA + 16384u;
            #pragma unroll
            for (int ks = 0; ks < 4; ks++) {
                uint32_t af[16], bh[8], bl[8];
                const int cA = cA0 + ks * 2;
                #pragma unroll
                for (int mf = 0; mf < 4; mf++) {
                    uint32_t o = a_off[mf] + (uint32_t)((cA ^ a_rs[mf]) << 4);
                    ldsm4(af[mf*4], af[mf*4+1], af[mf*4+2], af[mf*4+3], stA + o);
                }
                const int cB = cB0 + ks * 2;
                #pragma unroll
                for (int p = 0; p < 2; p++) {
                    uint32_t o = b_off[p] + (uint32_t)((cB ^ b_rs[p]) << 4);
                    ldsm4(bh[p*4], bh[p*4+1], bh[p*4+2], bh[p*4+3], stB + o);
                    ldsm4(bl[p*4], bl[p*4+1], bl[p*4+2], bl[p*4+3], stB + 16384u + o);
                }
                // pass 1: A * B_hi (fp32 accumulate)
                #pragma unroll
                for (int mf = 0; mf < 4; mf++)
                    #pragma unroll
                    for (int nf = 0; nf < 4; nf++)
                        mma_f16f32(acc[mf][nf], &af[mf * 4], &bh[(nf >> 1) * 4 + (nf & 1) * 2]);
                // pass 2: A * B_lo (fp32 accumulate, same accumulators)
                #pragma unroll
                for (int mf = 0; mf < 4; mf++)
                    #pragma unroll
                    for (int nf = 0; nf < 4; nf++)
                        mma_f16f32(acc[mf][nf], &af[mf * 4], &bl[(nf >> 1) * 4 + (nf & 1) * 2]);
            }
        }
        if (lane == 0) mbar_arrive(mempty + s * 8);
        if (++s == 3) { s = 0; r++; }
    }

    if (skipw) return;

    // ---------------- epilogue ----------------
    #pragma unroll
    for (int mf = 0; mf < 4; mf++)
        #pragma unroll
        for (int nf = 0; nf < 4; nf++) {
            const float* c = acc[mf][nf];
            const int rbase = wm * 64 + mf * 16 + (lane >> 2);
            const int ncol = nt * 128 + wn * 32 + nf * 8 + (lane & 3) * 2;
            #pragma unroll
            for (int hh = 0; hh < 2; hh++) {
                const int rl = rbase + hh * 8;
                if (PHASE == 1) {
                    if (s_tok[rl] < 0) continue;
                    float v0 = gelu_exact(c[hh * 2]);
                    float v1 = gelu_exact(c[hh * 2 + 1]);
                    const int kt2 = ncol >> 6, kl = ncol & 63;
                    char* blk = g_H + ((size_t)gt * KT2 + kt2) * BLKA;
                    uint32_t off = (uint32_t)(rl * 128)
                                 + (uint32_t)((((kl >> 3) ^ (rl & 7)) << 4) + (kl & 7) * 2);
                    *(uint32_t*)(blk + off) = pack2h(v0, v1);
                } else {
                    const int tk = s_tok[rl];
                    if (tk < 0) continue;
                    const float wv = s_wv[rl];
                    float2 o = make_float2(c[hh * 2] * wv, c[hh * 2 + 1] * wv);
                    *(float2*)(out + (size_t)tk * D_MODEL + ncol) = o;
                }
            }
        }
}

// ---------------- launch ----------------
extern "C" void kernel_launch(void* const* d_in, const int* in_sizes, int n_in,
                              void* d_out, int out_size) {
    const float* x  = (const float*)d_in[0];
    const float* Wr = (const float*)d_in[1];
    const float* W1 = (const float*)d_in[2];
    const float* W2 = (const float*)d_in[3];
    float* out = (float*)d_out;

    cudaFuncSetAttribute(moe_gemm<1>, cudaFuncAttributeMaxDynamicSharedMemorySize, SMEM_TOT);
    cudaFuncSetAttribute(moe_gemm<2>, cudaFuncAttributeMaxDynamicSharedMemorySize, SMEM_TOT);

    router_kernel<<<T_TOK, 256>>>(x, Wr);
    bucket_kernel<<<1, 1024>>>();
    gather_a_kernel<<<dim3(PM, KT1), 256>>>(x);
    transconv1_kernel<<<dim3(NT1, KT1, NE), 256>>>(W1);
    moe_gemm<1><<<dim3(NT1, MAXT), 352, SMEM_TOT>>>(W2, nullptr);   // tc2 fused in helpers
    moe_gemm<2><<<dim3(NT2, MAXT), 352, SMEM_TOT>>>(W2, out);
}

// round 13
// speedup vs baseline: 5.8836x; 1.6388x over previous
#include <cuda_runtime.h>
#include <cuda_bf16.h>
#include <cuda_fp16.h>
#include <math.h>
#include <stdint.h>

#define T_TOK   4096
#define D_MODEL 2048
#define FF      8192
#define NE      8
#define PM      40
#define MAXT    40
#define KT1     32
#define NT1     64
#define KT2     128
#define NT2     16
#define BLKA    16384   // fp16 plane: 128 rows x 128B (A, H, and now B blocks)

// ---------------- scratch ----------------
__device__ int   g_idx[T_TOK];
__device__ float g_w[T_TOK];
__device__ int   g_order[T_TOK];
__device__ int   g_off[NE + 1];
__device__ int   g_ptok[PM * 128];
__device__ int   g_tile_e[MAXT];
__device__ int   g_tile_gt[MAXT];
__device__ int   g_tile_m64[MAXT];
__device__ int   g_ntiles;

__device__ __align__(128) char g_A [(size_t)PM * KT1 * BLKA];
__device__ __align__(128) char g_B1[(size_t)NE * NT1 * KT1 * BLKA];
__device__ __align__(128) char g_B2[(size_t)NE * NT2 * KT2 * BLKA];
__device__ __align__(128) char g_H [(size_t)PM * KT2 * BLKA];

// ---------------- helpers ----------------
__device__ __forceinline__ uint32_t s2u(const void* p) {
    uint32_t a;
    asm("{ .reg .u64 t; cvta.to.shared.u64 t, %1; cvt.u32.u64 %0, t; }" : "=r"(a) : "l"(p));
    return a;
}
__device__ __forceinline__ uint32_t pack2h(float a, float b) {
    __half2 t = __floats2half2_rn(a, b);
    return *(uint32_t*)&t;
}
__device__ __forceinline__ float gelu_exact(float v) {
    return 0.5f * v * (1.0f + erff(v * 0.70710678118654752440f));
}
__device__ __forceinline__ void mbar_init(uint32_t m, uint32_t c) {
    asm volatile("mbarrier.init.shared::cta.b64 [%0], %1;" :: "r"(m), "r"(c) : "memory");
}
__device__ __forceinline__ void mbar_arrive(uint32_t m) {
    asm volatile("mbarrier.arrive.shared::cta.b64 _, [%0];" :: "r"(m) : "memory");
}
__device__ __forceinline__ void mbar_expect_tx(uint32_t m, uint32_t b) {
    asm volatile("mbarrier.arrive.expect_tx.shared::cta.b64 _, [%0], %1;"
                 :: "r"(m), "r"(b) : "memory");
}
__device__ __forceinline__ void mbar_wait(uint32_t m, uint32_t ph) {
    asm volatile(
        "{\n\t.reg .pred P;\n"
        "W_%=:\n\t"
        "mbarrier.try_wait.parity.acquire.cta.shared::cta.b64 P, [%0], %1, 0x989680;\n\t"
        "@P bra.uni D_%=;\n\t"
        "bra.uni W_%=;\n"
        "D_%=:\n\t}"
        :: "r"(m), "r"(ph) : "memory");
}
__device__ __forceinline__ void bulk_g2s(uint32_t dst, const void* src, uint32_t bytes,
                                         uint32_t mbar) {
    asm volatile(
        "cp.async.bulk.shared::cta.global.mbarrier::complete_tx::bytes [%0], [%1], %2, [%3];"
        :: "r"(dst), "l"(src), "r"(bytes), "r"(mbar) : "memory");
}
__device__ __forceinline__ void ldsm4(uint32_t& r0, uint32_t& r1, uint32_t& r2, uint32_t& r3,
                                      uint32_t a) {
    asm volatile("ldmatrix.sync.aligned.m8n8.x4.shared.b16 {%0,%1,%2,%3}, [%4];"
                 : "=r"(r0), "=r"(r1), "=r"(r2), "=r"(r3) : "r"(a));
}
__device__ __forceinline__ void mma_f16f32(float* d, const uint32_t* a, const uint32_t* b) {
    asm volatile(
        "mma.sync.aligned.m16n8k16.row.col.f32.f16.f16.f32 "
        "{%0,%1,%2,%3}, {%4,%5,%6,%7}, {%8,%9}, {%0,%1,%2,%3};"
        : "+f"(d[0]), "+f"(d[1]), "+f"(d[2]), "+f"(d[3])
        : "r"(a[0]), "r"(a[1]), "r"(a[2]), "r"(a[3]), "r"(b[0]), "r"(b[1]));
}

// ---------------- router ----------------
__global__ void router_kernel(const float* __restrict__ x, const float* __restrict__ Wr) {
    __shared__ float sx[D_MODEL];
    __shared__ float slog[NE];
    const int t = blockIdx.x, tid = threadIdx.x;
    const float* xr = x + (size_t)t * D_MODEL;
    for (int i = tid * 4; i < D_MODEL; i += 256 * 4)
        *(float4*)(sx + i) = *(const float4*)(xr + i);
    __syncthreads();
    const int w = tid >> 5, lane = tid & 31;
    const float* wr = Wr + (size_t)w * D_MODEL;
    float s = 0.f;
    for (int i = lane; i < D_MODEL; i += 32) s += sx[i] * wr[i];
    #pragma unroll
    for (int o = 16; o; o >>= 1) s += __shfl_xor_sync(0xffffffffu, s, o);
    if (lane == 0) slog[w] = s;
    __syncthreads();
    if (tid == 0) {
        float mx = slog[0]; int mi = 0;
        #pragma unroll
        for (int e = 1; e < NE; e++) if (slog[e] > mx) { mx = slog[e]; mi = e; }
        float sum = 0.f;
        #pragma unroll
        for (int e = 0; e < NE; e++) sum += expf(slog[e] - mx);
        g_idx[t] = mi;
        g_w[t] = 1.0f / sum;
    }
}

// ---------------- bucket + tile table + padded token map ----------------
__global__ void bucket_kernel() {
    __shared__ int cnt[NE], off[NE], soff[NE], spo[NE + 1];
    const int tid = threadIdx.x;
    if (tid < NE) cnt[tid] = 0;
    __syncthreads();
    for (int t = tid; t < T_TOK; t += blockDim.x) atomicAdd(&cnt[g_idx[t]], 1);
    __syncthreads();
    if (tid == 0) {
        int acc = 0, pacc = 0, nt = 0;
        #pragma unroll
        for (int e = 0; e < NE; e++) {
            off[e] = acc; soff[e] = acc; g_off[e] = acc;
            spo[e] = pacc;
            int tiles = (cnt[e] + 127) >> 7;
            for (int i = 0; i < tiles; i++) {
                g_tile_e[nt] = e;
                g_tile_gt[nt] = (pacc >> 7) + i;
                g_tile_m64[nt] = (cnt[e] - i * 128) <= 64;
                nt++;
            }
            acc += cnt[e];
            pacc += tiles << 7;
        }
        g_off[NE] = acc;
        spo[NE] = pacc;
        g_ntiles = nt;
    }
    __syncthreads();
    for (int t = tid; t < T_TOK; t += blockDim.x) {
        int p = atomicAdd(&off[g_idx[t]], 1);
        g_order[p] = t;
    }
    __syncthreads();
    for (int p = tid; p < PM * 128; p += blockDim.x) {
        int tk = -1;
        #pragma unroll
        for (int e = 0; e < NE; e++)
            if (p >= spo[e] && p < spo[e] + cnt[e])
                tk = g_order[soff[e] + (p - spo[e])];
        g_ptok[p] = tk;
    }
}

// ---------------- prepass: gather x rows -> swizzled fp16 blocks ----------------
__global__ void __launch_bounds__(256) gather_a_kernel(const float* __restrict__ x) {
    const int gt = blockIdx.x, kt = blockIdx.y;
    const int tid = threadIdx.x;
    const int r = tid >> 1, half = tid & 1;
    const int tok = g_ptok[gt * 128 + r];
    uint32_t fw[16];
    if (tok >= 0) {
        const float4* src = (const float4*)(x + (size_t)tok * D_MODEL + kt * 64 + half * 32);
        #pragma unroll
        for (int q = 0; q < 8; q++) {
            float4 v = src[q];
            fw[q * 2]     = pack2h(v.x, v.y);
            fw[q * 2 + 1] = pack2h(v.z, v.w);
        }
    } else {
        #pragma unroll
        for (int q = 0; q < 16; q++) fw[q] = 0;
    }
    char* blk = g_A + ((size_t)gt * KT1 + kt) * BLKA;
    #pragma unroll
    for (int c = 0; c < 4; c++) {
        int ch = half * 4 + c;
        uint32_t off = (uint32_t)(r * 128) + (uint32_t)((ch ^ (r & 7)) << 4);
        *(uint4*)(blk + off) = ((uint4*)fw)[c];
    }
}

// ---------------- prepass: transpose + convert W1 (single fp16 plane) ----------------
__global__ void __launch_bounds__(256) transconv1_kernel(const float* __restrict__ src) {
    __shared__ float s[64 * 132];
    const int nt = blockIdx.x, kt = blockIdx.y, e = blockIdx.z;
    const int tid = threadIdx.x;
    const float* sp = src + (size_t)e * D_MODEL * FF + (size_t)(kt * 64) * FF + nt * 128;
    #pragma unroll
    for (int i = 0; i < 8; i++) {
        int q = i * 256 + tid;
        int k = q >> 5, c4 = q & 31;
        *(float4*)(s + k * 132 + c4 * 4) = *(const float4*)(sp + (size_t)k * FF + c4 * 4);
    }
    __syncthreads();
    const int n = tid >> 1, half = tid & 1;
    uint32_t hw[16];
    #pragma unroll
    for (int jw = 0; jw < 16; jw++) {
        float v0 = s[(half * 32 + jw * 2) * 132 + n];
        float v1 = s[(half * 32 + jw * 2 + 1) * 132 + n];
        hw[jw] = pack2h(v0, v1);
    }
    char* dst = g_B1 + (((size_t)e * NT1 + nt) * KT1 + kt) * BLKA;
    #pragma unroll
    for (int c = 0; c < 4; c++) {
        int ch = half * 4 + c;
        uint32_t off = (uint32_t)(n * 128) + (uint32_t)((ch ^ (n & 7)) << 4);
        *(uint4*)(dst + off) = ((uint4*)hw)[c];
    }
}

// ---------------- warp-MMA grouped GEMM (pure fp16) + tc2 helper warps ---------------
// 352 threads: warps 0-7 consumers, warp 8 producer, warps 9-10 (64 thr) tc2 helpers.
// Stage (32KB): [A fp16 16KB][B fp16 16KB], 3 stages.
#define ST_BYTES   32768u
#define SM_TOKOFF  98304
#define SM_WVOFF   98816
#define SM_MBROFF  99328
#define SM_TC      99392           // 32 x 132 fp32 transpose buffer (16,896 B)
#define SMEM_TOT   116288

template <int PHASE>
__global__ void __launch_bounds__(352, 1)
moe_gemm(const float* __restrict__ W2, float* __restrict__ out) {
    constexpr int KT = (PHASE == 1) ? KT1 : KT2;
    const int tix = blockIdx.y;
    const int nt = blockIdx.x;
    const int tid = threadIdx.x;
    const int wid = tid >> 5, lane = tid & 31;

    extern __shared__ char smem[];
    const uint32_t sb = s2u(smem);
    int* s_tok = (int*)(smem + SM_TOKOFF);
    float* s_wv = (float*)(smem + SM_WVOFF);
    const uint32_t mfull = sb + SM_MBROFF;
    const uint32_t mempty = sb + SM_MBROFF + 24;

    // ---------- tc2 helper warps (warps 9,10 = 64 threads) ----------
    if (wid >= 9) {
        if (PHASE == 1 && tix < 32) {
            float* tb = (float*)(smem + SM_TC);
            const int hl = tid - 288;                  // 0..63
            const int bi = nt * 32 + tix;              // 0..2047
            for (int u = 0; u < 8; u++) {
                const int unit = bi * 8 + u;           // 0..16383
                const int e2 = unit >> 11;
                const int rem = unit & 2047;
                const int nt2 = rem >> 7;
                const int kt2 = rem & 127;
                const float* src = W2 + (size_t)e2 * FF * D_MODEL
                                 + (size_t)(kt2 * 64) * D_MODEL + nt2 * 128;
                char* dst = g_B2 + (((size_t)e2 * NT2 + nt2) * KT2 + kt2) * BLKA;
                #pragma unroll
                for (int half = 0; half < 2; half++) {
                    #pragma unroll
                    for (int i = 0; i < 16; i++) {
                        int q = i * 64 + hl;
                        int r = q >> 5, c4 = q & 31;
                        *(float4*)(tb + r * 132 + c4 * 4) =
                            *(const float4*)(src + (size_t)(half * 32 + r) * D_MODEL + c4 * 4);
                    }
                    asm volatile("bar.sync 1, 64;" ::: "memory");
                    #pragma unroll
                    for (int nn = 0; nn < 2; nn++) {
                        const int n = hl * 2 + nn;
                        uint32_t hw[16];
                        #pragma unroll
                        for (int j = 0; j < 16; j++) {
                            float v0 = tb[(j * 2) * 132 + n];
                            float v1 = tb[(j * 2 + 1) * 132 + n];
                            hw[j] = pack2h(v0, v1);
                        }
                        #pragma unroll
                        for (int c = 0; c < 4; c++) {
                            int ch = half * 4 + c;
                            uint32_t off = (uint32_t)(n * 128)
                                         + (uint32_t)((ch ^ (n & 7)) << 4);
                            *(uint4*)(dst + off) = ((uint4*)hw)[c];
                        }
                    }
                    asm volatile("bar.sync 1, 64;" ::: "memory");
                }
            }
        }
        return;
    }

    if (tix >= g_ntiles) return;
    const int e = g_tile_e[tix];
    const int gt = g_tile_gt[tix];
    const int m64 = g_tile_m64[tix];

    if (tid < 128) {
        int tk = g_ptok[gt * 128 + tid];
        s_tok[tid] = tk;
        s_wv[tid] = (tk >= 0) ? g_w[tk] : 0.f;
    }
    if (tid == 0) {
        #pragma unroll
        for (int i = 0; i < 3; i++) { mbar_init(mfull + i * 8, 1); mbar_init(mempty + i * 8, 8); }
    }
    asm volatile("bar.sync 2, 288;" ::: "memory");   // warps 0-8 only

    if (wid == 8) {
        if (lane == 0) {
            const char* srcA = (PHASE == 1) ? (g_A + (size_t)gt * KT1 * BLKA)
                                            : (g_H + (size_t)gt * KT2 * BLKA);
            const char* srcB = (PHASE == 1)
                ? (g_B1 + ((size_t)(e * NT1 + nt)) * KT1 * BLKA)
                : (g_B2 + ((size_t)(e * NT2 + nt)) * KT2 * BLKA);
            int s = 0, r = 0;
            for (int kt = 0; kt < KT; kt++) {
                if (r > 0) mbar_wait(mempty + s * 8, (r - 1) & 1);
                mbar_expect_tx(mfull + s * 8, ST_BYTES);
                uint32_t dst = sb + (uint32_t)s * ST_BYTES;
                bulk_g2s(dst,          srcA + (size_t)kt * BLKA, BLKA, mfull + s * 8);
                bulk_g2s(dst + 16384u, srcB + (size_t)kt * BLKA, BLKA, mfull + s * 8);
                if (++s == 3) { s = 0; r++; }
            }
        }
        return;
    }

    // consumers: wm in [0,2) (64 M-rows), wn in [0,4) (32 N-cols)
    const int wm = wid >> 2, wn = wid & 3;
    const bool skipw = (m64 && wm == 1);

    const int lrA = (lane & 7) + ((lane >> 3) & 1) * 8;
    const int cA0 = lane >> 4;
    uint32_t a_off[4]; int a_rs[4];
    #pragma unroll
    for (int mf = 0; mf < 4; mf++) {
        int rr = wm * 64 + mf * 16 + lrA;
        a_off[mf] = (uint32_t)(rr * 128);
        a_rs[mf] = rr & 7;
    }
    const int lrB = (lane & 7) + ((lane >> 4) << 3);
    const int cB0 = (lane >> 3) & 1;
    uint32_t b_off[2]; int b_rs[2];
    #pragma unroll
    for (int p = 0; p < 2; p++) {
        int rr = wn * 32 + p * 16 + lrB;
        b_off[p] = (uint32_t)(rr * 128);
        b_rs[p] = rr & 7;
    }

    float acc[4][4][4];
    #pragma unroll
    for (int i = 0; i < 4; i++)
        #pragma unroll
        for (int j = 0; j < 4; j++)
            #pragma unroll
            for (int q = 0; q < 4; q++) acc[i][j][q] = 0.f;

    int s = 0, r = 0;
    for (int kt = 0; kt < KT; kt++) {
        mbar_wait(mfull + s * 8, r & 1);
        if (!skipw) {
            const uint32_t stA = sb + (uint32_t)s * ST_BYTES;
            const uint32_t stB = stA + 16384u;
            #pragma unroll
            for (int ks = 0; ks < 4; ks++) {
                uint32_t af[16], bf[8];
                const int cA = cA0 + ks * 2;
                #pragma unroll
                for (int mf = 0; mf < 4; mf++) {
                    uint32_t o = a_off[mf] + (uint32_t)((cA ^ a_rs[mf]) << 4);
                    ldsm4(af[mf*4], af[mf*4+1], af[mf*4+2], af[mf*4+3], stA + o);
                }
                const int cB = cB0 + ks * 2;
                #pragma unroll
                for (int p = 0; p < 2; p++) {
                    uint32_t o = b_off[p] + (uint32_t)((cB ^ b_rs[p]) << 4);
                    ldsm4(bf[p*4], bf[p*4+1], bf[p*4+2], bf[p*4+3], stB + o);
                }
                #pragma unroll
                for (int mf = 0; mf < 4; mf++)
                    #pragma unroll
                    for (int nf = 0; nf < 4; nf++)
                        mma_f16f32(acc[mf][nf], &af[mf * 4], &bf[(nf >> 1) * 4 + (nf & 1) * 2]);
            }
        }
        if (lane == 0) mbar_arrive(mempty + s * 8);
        if (++s == 3) { s = 0; r++; }
    }

    if (skipw) return;

    // ---------------- epilogue ----------------
    #pragma unroll
    for (int mf = 0; mf < 4; mf++)
        #pragma unroll
        for (int nf = 0; nf < 4; nf++) {
            const float* c = acc[mf][nf];
            const int rbase = wm * 64 + mf * 16 + (lane >> 2);
            const int ncol = nt * 128 + wn * 32 + nf * 8 + (lane & 3) * 2;
            #pragma unroll
            for (int hh = 0; hh < 2; hh++) {
                const int rl = rbase + hh * 8;
                if (PHASE == 1) {
                    if (s_tok[rl] < 0) continue;
                    float v0 = gelu_exact(c[hh * 2]);
                    float v1 = gelu_exact(c[hh * 2 + 1]);
                    const int kt2 = ncol >> 6, kl = ncol & 63;
                    char* blk = g_H + ((size_t)gt * KT2 + kt2) * BLKA;
                    uint32_t off = (uint32_t)(rl * 128)
                                 + (uint32_t)((((kl >> 3) ^ (rl & 7)) << 4) + (kl & 7) * 2);
                    *(uint32_t*)(blk + off) = pack2h(v0, v1);
                } else {
                    const int tk = s_tok[rl];
                    if (tk < 0) continue;
                    const float wv = s_wv[rl];
                    float2 o = make_float2(c[hh * 2] * wv, c[hh * 2 + 1] * wv);
                    *(float2*)(out + (size_t)tk * D_MODEL + ncol) = o;
                }
            }
        }
}

// ---------------- launch ----------------
extern "C" void kernel_launch(void* const* d_in, const int* in_sizes, int n_in,
                              void* d_out, int out_size) {
    const float* x  = (const float*)d_in[0];
    const float* Wr = (const float*)d_in[1];
    const float* W1 = (const float*)d_in[2];
    const float* W2 = (const float*)d_in[3];
    float* out = (float*)d_out;

    cudaFuncSetAttribute(moe_gemm<1>, cudaFuncAttributeMaxDynamicSharedMemorySize, SMEM_TOT);
    cudaFuncSetAttribute(moe_gemm<2>, cudaFuncAttributeMaxDynamicSharedMemorySize, SMEM_TOT);

    router_kernel<<<T_TOK, 256>>>(x, Wr);
    bucket_kernel<<<1, 1024>>>();
    gather_a_kernel<<<dim3(PM, KT1), 256>>>(x);
    transconv1_kernel<<<dim3(NT1, KT1, NE), 256>>>(W1);
    moe_gemm<1><<<dim3(NT1, MAXT), 352, SMEM_TOT>>>(W2, nullptr);   // tc2 fused in helpers
    moe_gemm<2><<<dim3(NT2, MAXT), 352, SMEM_TOT>>>(W2, out);
}

// round 14
// speedup vs baseline: 5.8859x; 1.0004x over previous
#include <cuda_runtime.h>
#include <cuda_bf16.h>
#include <cuda_fp16.h>
#include <math.h>
#include <stdint.h>

#define T_TOK   4096
#define D_MODEL 2048
#define FF      8192
#define NE      8
#define PM      40
#define MAXT    40
#define KT1     32
#define NT1     64
#define KT2     128
#define NT2     16
#define BLKA    16384   // fp16 plane: 128 rows x 128B

// ---------------- scratch ----------------
__device__ int   g_idx[T_TOK];
__device__ float g_w[T_TOK];
__device__ int   g_order[T_TOK];
__device__ int   g_off[NE + 1];
__device__ int   g_ptok[PM * 128];
__device__ int   g_tile_e[MAXT];
__device__ int   g_tile_gt[MAXT];
__device__ int   g_tile_m64[MAXT];
__device__ int   g_ntiles;

__device__ __align__(128) char g_A [(size_t)PM * KT1 * BLKA];
__device__ __align__(128) char g_B1[(size_t)NE * NT1 * KT1 * BLKA];
__device__ __align__(128) char g_B2[(size_t)NE * NT2 * KT2 * BLKA];
__device__ __align__(128) char g_H [(size_t)PM * KT2 * BLKA];

// ---------------- helpers ----------------
__device__ __forceinline__ uint32_t s2u(const void* p) {
    uint32_t a;
    asm("{ .reg .u64 t; cvta.to.shared.u64 t, %1; cvt.u32.u64 %0, t; }" : "=r"(a) : "l"(p));
    return a;
}
__device__ __forceinline__ uint32_t pack2h(float a, float b) {
    __half2 t = __floats2half2_rn(a, b);
    return *(uint32_t*)&t;
}
__device__ __forceinline__ float gelu_exact(float v) {
    return 0.5f * v * (1.0f + erff(v * 0.70710678118654752440f));
}
__device__ __forceinline__ void mbar_init(uint32_t m, uint32_t c) {
    asm volatile("mbarrier.init.shared::cta.b64 [%0], %1;" :: "r"(m), "r"(c) : "memory");
}
__device__ __forceinline__ void mbar_arrive(uint32_t m) {
    asm volatile("mbarrier.arrive.shared::cta.b64 _, [%0];" :: "r"(m) : "memory");
}
__device__ __forceinline__ void mbar_expect_tx(uint32_t m, uint32_t b) {
    asm volatile("mbarrier.arrive.expect_tx.shared::cta.b64 _, [%0], %1;"
                 :: "r"(m), "r"(b) : "memory");
}
__device__ __forceinline__ void mbar_wait(uint32_t m, uint32_t ph) {
    asm volatile(
        "{\n\t.reg .pred P;\n"
        "W_%=:\n\t"
        "mbarrier.try_wait.parity.acquire.cta.shared::cta.b64 P, [%0], %1, 0x989680;\n\t"
        "@P bra.uni D_%=;\n\t"
        "bra.uni W_%=;\n"
        "D_%=:\n\t}"
        :: "r"(m), "r"(ph) : "memory");
}
__device__ __forceinline__ void bulk_g2s(uint32_t dst, const void* src, uint32_t bytes,
                                         uint32_t mbar) {
    asm volatile(
        "cp.async.bulk.shared::cta.global.mbarrier::complete_tx::bytes [%0], [%1], %2, [%3];"
        :: "r"(dst), "l"(src), "r"(bytes), "r"(mbar) : "memory");
}
__device__ __forceinline__ void bulk_s2g(void* dst, uint32_t src, uint32_t bytes) {
    asm volatile(
        "cp.async.bulk.global.shared::cta.bulk_group [%0], [%1], %2;"
        :: "l"(dst), "r"(src), "r"(bytes) : "memory");
}
__device__ __forceinline__ void ldsm4(uint32_t& r0, uint32_t& r1, uint32_t& r2, uint32_t& r3,
                                      uint32_t a) {
    asm volatile("ldmatrix.sync.aligned.m8n8.x4.shared.b16 {%0,%1,%2,%3}, [%4];"
                 : "=r"(r0), "=r"(r1), "=r"(r2), "=r"(r3) : "r"(a));
}
__device__ __forceinline__ void mma_f16f32(float* d, const uint32_t* a, const uint32_t* b) {
    asm volatile(
        "mma.sync.aligned.m16n8k16.row.col.f32.f16.f16.f32 "
        "{%0,%1,%2,%3}, {%4,%5,%6,%7}, {%8,%9}, {%0,%1,%2,%3};"
        : "+f"(d[0]), "+f"(d[1]), "+f"(d[2]), "+f"(d[3])
        : "r"(a[0]), "r"(a[1]), "r"(a[2]), "r"(a[3]), "r"(b[0]), "r"(b[1]));
}

// ---------------- router ----------------
__global__ void router_kernel(const float* __restrict__ x, const float* __restrict__ Wr) {
    __shared__ float sx[D_MODEL];
    __shared__ float slog[NE];
    const int t = blockIdx.x, tid = threadIdx.x;
    const float* xr = x + (size_t)t * D_MODEL;
    for (int i = tid * 4; i < D_MODEL; i += 256 * 4)
        *(float4*)(sx + i) = *(const float4*)(xr + i);
    __syncthreads();
    const int w = tid >> 5, lane = tid & 31;
    const float* wr = Wr + (size_t)w * D_MODEL;
    float s = 0.f;
    for (int i = lane; i < D_MODEL; i += 32) s += sx[i] * wr[i];
    #pragma unroll
    for (int o = 16; o; o >>= 1) s += __shfl_xor_sync(0xffffffffu, s, o);
    if (lane == 0) slog[w] = s;
    __syncthreads();
    if (tid == 0) {
        float mx = slog[0]; int mi = 0;
        #pragma unroll
        for (int e = 1; e < NE; e++) if (slog[e] > mx) { mx = slog[e]; mi = e; }
        float sum = 0.f;
        #pragma unroll
        for (int e = 0; e < NE; e++) sum += expf(slog[e] - mx);
        g_idx[t] = mi;
        g_w[t] = 1.0f / sum;
    }
}

// ---------------- bucket + tile table + padded token map ----------------
__global__ void bucket_kernel() {
    __shared__ int cnt[NE], off[NE], soff[NE], spo[NE + 1];
    const int tid = threadIdx.x;
    if (tid < NE) cnt[tid] = 0;
    __syncthreads();
    for (int t = tid; t < T_TOK; t += blockDim.x) atomicAdd(&cnt[g_idx[t]], 1);
    __syncthreads();
    if (tid == 0) {
        int acc = 0, pacc = 0, nt = 0;
        #pragma unroll
        for (int e = 0; e < NE; e++) {
            off[e] = acc; soff[e] = acc; g_off[e] = acc;
            spo[e] = pacc;
            int tiles = (cnt[e] + 127) >> 7;
            for (int i = 0; i < tiles; i++) {
                g_tile_e[nt] = e;
                g_tile_gt[nt] = (pacc >> 7) + i;
                g_tile_m64[nt] = (cnt[e] - i * 128) <= 64;
                nt++;
            }
            acc += cnt[e];
            pacc += tiles << 7;
        }
        g_off[NE] = acc;
        spo[NE] = pacc;
        g_ntiles = nt;
    }
    __syncthreads();
    for (int t = tid; t < T_TOK; t += blockDim.x) {
        int p = atomicAdd(&off[g_idx[t]], 1);
        g_order[p] = t;
    }
    __syncthreads();
    for (int p = tid; p < PM * 128; p += blockDim.x) {
        int tk = -1;
        #pragma unroll
        for (int e = 0; e < NE; e++)
            if (p >= spo[e] && p < spo[e] + cnt[e])
                tk = g_order[soff[e] + (p - spo[e])];
        g_ptok[p] = tk;
    }
}

// ---------------- prepass: gather x rows -> swizzled fp16 blocks ----------------
__global__ void __launch_bounds__(256) gather_a_kernel(const float* __restrict__ x) {
    const int gt = blockIdx.x, kt = blockIdx.y;
    const int tid = threadIdx.x;
    const int r = tid >> 1, half = tid & 1;
    const int tok = g_ptok[gt * 128 + r];
    uint32_t fw[16];
    if (tok >= 0) {
        const float4* src = (const float4*)(x + (size_t)tok * D_MODEL + kt * 64 + half * 32);
        #pragma unroll
        for (int q = 0; q < 8; q++) {
            float4 v = src[q];
            fw[q * 2]     = pack2h(v.x, v.y);
            fw[q * 2 + 1] = pack2h(v.z, v.w);
        }
    } else {
        #pragma unroll
        for (int q = 0; q < 16; q++) fw[q] = 0;
    }
    char* blk = g_A + ((size_t)gt * KT1 + kt) * BLKA;
    #pragma unroll
    for (int c = 0; c < 4; c++) {
        int ch = half * 4 + c;
        uint32_t off = (uint32_t)(r * 128) + (uint32_t)((ch ^ (r & 7)) << 4);
        *(uint4*)(blk + off) = ((uint4*)fw)[c];
    }
}

// ---------------- prepass: transpose + convert W1 (single fp16 plane) ----------------
__global__ void __launch_bounds__(256) transconv1_kernel(const float* __restrict__ src) {
    __shared__ float s[64 * 132];
    const int nt = blockIdx.x, kt = blockIdx.y, e = blockIdx.z;
    const int tid = threadIdx.x;
    const float* sp = src + (size_t)e * D_MODEL * FF + (size_t)(kt * 64) * FF + nt * 128;
    #pragma unroll
    for (int i = 0; i < 8; i++) {
        int q = i * 256 + tid;
        int k = q >> 5, c4 = q & 31;
        *(float4*)(s + k * 132 + c4 * 4) = *(const float4*)(sp + (size_t)k * FF + c4 * 4);
    }
    __syncthreads();
    const int n = tid >> 1, half = tid & 1;
    uint32_t hw[16];
    #pragma unroll
    for (int jw = 0; jw < 16; jw++) {
        float v0 = s[(half * 32 + jw * 2) * 132 + n];
        float v1 = s[(half * 32 + jw * 2 + 1) * 132 + n];
        hw[jw] = pack2h(v0, v1);
    }
    char* dst = g_B1 + (((size_t)e * NT1 + nt) * KT1 + kt) * BLKA;
    #pragma unroll
    for (int c = 0; c < 4; c++) {
        int ch = half * 4 + c;
        uint32_t off = (uint32_t)(n * 128) + (uint32_t)((ch ^ (n & 7)) << 4);
        *(uint4*)(dst + off) = ((uint4*)hw)[c];
    }
}

// ---------------- warp-MMA grouped GEMM (pure fp16) + tc2 helpers + staged epilogue --
// 352 threads: warps 0-7 consumers, warp 8 producer, warps 9-10 (64 thr) tc2 helpers.
// Stage (32KB): [A fp16 16KB][B fp16 16KB], 3 stages. Epilogue reuses stage smem.
#define ST_BYTES   32768u
#define SM_TOKOFF  98304
#define SM_WVOFF   98816
#define SM_MBROFF  99328
#define SM_TC      99392           // 32 x 132 fp32 transpose buffer (16,896 B)
#define SMEM_TOT   116288

template <int PHASE>
__global__ void __launch_bounds__(352, 1)
moe_gemm(const float* __restrict__ W2, float* __restrict__ out) {
    constexpr int KT = (PHASE == 1) ? KT1 : KT2;
    const int tix = blockIdx.y;
    const int nt = blockIdx.x;
    const int tid = threadIdx.x;
    const int wid = tid >> 5, lane = tid & 31;

    extern __shared__ char smem[];
    const uint32_t sb = s2u(smem);
    int* s_tok = (int*)(smem + SM_TOKOFF);
    float* s_wv = (float*)(smem + SM_WVOFF);
    const uint32_t mfull = sb + SM_MBROFF;
    const uint32_t mempty = sb + SM_MBROFF + 24;

    // ---------- tc2 helper warps (warps 9,10 = 64 threads) ----------
    if (wid >= 9) {
        if (PHASE == 1 && tix < 32) {
            float* tb = (float*)(smem + SM_TC);
            const int hl = tid - 288;                  // 0..63
            const int bi = nt * 32 + tix;              // 0..2047
            for (int u = 0; u < 8; u++) {
                const int unit = bi * 8 + u;           // 0..16383
                const int e2 = unit >> 11;
                const int rem = unit & 2047;
                const int nt2 = rem >> 7;
                const int kt2 = rem & 127;
                const float* src = W2 + (size_t)e2 * FF * D_MODEL
                                 + (size_t)(kt2 * 64) * D_MODEL + nt2 * 128;
                char* dst = g_B2 + (((size_t)e2 * NT2 + nt2) * KT2 + kt2) * BLKA;
                #pragma unroll
                for (int half = 0; half < 2; half++) {
                    #pragma unroll
                    for (int i = 0; i < 16; i++) {
                        int q = i * 64 + hl;
                        int r = q >> 5, c4 = q & 31;
                        *(float4*)(tb + r * 132 + c4 * 4) =
                            *(const float4*)(src + (size_t)(half * 32 + r) * D_MODEL + c4 * 4);
                    }
                    asm volatile("bar.sync 1, 64;" ::: "memory");
                    #pragma unroll
                    for (int nn = 0; nn < 2; nn++) {
                        const int n = hl * 2 + nn;
                        uint32_t hw[16];
                        #pragma unroll
                        for (int j = 0; j < 16; j++) {
                            float v0 = tb[(j * 2) * 132 + n];
                            float v1 = tb[(j * 2 + 1) * 132 + n];
                            hw[j] = pack2h(v0, v1);
                        }
                        #pragma unroll
                        for (int c = 0; c < 4; c++) {
                            int ch = half * 4 + c;
                            uint32_t off = (uint32_t)(n * 128)
                                         + (uint32_t)((ch ^ (n & 7)) << 4);
                            *(uint4*)(dst + off) = ((uint4*)hw)[c];
                        }
                    }
                    asm volatile("bar.sync 1, 64;" ::: "memory");
                }
            }
        }
        return;
    }

    if (tix >= g_ntiles) return;
    const int e = g_tile_e[tix];
    const int gt = g_tile_gt[tix];
    const int m64 = g_tile_m64[tix];

    if (tid < 128) {
        int tk = g_ptok[gt * 128 + tid];
        s_tok[tid] = tk;
        s_wv[tid] = (tk >= 0) ? g_w[tk] : 0.f;
    }
    if (tid == 0) {
        #pragma unroll
        for (int i = 0; i < 3; i++) { mbar_init(mfull + i * 8, 1); mbar_init(mempty + i * 8, 8); }
    }
    asm volatile("bar.sync 2, 288;" ::: "memory");   // warps 0-8 only

    if (wid == 8) {
        if (lane == 0) {
            const char* srcA = (PHASE == 1) ? (g_A + (size_t)gt * KT1 * BLKA)
                                            : (g_H + (size_t)gt * KT2 * BLKA);
            const char* srcB = (PHASE == 1)
                ? (g_B1 + ((size_t)(e * NT1 + nt)) * KT1 * BLKA)
                : (g_B2 + ((size_t)(e * NT2 + nt)) * KT2 * BLKA);
            int s = 0, r = 0;
            for (int kt = 0; kt < KT; kt++) {
                if (r > 0) mbar_wait(mempty + s * 8, (r - 1) & 1);
                mbar_expect_tx(mfull + s * 8, ST_BYTES);
                uint32_t dst = sb + (uint32_t)s * ST_BYTES;
                bulk_g2s(dst,          srcA + (size_t)kt * BLKA, BLKA, mfull + s * 8);
                bulk_g2s(dst + 16384u, srcB + (size_t)kt * BLKA, BLKA, mfull + s * 8);
                if (++s == 3) { s = 0; r++; }
            }
        }
        return;
    }

    // consumers: wm in [0,2) (64 M-rows), wn in [0,4) (32 N-cols)
    const int wm = wid >> 2, wn = wid & 3;
    const bool skipw = (m64 && wm == 1);

    const int lrA = (lane & 7) + ((lane >> 3) & 1) * 8;
    const int cA0 = lane >> 4;
    uint32_t a_off[4]; int a_rs[4];
    #pragma unroll
    for (int mf = 0; mf < 4; mf++) {
        int rr = wm * 64 + mf * 16 + lrA;
        a_off[mf] = (uint32_t)(rr * 128);
        a_rs[mf] = rr & 7;
    }
    const int lrB = (lane & 7) + ((lane >> 4) << 3);
    const int cB0 = (lane >> 3) & 1;
    uint32_t b_off[2]; int b_rs[2];
    #pragma unroll
    for (int p = 0; p < 2; p++) {
        int rr = wn * 32 + p * 16 + lrB;
        b_off[p] = (uint32_t)(rr * 128);
        b_rs[p] = rr & 7;
    }

    float acc[4][4][4];
    #pragma unroll
    for (int i = 0; i < 4; i++)
        #pragma unroll
        for (int j = 0; j < 4; j++)
            #pragma unroll
            for (int q = 0; q < 4; q++) acc[i][j][q] = 0.f;

    int s = 0, r = 0;
    for (int kt = 0; kt < KT; kt++) {
        mbar_wait(mfull + s * 8, r & 1);
        if (!skipw) {
            const uint32_t stA = sb + (uint32_t)s * ST_BYTES;
            const uint32_t stB = stA + 16384u;
            #pragma unroll
            for (int ks = 0; ks < 4; ks++) {
                uint32_t af[16], bf[8];
                const int cA = cA0 + ks * 2;
                #pragma unroll
                for (int mf = 0; mf < 4; mf++) {
                    uint32_t o = a_off[mf] + (uint32_t)((cA ^ a_rs[mf]) << 4);
                    ldsm4(af[mf*4], af[mf*4+1], af[mf*4+2], af[mf*4+3], stA + o);
                }
                const int cB = cB0 + ks * 2;
                #pragma unroll
                for (int p = 0; p < 2; p++) {
                    uint32_t o = b_off[p] + (uint32_t)((cB ^ b_rs[p]) << 4);
                    ldsm4(bf[p*4], bf[p*4+1], bf[p*4+2], bf[p*4+3], stB + o);
                }
                #pragma unroll
                for (int mf = 0; mf < 4; mf++)
                    #pragma unroll
                    for (int nf = 0; nf < 4; nf++)
                        mma_f16f32(acc[mf][nf], &af[mf * 4], &bf[(nf >> 1) * 4 + (nf & 1) * 2]);
            }
        }
        if (lane == 0) mbar_arrive(mempty + s * 8);
        if (++s == 3) { s = 0; r++; }
    }

    // ---------------- staged epilogue (all 8 consumer warps participate) -------------
    asm volatile("bar.sync 3, 256;" ::: "memory");   // stage smem now safe to reuse
    if (PHASE == 1) {
        // stage as 2 swizzled H blocks (fp16), then bulk S2G
        if (!skipw) {
            #pragma unroll
            for (int mf = 0; mf < 4; mf++)
                #pragma unroll
                for (int nf = 0; nf < 4; nf++) {
                    const float* c = acc[mf][nf];
                    const int rbase = wm * 64 + mf * 16 + (lane >> 2);
                    const int cl = wn * 32 + nf * 8 + (lane & 3) * 2;
                    const int blk = cl >> 6, kl = cl & 63;
                    #pragma unroll
                    for (int hh = 0; hh < 2; hh++) {
                        const int rl = rbase + hh * 8;
                        float v0 = gelu_exact(c[hh * 2]);
                        float v1 = gelu_exact(c[hh * 2 + 1]);
                        uint32_t off = (uint32_t)(blk * 16384 + rl * 128)
                                     + (uint32_t)((((kl >> 3) ^ (rl & 7)) << 4) + (kl & 7) * 2);
                        *(uint32_t*)(smem + off) = pack2h(v0, v1);
                    }
                }
        }
        asm volatile("bar.sync 3, 256;" ::: "memory");
        if (tid == 0) {
            asm volatile("fence.proxy.async.shared::cta;" ::: "memory");
            char* d0 = g_H + ((size_t)gt * KT2 + nt * 2) * BLKA;
            bulk_s2g(d0,         sb,          16384u);
            bulk_s2g(d0 + BLKA,  sb + 16384u, 16384u);
            asm volatile("cp.async.bulk.commit_group;" ::: "memory");
            asm volatile("cp.async.bulk.wait_group 0;" ::: "memory");
        }
    } else {
        // stage fp32 (x wv) with 132-float row stride, then coalesced row writes
        float* stg = (float*)smem;
        if (!skipw) {
            #pragma unroll
            for (int mf = 0; mf < 4; mf++)
                #pragma unroll
                for (int nf = 0; nf < 4; nf++) {
                    const float* c = acc[mf][nf];
                    const int rbase = wm * 64 + mf * 16 + (lane >> 2);
                    const int cl = wn * 32 + nf * 8 + (lane & 3) * 2;
                    #pragma unroll
                    for (int hh = 0; hh < 2; hh++) {
                        const int rl = rbase + hh * 8;
                        const float wv = s_wv[rl];
                        stg[rl * 132 + cl]     = c[hh * 2]     * wv;
                        stg[rl * 132 + cl + 1] = c[hh * 2 + 1] * wv;
                    }
                }
        }
        asm volatile("bar.sync 3, 256;" ::: "memory");
        const int rlo = tid >> 3, ch = tid & 7;
        #pragma unroll
        for (int pass = 0; pass < 4; pass++) {
            const int row = pass * 32 + rlo;
            const int tk = s_tok[row];
            if (tk >= 0) {
                float* op = out + (size_t)tk * D_MODEL + nt * 128;
                const float* sp = stg + row * 132;
                #pragma unroll
                for (int j = 0; j < 4; j++) {
                    const int col = j * 32 + ch * 4;
                    float4 v = *(const float4*)(sp + col);
                    *(float4*)(op + col) = v;
                }
            }
        }
    }
}

// ---------------- launch ----------------
extern "C" void kernel_launch(void* const* d_in, const int* in_sizes, int n_in,
                              void* d_out, int out_size) {
    const float* x  = (const float*)d_in[0];
    const float* Wr = (const float*)d_in[1];
    const float* W1 = (const float*)d_in[2];
    const float* W2 = (const float*)d_in[3];
    float* out = (float*)d_out;

    cudaFuncSetAttribute(moe_gemm<1>, cudaFuncAttributeMaxDynamicSharedMemorySize, SMEM_TOT);
    cudaFuncSetAttribute(moe_gemm<2>, cudaFuncAttributeMaxDynamicSharedMemorySize, SMEM_TOT);

    router_kernel<<<T_TOK, 256>>>(x, Wr);
    bucket_kernel<<<1, 1024>>>();
    gather_a_kernel<<<dim3(PM, KT1), 256>>>(x);
    transconv1_kernel<<<dim3(NT1, KT1, NE), 256>>>(W1);
    moe_gemm<1><<<dim3(NT1, MAXT), 352, SMEM_TOT>>>(W2, nullptr);   // tc2 fused in helpers
    moe_gemm<2><<<dim3(NT2, MAXT), 352, SMEM_TOT>>>(W2, out);
}

// round 15
// speedup vs baseline: 5.8941x; 1.0014x over previous
#include <cuda_runtime.h>
#include <cuda_bf16.h>
#include <cuda_fp16.h>
#include <math.h>
#include <stdint.h>

#define T_TOK   4096
#define D_MODEL 2048
#define FF      8192
#define NE      8
#define PM      40
#define MAXT    40
#define KT1     32
#define NT1     64
#define KT2     128
#define NT2     16
#define BLKA    16384   // fp16 plane: 128 rows x 128B

// ---------------- scratch ----------------
__device__ int   g_idx[T_TOK];
__device__ float g_w[T_TOK];
__device__ int   g_order[T_TOK];
__device__ int   g_off[NE + 1];
__device__ int   g_ptok[PM * 128];
__device__ int   g_tile_e[MAXT];
__device__ int   g_tile_gt[MAXT];
__device__ int   g_tile_m64[MAXT];
__device__ int   g_ntiles;

__device__ __align__(128) char g_A [(size_t)PM * KT1 * BLKA];
__device__ __align__(128) char g_B1[(size_t)NE * NT1 * KT1 * BLKA];
__device__ __align__(128) char g_B2[(size_t)NE * NT2 * KT2 * BLKA];
__device__ __align__(128) char g_H [(size_t)PM * KT2 * BLKA];

// ---------------- helpers ----------------
__device__ __forceinline__ uint32_t s2u(const void* p) {
    uint32_t a;
    asm("{ .reg .u64 t; cvta.to.shared.u64 t, %1; cvt.u32.u64 %0, t; }" : "=r"(a) : "l"(p));
    return a;
}
__device__ __forceinline__ uint32_t pack2h(float a, float b) {
    __half2 t = __floats2half2_rn(a, b);
    return *(uint32_t*)&t;
}
__device__ __forceinline__ float gelu_exact(float v) {
    return 0.5f * v * (1.0f + erff(v * 0.70710678118654752440f));
}
__device__ __forceinline__ void mbar_init(uint32_t m, uint32_t c) {
    asm volatile("mbarrier.init.shared::cta.b64 [%0], %1;" :: "r"(m), "r"(c) : "memory");
}
__device__ __forceinline__ void mbar_arrive(uint32_t m) {
    asm volatile("mbarrier.arrive.shared::cta.b64 _, [%0];" :: "r"(m) : "memory");
}
__device__ __forceinline__ void mbar_expect_tx(uint32_t m, uint32_t b) {
    asm volatile("mbarrier.arrive.expect_tx.shared::cta.b64 _, [%0], %1;"
                 :: "r"(m), "r"(b) : "memory");
}
__device__ __forceinline__ void mbar_wait(uint32_t m, uint32_t ph) {
    asm volatile(
        "{\n\t.reg .pred P;\n"
        "W_%=:\n\t"
        "mbarrier.try_wait.parity.acquire.cta.shared::cta.b64 P, [%0], %1, 0x989680;\n\t"
        "@P bra.uni D_%=;\n\t"
        "bra.uni W_%=;\n"
        "D_%=:\n\t}"
        :: "r"(m), "r"(ph) : "memory");
}
__device__ __forceinline__ void bulk_g2s(uint32_t dst, const void* src, uint32_t bytes,
                                         uint32_t mbar) {
    asm volatile(
        "cp.async.bulk.shared::cta.global.mbarrier::complete_tx::bytes [%0], [%1], %2, [%3];"
        :: "r"(dst), "l"(src), "r"(bytes), "r"(mbar) : "memory");
}
__device__ __forceinline__ void bulk_s2g(void* dst, uint32_t src, uint32_t bytes) {
    asm volatile(
        "cp.async.bulk.global.shared::cta.bulk_group [%0], [%1], %2;"
        :: "l"(dst), "r"(src), "r"(bytes) : "memory");
}
__device__ __forceinline__ void ldsm4(uint32_t& r0, uint32_t& r1, uint32_t& r2, uint32_t& r3,
                                      uint32_t a) {
    asm volatile("ldmatrix.sync.aligned.m8n8.x4.shared.b16 {%0,%1,%2,%3}, [%4];"
                 : "=r"(r0), "=r"(r1), "=r"(r2), "=r"(r3) : "r"(a));
}
__device__ __forceinline__ void mma_f16f32(float* d, const uint32_t* a, const uint32_t* b) {
    asm volatile(
        "mma.sync.aligned.m16n8k16.row.col.f32.f16.f16.f32 "
        "{%0,%1,%2,%3}, {%4,%5,%6,%7}, {%8,%9}, {%0,%1,%2,%3};"
        : "+f"(d[0]), "+f"(d[1]), "+f"(d[2]), "+f"(d[3])
        : "r"(a[0]), "r"(a[1]), "r"(a[2]), "r"(a[3]), "r"(b[0]), "r"(b[1]));
}

// ---------------- router ----------------
__global__ void router_kernel(const float* __restrict__ x, const float* __restrict__ Wr) {
    __shared__ float sx[D_MODEL];
    __shared__ float slog[NE];
    const int t = blockIdx.x, tid = threadIdx.x;
    const float* xr = x + (size_t)t * D_MODEL;
    for (int i = tid * 4; i < D_MODEL; i += 256 * 4)
        *(float4*)(sx + i) = *(const float4*)(xr + i);
    __syncthreads();
    const int w = tid >> 5, lane = tid & 31;
    const float* wr = Wr + (size_t)w * D_MODEL;
    float s = 0.f;
    for (int i = lane; i < D_MODEL; i += 32) s += sx[i] * wr[i];
    #pragma unroll
    for (int o = 16; o; o >>= 1) s += __shfl_xor_sync(0xffffffffu, s, o);
    if (lane == 0) slog[w] = s;
    __syncthreads();
    if (tid == 0) {
        float mx = slog[0]; int mi = 0;
        #pragma unroll
        for (int e = 1; e < NE; e++) if (slog[e] > mx) { mx = slog[e]; mi = e; }
        float sum = 0.f;
        #pragma unroll
        for (int e = 0; e < NE; e++) sum += expf(slog[e] - mx);
        g_idx[t] = mi;
        g_w[t] = 1.0f / sum;
    }
}

// ---------------- bucket + tile table + padded token map ----------------
__global__ void bucket_kernel() {
    __shared__ int cnt[NE], off[NE], soff[NE], spo[NE + 1];
    const int tid = threadIdx.x;
    if (tid < NE) cnt[tid] = 0;
    __syncthreads();
    for (int t = tid; t < T_TOK; t += blockDim.x) atomicAdd(&cnt[g_idx[t]], 1);
    __syncthreads();
    if (tid == 0) {
        int acc = 0, pacc = 0, nt = 0;
        #pragma unroll
        for (int e = 0; e < NE; e++) {
            off[e] = acc; soff[e] = acc; g_off[e] = acc;
            spo[e] = pacc;
            int tiles = (cnt[e] + 127) >> 7;
            for (int i = 0; i < tiles; i++) {
                g_tile_e[nt] = e;
                g_tile_gt[nt] = (pacc >> 7) + i;
                g_tile_m64[nt] = (cnt[e] - i * 128) <= 64;
                nt++;
            }
            acc += cnt[e];
            pacc += tiles << 7;
        }
        g_off[NE] = acc;
        spo[NE] = pacc;
        g_ntiles = nt;
    }
    __syncthreads();
    for (int t = tid; t < T_TOK; t += blockDim.x) {
        int p = atomicAdd(&off[g_idx[t]], 1);
        g_order[p] = t;
    }
    __syncthreads();
    for (int p = tid; p < PM * 128; p += blockDim.x) {
        int tk = -1;
        #pragma unroll
        for (int e = 0; e < NE; e++)
            if (p >= spo[e] && p < spo[e] + cnt[e])
                tk = g_order[soff[e] + (p - spo[e])];
        g_ptok[p] = tk;
    }
}

// ---------------- prepass: gather x rows -> swizzled fp16 blocks ----------------
__global__ void __launch_bounds__(256) gather_a_kernel(const float* __restrict__ x) {
    const int gt = blockIdx.x, kt = blockIdx.y;
    const int tid = threadIdx.x;
    const int r = tid >> 1, half = tid & 1;
    const int tok = g_ptok[gt * 128 + r];
    uint32_t fw[16];
    if (tok >= 0) {
        const float4* src = (const float4*)(x + (size_t)tok * D_MODEL + kt * 64 + half * 32);
        #pragma unroll
        for (int q = 0; q < 8; q++) {
            float4 v = src[q];
            fw[q * 2]     = pack2h(v.x, v.y);
            fw[q * 2 + 1] = pack2h(v.z, v.w);
        }
    } else {
        #pragma unroll
        for (int q = 0; q < 16; q++) fw[q] = 0;
    }
    char* blk = g_A + ((size_t)gt * KT1 + kt) * BLKA;
    #pragma unroll
    for (int c = 0; c < 4; c++) {
        int ch = half * 4 + c;
        uint32_t off = (uint32_t)(r * 128) + (uint32_t)((ch ^ (r & 7)) << 4);
        *(uint4*)(blk + off) = ((uint4*)fw)[c];
    }
}

// ---------------- prepass: transpose + convert W1 (single fp16 plane) ----------------
__global__ void __launch_bounds__(256) transconv1_kernel(const float* __restrict__ src) {
    __shared__ float s[64 * 132];
    const int nt = blockIdx.x, kt = blockIdx.y, e = blockIdx.z;
    const int tid = threadIdx.x;
    const float* sp = src + (size_t)e * D_MODEL * FF + (size_t)(kt * 64) * FF + nt * 128;
    #pragma unroll
    for (int i = 0; i < 8; i++) {
        int q = i * 256 + tid;
        int k = q >> 5, c4 = q & 31;
        *(float4*)(s + k * 132 + c4 * 4) = *(const float4*)(sp + (size_t)k * FF + c4 * 4);
    }
    __syncthreads();
    const int n = tid >> 1, half = tid & 1;
    uint32_t hw[16];
    #pragma unroll
    for (int jw = 0; jw < 16; jw++) {
        float v0 = s[(half * 32 + jw * 2) * 132 + n];
        float v1 = s[(half * 32 + jw * 2 + 1) * 132 + n];
        hw[jw] = pack2h(v0, v1);
    }
    char* dst = g_B1 + (((size_t)e * NT1 + nt) * KT1 + kt) * BLKA;
    #pragma unroll
    for (int c = 0; c < 4; c++) {
        int ch = half * 4 + c;
        uint32_t off = (uint32_t)(n * 128) + (uint32_t)((ch ^ (n & 7)) << 4);
        *(uint4*)(dst + off) = ((uint4*)hw)[c];
    }
}

// ---------------- warp-MMA grouped GEMM (pure fp16) + tc2 helpers + staged epilogue --
#define ST_BYTES   32768u
#define SM_TOKOFF  98304
#define SM_WVOFF   98816
#define SM_MBROFF  99328
#define SM_TC      99392           // 32 x 132 fp32 transpose buffer (16,896 B)
#define SMEM_TOT   116288

template <int PHASE>
__global__ void __launch_bounds__(352, 1)
moe_gemm(const float* __restrict__ W2, float* __restrict__ out) {
    constexpr int KT = (PHASE == 1) ? KT1 : KT2;
    const int tix = blockIdx.y;
    const int nt = blockIdx.x;
    const int tid = threadIdx.x;
    const int wid = tid >> 5, lane = tid & 31;

    extern __shared__ char smem[];
    const uint32_t sb = s2u(smem);
    int* s_tok = (int*)(smem + SM_TOKOFF);
    float* s_wv = (float*)(smem + SM_WVOFF);
    const uint32_t mfull = sb + SM_MBROFF;
    const uint32_t mempty = sb + SM_MBROFF + 24;

    // ---------- tc2 helper warps (warps 9,10 = 64 threads) ----------
    if (wid >= 9) {
        if (PHASE == 1 && tix < 32) {
            float* tb = (float*)(smem + SM_TC);
            const int hl = tid - 288;                  // 0..63
            const int bi = nt * 32 + tix;              // 0..2047
            for (int u = 0; u < 8; u++) {
                const int unit = bi * 8 + u;           // 0..16383
                const int e2 = unit >> 11;
                const int rem = unit & 2047;
                const int nt2 = rem >> 7;
                const int kt2 = rem & 127;
                const float* src = W2 + (size_t)e2 * FF * D_MODEL
                                 + (size_t)(kt2 * 64) * D_MODEL + nt2 * 128;
                char* dst = g_B2 + (((size_t)e2 * NT2 + nt2) * KT2 + kt2) * BLKA;
                #pragma unroll
                for (int half = 0; half < 2; half++) {
                    #pragma unroll
                    for (int i = 0; i < 16; i++) {
                        int q = i * 64 + hl;
                        int r = q >> 5, c4 = q & 31;
                        *(float4*)(tb + r * 132 + c4 * 4) =
                            *(const float4*)(src + (size_t)(half * 32 + r) * D_MODEL + c4 * 4);
                    }
                    asm volatile("bar.sync 1, 64;" ::: "memory");
                    #pragma unroll
                    for (int nn = 0; nn < 2; nn++) {
                        const int n = hl * 2 + nn;
                        uint32_t hw[16];
                        #pragma unroll
                        for (int j = 0; j < 16; j++) {
                            float v0 = tb[(j * 2) * 132 + n];
                            float v1 = tb[(j * 2 + 1) * 132 + n];
                            hw[j] = pack2h(v0, v1);
                        }
                        #pragma unroll
                        for (int c = 0; c < 4; c++) {
                            int ch = half * 4 + c;
                            uint32_t off = (uint32_t)(n * 128)
                                         + (uint32_t)((ch ^ (n & 7)) << 4);
                            *(uint4*)(dst + off) = ((uint4*)hw)[c];
                        }
                    }
                    asm volatile("bar.sync 1, 64;" ::: "memory");
                }
            }
        }
        return;
    }

    if (tix >= g_ntiles) return;
    const int e = g_tile_e[tix];
    const int gt = g_tile_gt[tix];
    const int m64 = g_tile_m64[tix];

    if (tid < 128) {
        int tk = g_ptok[gt * 128 + tid];
        s_tok[tid] = tk;
        s_wv[tid] = (tk >= 0) ? g_w[tk] : 0.f;
    }
    if (tid == 0) {
        #pragma unroll
        for (int i = 0; i < 3; i++) { mbar_init(mfull + i * 8, 1); mbar_init(mempty + i * 8, 8); }
    }
    asm volatile("bar.sync 2, 288;" ::: "memory");   // warps 0-8 only

    if (wid == 8) {
        if (lane == 0) {
            const char* srcA = (PHASE == 1) ? (g_A + (size_t)gt * KT1 * BLKA)
                                            : (g_H + (size_t)gt * KT2 * BLKA);
            const char* srcB = (PHASE == 1)
                ? (g_B1 + ((size_t)(e * NT1 + nt)) * KT1 * BLKA)
                : (g_B2 + ((size_t)(e * NT2 + nt)) * KT2 * BLKA);
            int s = 0, r = 0;
            for (int kt = 0; kt < KT; kt++) {
                if (r > 0) mbar_wait(mempty + s * 8, (r - 1) & 1);
                mbar_expect_tx(mfull + s * 8, ST_BYTES);
                uint32_t dst = sb + (uint32_t)s * ST_BYTES;
                bulk_g2s(dst,          srcA + (size_t)kt * BLKA, BLKA, mfull + s * 8);
                bulk_g2s(dst + 16384u, srcB + (size_t)kt * BLKA, BLKA, mfull + s * 8);
                if (++s == 3) { s = 0; r++; }
            }
        }
        return;
    }

    // consumers: wm in [0,2) (64 M-rows), wn in [0,4) (32 N-cols)
    const int wm = wid >> 2, wn = wid & 3;
    const bool skipw = (m64 && wm == 1);

    const int lrA = (lane & 7) + ((lane >> 3) & 1) * 8;
    const int cA0 = lane >> 4;
    uint32_t a_off[4]; int a_rs[4];
    #pragma unroll
    for (int mf = 0; mf < 4; mf++) {
        int rr = wm * 64 + mf * 16 + lrA;
        a_off[mf] = (uint32_t)(rr * 128);
        a_rs[mf] = rr & 7;
    }
    const int lrB = (lane & 7) + ((lane >> 4) << 3);
    const int cB0 = (lane >> 3) & 1;
    uint32_t b_off[2]; int b_rs[2];
    #pragma unroll
    for (int p = 0; p < 2; p++) {
        int rr = wn * 32 + p * 16 + lrB;
        b_off[p] = (uint32_t)(rr * 128);
        b_rs[p] = rr & 7;
    }

    float acc[4][4][4];
    #pragma unroll
    for (int i = 0; i < 4; i++)
        #pragma unroll
        for (int j = 0; j < 4; j++)
            #pragma unroll
            for (int q = 0; q < 4; q++) acc[i][j][q] = 0.f;

    int s = 0, r = 0;
    for (int kt = 0; kt < KT; kt++) {
        mbar_wait(mfull + s * 8, r & 1);
        if (!skipw) {
            const uint32_t stA = sb + (uint32_t)s * ST_BYTES;
            const uint32_t stB = stA + 16384u;
            #pragma unroll
            for (int ks = 0; ks < 4; ks++) {
                uint32_t af[16], bf[8];
                const int cA = cA0 + ks * 2;
                #pragma unroll
                for (int mf = 0; mf < 4; mf++) {
                    uint32_t o = a_off[mf] + (uint32_t)((cA ^ a_rs[mf]) << 4);
                    ldsm4(af[mf*4], af[mf*4+1], af[mf*4+2], af[mf*4+3], stA + o);
                }
                const int cB = cB0 + ks * 2;
                #pragma unroll
                for (int p = 0; p < 2; p++) {
                    uint32_t o = b_off[p] + (uint32_t)((cB ^ b_rs[p]) << 4);
                    ldsm4(bf[p*4], bf[p*4+1], bf[p*4+2], bf[p*4+3], stB + o);
                }
                #pragma unroll
                for (int mf = 0; mf < 4; mf++)
                    #pragma unroll
                    for (int nf = 0; nf < 4; nf++)
                        mma_f16f32(acc[mf][nf], &af[mf * 4], &bf[(nf >> 1) * 4 + (nf & 1) * 2]);
            }
        }
        if (lane == 0) mbar_arrive(mempty + s * 8);
        if (++s == 3) { s = 0; r++; }
    }

    // ---------------- staged epilogue (all 8 consumer warps participate) -------------
    asm volatile("bar.sync 3, 256;" ::: "memory");   // stage smem now safe to reuse
    if (PHASE == 1) {
        if (!skipw) {
            #pragma unroll
            for (int mf = 0; mf < 4; mf++)
                #pragma unroll
                for (int nf = 0; nf < 4; nf++) {
                    const float* c = acc[mf][nf];
                    const int rbase = wm * 64 + mf * 16 + (lane >> 2);
                    const int cl = wn * 32 + nf * 8 + (lane & 3) * 2;
                    const int blk = cl >> 6, kl = cl & 63;
                    #pragma unroll
                    for (int hh = 0; hh < 2; hh++) {
                        const int rl = rbase + hh * 8;
                        float v0 = gelu_exact(c[hh * 2]);
                        float v1 = gelu_exact(c[hh * 2 + 1]);
                        uint32_t off = (uint32_t)(blk * 16384 + rl * 128)
                                     + (uint32_t)((((kl >> 3) ^ (rl & 7)) << 4) + (kl & 7) * 2);
                        *(uint32_t*)(smem + off) = pack2h(v0, v1);
                    }
                }
        }
        asm volatile("bar.sync 3, 256;" ::: "memory");
        if (tid == 0) {
            asm volatile("fence.proxy.async.shared::cta;" ::: "memory");
            char* d0 = g_H + ((size_t)gt * KT2 + nt * 2) * BLKA;
            bulk_s2g(d0,         sb,          16384u);
            bulk_s2g(d0 + BLKA,  sb + 16384u, 16384u);
            asm volatile("cp.async.bulk.commit_group;" ::: "memory");
            asm volatile("cp.async.bulk.wait_group 0;" ::: "memory");
        }
    } else {
        float* stg = (float*)smem;
        if (!skipw) {
            #pragma unroll
            for (int mf = 0; mf < 4; mf++)
                #pragma unroll
                for (int nf = 0; nf < 4; nf++) {
                    const float* c = acc[mf][nf];
                    const int rbase = wm * 64 + mf * 16 + (lane >> 2);
                    const int cl = wn * 32 + nf * 8 + (lane & 3) * 2;
                    #pragma unroll
                    for (int hh = 0; hh < 2; hh++) {
                        const int rl = rbase + hh * 8;
                        const float wv = s_wv[rl];
                        stg[rl * 132 + cl]     = c[hh * 2]     * wv;
                        stg[rl * 132 + cl + 1] = c[hh * 2 + 1] * wv;
                    }
                }
        }
        asm volatile("bar.sync 3, 256;" ::: "memory");
        const int rlo = tid >> 3, ch = tid & 7;
        #pragma unroll
        for (int pass = 0; pass < 4; pass++) {
            const int row = pass * 32 + rlo;
            const int tk = s_tok[row];
            if (tk >= 0) {
                float* op = out + (size_t)tk * D_MODEL + nt * 128;
                const float* sp = stg + row * 132;
                #pragma unroll
                for (int j = 0; j < 4; j++) {
                    const int col = j * 32 + ch * 4;
                    float4 v = *(const float4*)(sp + col);
                    *(float4*)(op + col) = v;
                }
            }
        }
    }
}

// ---------------- launch: fork tc1 parallel to router/bucket/gather ----------------
extern "C" void kernel_launch(void* const* d_in, const int* in_sizes, int n_in,
                              void* d_out, int out_size) {
    const float* x  = (const float*)d_in[0];
    const float* Wr = (const float*)d_in[1];
    const float* W1 = (const float*)d_in[2];
    const float* W2 = (const float*)d_in[3];
    float* out = (float*)d_out;

    cudaFuncSetAttribute(moe_gemm<1>, cudaFuncAttributeMaxDynamicSharedMemorySize, SMEM_TOT);
    cudaFuncSetAttribute(moe_gemm<2>, cudaFuncAttributeMaxDynamicSharedMemorySize, SMEM_TOT);

    cudaStream_t s2;
    cudaEvent_t e1, e2;
    cudaStreamCreateWithFlags(&s2, cudaStreamNonBlocking);
    cudaEventCreateWithFlags(&e1, cudaEventDisableTiming);
    cudaEventCreateWithFlags(&e2, cudaEventDisableTiming);

    // fork: branch B (tc1, big) runs parallel to branch A (router->bucket->gather)
    cudaEventRecord(e1, 0);
    cudaStreamWaitEvent(s2, e1, 0);
    transconv1_kernel<<<dim3(NT1, KT1, NE), 256, 0, s2>>>(W1);
    cudaEventRecord(e2, s2);

    router_kernel<<<T_TOK, 256>>>(x, Wr);
    bucket_kernel<<<1, 1024>>>();
    gather_a_kernel<<<dim3(PM, KT1), 256>>>(x);

    // join before gemm1 (needs both A and B1)
    cudaStreamWaitEvent(0, e2, 0);
    moe_gemm<1><<<dim3(NT1, MAXT), 352, SMEM_TOT>>>(W2, nullptr);   // tc2 fused in helpers
    moe_gemm<2><<<dim3(NT2, MAXT), 352, SMEM_TOT>>>(W2, out);
}

// round 16
// speedup vs baseline: 6.1177x; 1.0379x over previous
#include <cuda_runtime.h>
#include <cuda_bf16.h>
#include <cuda_fp16.h>
#include <math.h>
#include <stdint.h>

#define T_TOK   4096
#define D_MODEL 2048
#define FF      8192
#define NE      8
#define PM      40
#define MAXT    40
#define KT1     32
#define NT1     64
#define KT2     128
#define NT2     16
#define BLKA    16384   // fp16 plane: 128 rows x 128B
#define NBLK    152     // persistent blocks (GB300: 152 SMs)

// ---------------- scratch ----------------
__device__ int   g_idx[T_TOK];
__device__ float g_w[T_TOK];
__device__ int   g_order[T_TOK];
__device__ int   g_off[NE + 1];
__device__ int   g_ptok[PM * 128];
__device__ int   g_tile_e[MAXT];
__device__ int   g_tile_gt[MAXT];
__device__ int   g_tile_m64[MAXT];
__device__ int   g_ntiles;
__device__ int   g_work1;
__device__ int   g_work2;

__device__ __align__(128) char g_A [(size_t)PM * KT1 * BLKA];
__device__ __align__(128) char g_B1[(size_t)NE * NT1 * KT1 * BLKA];
__device__ __align__(128) char g_B2[(size_t)NE * NT2 * KT2 * BLKA];
__device__ __align__(128) char g_H [(size_t)PM * KT2 * BLKA];

// ---------------- helpers ----------------
__device__ __forceinline__ uint32_t s2u(const void* p) {
    uint32_t a;
    asm("{ .reg .u64 t; cvta.to.shared.u64 t, %1; cvt.u32.u64 %0, t; }" : "=r"(a) : "l"(p));
    return a;
}
__device__ __forceinline__ uint32_t pack2h(float a, float b) {
    __half2 t = __floats2half2_rn(a, b);
    return *(uint32_t*)&t;
}
__device__ __forceinline__ float gelu_exact(float v) {
    return 0.5f * v * (1.0f + erff(v * 0.70710678118654752440f));
}
__device__ __forceinline__ void mbar_init(uint32_t m, uint32_t c) {
    asm volatile("mbarrier.init.shared::cta.b64 [%0], %1;" :: "r"(m), "r"(c) : "memory");
}
__device__ __forceinline__ void mbar_arrive(uint32_t m) {
    asm volatile("mbarrier.arrive.shared::cta.b64 _, [%0];" :: "r"(m) : "memory");
}
__device__ __forceinline__ void mbar_expect_tx(uint32_t m, uint32_t b) {
    asm volatile("mbarrier.arrive.expect_tx.shared::cta.b64 _, [%0], %1;"
                 :: "r"(m), "r"(b) : "memory");
}
__device__ __forceinline__ void mbar_wait(uint32_t m, uint32_t ph) {
    asm volatile(
        "{\n\t.reg .pred P;\n"
        "W_%=:\n\t"
        "mbarrier.try_wait.parity.acquire.cta.shared::cta.b64 P, [%0], %1, 0x989680;\n\t"
        "@P bra.uni D_%=;\n\t"
        "bra.uni W_%=;\n"
        "D_%=:\n\t}"
        :: "r"(m), "r"(ph) : "memory");
}
__device__ __forceinline__ void bulk_g2s(uint32_t dst, const void* src, uint32_t bytes,
                                         uint32_t mbar) {
    asm volatile(
        "cp.async.bulk.shared::cta.global.mbarrier::complete_tx::bytes [%0], [%1], %2, [%3];"
        :: "r"(dst), "l"(src), "r"(bytes), "r"(mbar) : "memory");
}
__device__ __forceinline__ void ldsm4(uint32_t& r0, uint32_t& r1, uint32_t& r2, uint32_t& r3,
                                      uint32_t a) {
    asm volatile("ldmatrix.sync.aligned.m8n8.x4.shared.b16 {%0,%1,%2,%3}, [%4];"
                 : "=r"(r0), "=r"(r1), "=r"(r2), "=r"(r3) : "r"(a));
}
__device__ __forceinline__ void mma_f16f32(float* d, const uint32_t* a, const uint32_t* b) {
    asm volatile(
        "mma.sync.aligned.m16n8k16.row.col.f32.f16.f16.f32 "
        "{%0,%1,%2,%3}, {%4,%5,%6,%7}, {%8,%9}, {%0,%1,%2,%3};"
        : "+f"(d[0]), "+f"(d[1]), "+f"(d[2]), "+f"(d[3])
        : "r"(a[0]), "r"(a[1]), "r"(a[2]), "r"(a[3]), "r"(b[0]), "r"(b[1]));
}

// ---------------- router ----------------
__global__ void router_kernel(const float* __restrict__ x, const float* __restrict__ Wr) {
    __shared__ float sx[D_MODEL];
    __shared__ float slog[NE];
    const int t = blockIdx.x, tid = threadIdx.x;
    const float* xr = x + (size_t)t * D_MODEL;
    for (int i = tid * 4; i < D_MODEL; i += 256 * 4)
        *(float4*)(sx + i) = *(const float4*)(xr + i);
    __syncthreads();
    const int w = tid >> 5, lane = tid & 31;
    const float* wr = Wr + (size_t)w * D_MODEL;
    float s = 0.f;
    for (int i = lane; i < D_MODEL; i += 32) s += sx[i] * wr[i];
    #pragma unroll
    for (int o = 16; o; o >>= 1) s += __shfl_xor_sync(0xffffffffu, s, o);
    if (lane == 0) slog[w] = s;
    __syncthreads();
    if (tid == 0) {
        float mx = slog[0]; int mi = 0;
        #pragma unroll
        for (int e = 1; e < NE; e++) if (slog[e] > mx) { mx = slog[e]; mi = e; }
        float sum = 0.f;
        #pragma unroll
        for (int e = 0; e < NE; e++) sum += expf(slog[e] - mx);
        g_idx[t] = mi;
        g_w[t] = 1.0f / sum;
    }
}

// ---------------- bucket + tile table + padded token map + counter reset -------------
__global__ void bucket_kernel() {
    __shared__ int cnt[NE], off[NE], soff[NE], spo[NE + 1];
    const int tid = threadIdx.x;
    if (tid < NE) cnt[tid] = 0;
    __syncthreads();
    for (int t = tid; t < T_TOK; t += blockDim.x) atomicAdd(&cnt[g_idx[t]], 1);
    __syncthreads();
    if (tid == 0) {
        int acc = 0, pacc = 0, nt = 0;
        #pragma unroll
        for (int e = 0; e < NE; e++) {
            off[e] = acc; soff[e] = acc; g_off[e] = acc;
            spo[e] = pacc;
            int tiles = (cnt[e] + 127) >> 7;
            for (int i = 0; i < tiles; i++) {
                g_tile_e[nt] = e;
                g_tile_gt[nt] = (pacc >> 7) + i;
                g_tile_m64[nt] = (cnt[e] - i * 128) <= 64;
                nt++;
            }
            acc += cnt[e];
            pacc += tiles << 7;
        }
        g_off[NE] = acc;
        spo[NE] = pacc;
        g_ntiles = nt;
        g_work1 = 0;
        g_work2 = 0;
    }
    __syncthreads();
    for (int t = tid; t < T_TOK; t += blockDim.x) {
        int p = atomicAdd(&off[g_idx[t]], 1);
        g_order[p] = t;
    }
    __syncthreads();
    for (int p = tid; p < PM * 128; p += blockDim.x) {
        int tk = -1;
        #pragma unroll
        for (int e = 0; e < NE; e++)
            if (p >= spo[e] && p < spo[e] + cnt[e])
                tk = g_order[soff[e] + (p - spo[e])];
        g_ptok[p] = tk;
    }
}

// ---------------- prepass: gather x rows -> swizzled fp16 blocks ----------------
__global__ void __launch_bounds__(256) gather_a_kernel(const float* __restrict__ x) {
    const int gt = blockIdx.x, kt = blockIdx.y;
    const int tid = threadIdx.x;
    const int r = tid >> 1, half = tid & 1;
    const int tok = g_ptok[gt * 128 + r];
    uint32_t fw[16];
    if (tok >= 0) {
        const float4* src = (const float4*)(x + (size_t)tok * D_MODEL + kt * 64 + half * 32);
        #pragma unroll
        for (int q = 0; q < 8; q++) {
            float4 v = src[q];
            fw[q * 2]     = pack2h(v.x, v.y);
            fw[q * 2 + 1] = pack2h(v.z, v.w);
        }
    } else {
        #pragma unroll
        for (int q = 0; q < 16; q++) fw[q] = 0;
    }
    char* blk = g_A + ((size_t)gt * KT1 + kt) * BLKA;
    #pragma unroll
    for (int c = 0; c < 4; c++) {
        int ch = half * 4 + c;
        uint32_t off = (uint32_t)(r * 128) + (uint32_t)((ch ^ (r & 7)) << 4);
        *(uint4*)(blk + off) = ((uint4*)fw)[c];
    }
}

// ---------------- prepass: transpose + convert W1 (single fp16 plane) ----------------
__global__ void __launch_bounds__(256) transconv1_kernel(const float* __restrict__ src) {
    __shared__ float s[64 * 132];
    const int nt = blockIdx.x, kt = blockIdx.y, e = blockIdx.z;
    const int tid = threadIdx.x;
    const float* sp = src + (size_t)e * D_MODEL * FF + (size_t)(kt * 64) * FF + nt * 128;
    #pragma unroll
    for (int i = 0; i < 8; i++) {
        int q = i * 256 + tid;
        int k = q >> 5, c4 = q & 31;
        *(float4*)(s + k * 132 + c4 * 4) = *(const float4*)(sp + (size_t)k * FF + c4 * 4);
    }
    __syncthreads();
    const int n = tid >> 1, half = tid & 1;
    uint32_t hw[16];
    #pragma unroll
    for (int jw = 0; jw < 16; jw++) {
        float v0 = s[(half * 32 + jw * 2) * 132 + n];
        float v1 = s[(half * 32 + jw * 2 + 1) * 132 + n];
        hw[jw] = pack2h(v0, v1);
    }
    char* dst = g_B1 + (((size_t)e * NT1 + nt) * KT1 + kt) * BLKA;
    #pragma unroll
    for (int c = 0; c < 4; c++) {
        int ch = half * 4 + c;
        uint32_t off = (uint32_t)(n * 128) + (uint32_t)((ch ^ (n & 7)) << 4);
        *(uint4*)(dst + off) = ((uint4*)hw)[c];
    }
}

// ---------------- persistent warp-MMA grouped GEMM + tc2 helper warps ----------------
// warps 0-7 consumers, warp 8 producer (tile acquisition + fills), warps 9-10 helpers.
// Stage (32KB): [A fp16 16KB][B fp16 16KB], 3 stages; pipeline runs across tiles.
#define ST_BYTES   32768u
#define SM_SLOT    98304           // 4 x int4 slot ring
#define SM_MBROFF  98368           // mfull 3x8 | mempty 3x8
#define SM_TC      98432           // 32 x 132 fp32 helper transpose buffer
#define SMEM_TOT   115328

template <int PHASE>
__global__ void __launch_bounds__(352, 1)
moe_gemm(const float* __restrict__ W2, float* __restrict__ out) {
    constexpr int KT = (PHASE == 1) ? KT1 : KT2;
    constexpr int NTD = (PHASE == 1) ? NT1 : NT2;
    const int tid = threadIdx.x;
    const int wid = tid >> 5, lane = tid & 31;

    extern __shared__ char smem[];
    const uint32_t sb = s2u(smem);
    int4* slots = (int4*)(smem + SM_SLOT);
    const uint32_t mfull = sb + SM_MBROFF;
    const uint32_t mempty = sb + SM_MBROFF + 24;

    if (tid == 0) {
        #pragma unroll
        for (int i = 0; i < 3; i++) { mbar_init(mfull + i * 8, 1); mbar_init(mempty + i * 8, 8); }
    }
    __syncthreads();

    // ---------- tc2 helper warps (warps 9,10 = 64 threads; gemm1 only) ----------
    if (wid >= 9) {
        if (PHASE == 1) {
            float* tb = (float*)(smem + SM_TC);
            const int hl = tid - 288;                  // 0..63
            for (int unit = blockIdx.x; unit < NE * NT2 * KT2; unit += gridDim.x) {
                const int e2 = unit >> 11;
                const int rem = unit & 2047;
                const int nt2 = rem >> 7;
                const int kt2 = rem & 127;
                const float* src = W2 + (size_t)e2 * FF * D_MODEL
                                 + (size_t)(kt2 * 64) * D_MODEL + nt2 * 128;
                char* dst = g_B2 + (((size_t)e2 * NT2 + nt2) * KT2 + kt2) * BLKA;
                #pragma unroll
                for (int half = 0; half < 2; half++) {
                    #pragma unroll
                    for (int i = 0; i < 16; i++) {
                        int q = i * 64 + hl;
                        int r = q >> 5, c4 = q & 31;
                        *(float4*)(tb + r * 132 + c4 * 4) =
                            *(const float4*)(src + (size_t)(half * 32 + r) * D_MODEL + c4 * 4);
                    }
                    asm volatile("bar.sync 1, 64;" ::: "memory");
                    #pragma unroll
                    for (int nn = 0; nn < 2; nn++) {
                        const int n = hl * 2 + nn;
                        uint32_t hw[16];
                        #pragma unroll
                        for (int j = 0; j < 16; j++) {
                            float v0 = tb[(j * 2) * 132 + n];
                            float v1 = tb[(j * 2 + 1) * 132 + n];
                            hw[j] = pack2h(v0, v1);
                        }
                        #pragma unroll
                        for (int c = 0; c < 4; c++) {
                            int ch = half * 4 + c;
                            uint32_t off = (uint32_t)(n * 128)
                                         + (uint32_t)((ch ^ (n & 7)) << 4);
                            *(uint4*)(dst + off) = ((uint4*)hw)[c];
                        }
                    }
                    asm volatile("bar.sync 1, 64;" ::: "memory");
                }
            }
        }
        return;
    }

    // ---------- producer warp: tile acquisition + continuous fills ----------
    if (wid == 8) {
        if (lane == 0) {
            const int total = NTD * g_ntiles;
            int f = 0;
            for (int seq = 0; ; seq++) {
                const int w = atomicAdd((PHASE == 1) ? &g_work1 : &g_work2, 1);
                int4 info;
                if (w >= total) {
                    info = make_int4(-1, 0, 0, 0);
                } else {
                    const int nt = w % NTD, tix = w / NTD;
                    info = make_int4(nt, g_tile_e[tix], g_tile_gt[tix], g_tile_m64[tix]);
                }
                slots[seq & 3] = info;
                if (info.x < 0) {
                    const int s = f % 3;
                    if (f >= 3) mbar_wait(mempty + s * 8, ((f - 3) / 3) & 1);
                    mbar_arrive(mfull + s * 8);        // sentinel (no tx)
                    break;
                }
                const char* srcA = (PHASE == 1) ? (g_A + (size_t)info.z * KT1 * BLKA)
                                                : (g_H + (size_t)info.z * KT2 * BLKA);
                const char* srcB = (PHASE == 1)
                    ? (g_B1 + ((size_t)(info.y * NT1 + info.x)) * KT1 * BLKA)
                    : (g_B2 + ((size_t)(info.y * NT2 + info.x)) * KT2 * BLKA);
                for (int kt = 0; kt < KT; kt++, f++) {
                    const int s = f % 3;
                    if (f >= 3) mbar_wait(mempty + s * 8, ((f - 3) / 3) & 1);
                    mbar_expect_tx(mfull + s * 8, ST_BYTES);
                    uint32_t dst = sb + (uint32_t)s * ST_BYTES;
                    bulk_g2s(dst,          srcA + (size_t)kt * BLKA, BLKA, mfull + s * 8);
                    bulk_g2s(dst + 16384u, srcB + (size_t)kt * BLKA, BLKA, mfull + s * 8);
                }
            }
        }
        return;
    }

    // ---------- consumer warps: wm in [0,2), wn in [0,4); warp tile 64x32 ----------
    const int wm = wid >> 2, wn = wid & 3;
    const int lrA = (lane & 7) + ((lane >> 3) & 1) * 8;
    const int cA0 = lane >> 4;
    uint32_t a_off[4]; int a_rs[4];
    #pragma unroll
    for (int mf = 0; mf < 4; mf++) {
        int rr = wm * 64 + mf * 16 + lrA;
        a_off[mf] = (uint32_t)(rr * 128);
        a_rs[mf] = rr & 7;
    }
    const int lrB = (lane & 7) + ((lane >> 4) << 3);
    const int cB0 = (lane >> 3) & 1;
    uint32_t b_off[2]; int b_rs[2];
    #pragma unroll
    for (int p = 0; p < 2; p++) {
        int rr = wn * 32 + p * 16 + lrB;
        b_off[p] = (uint32_t)(rr * 128);
        b_rs[p] = rr & 7;
    }

    int c = 0;
    for (int seq = 0; ; seq++) {
        {
            const int s0 = c % 3;
            mbar_wait(mfull + s0 * 8, (c / 3) & 1);
        }
        const int4 info = slots[seq & 3];
        if (info.x < 0) break;
        const int nt = info.x, gt = info.z;
        const bool skipw = (info.w && wm == 1);

        int mytok[8];
        float mywv[8];
        if (PHASE == 2 && !skipw) {
            #pragma unroll
            for (int mf = 0; mf < 4; mf++)
                #pragma unroll
                for (int hh = 0; hh < 2; hh++) {
                    const int rl = wm * 64 + mf * 16 + hh * 8 + (lane >> 2);
                    const int tk = g_ptok[gt * 128 + rl];
                    mytok[mf * 2 + hh] = tk;
                    mywv[mf * 2 + hh] = (tk >= 0) ? g_w[tk] : 0.f;
                }
        }

        float acc[4][4][4];
        #pragma unroll
        for (int i = 0; i < 4; i++)
            #pragma unroll
            for (int j = 0; j < 4; j++)
                #pragma unroll
                for (int q = 0; q < 4; q++) acc[i][j][q] = 0.f;

        for (int kt = 0; kt < KT; kt++) {
            const int s = c % 3;
            if (kt > 0) mbar_wait(mfull + s * 8, (c / 3) & 1);
            if (!skipw) {
                const uint32_t stA = sb + (uint32_t)s * ST_BYTES;
                const uint32_t stB = stA + 16384u;
                #pragma unroll
                for (int ks = 0; ks < 4; ks++) {
                    uint32_t af[16], bf[8];
                    const int cA = cA0 + ks * 2;
                    #pragma unroll
                    for (int mf = 0; mf < 4; mf++) {
                        uint32_t o = a_off[mf] + (uint32_t)((cA ^ a_rs[mf]) << 4);
                        ldsm4(af[mf*4], af[mf*4+1], af[mf*4+2], af[mf*4+3], stA + o);
                    }
                    const int cB = cB0 + ks * 2;
                    #pragma unroll
                    for (int p = 0; p < 2; p++) {
                        uint32_t o = b_off[p] + (uint32_t)((cB ^ b_rs[p]) << 4);
                        ldsm4(bf[p*4], bf[p*4+1], bf[p*4+2], bf[p*4+3], stB + o);
                    }
                    #pragma unroll
                    for (int mf = 0; mf < 4; mf++)
                        #pragma unroll
                        for (int nf = 0; nf < 4; nf++)
                            mma_f16f32(acc[mf][nf], &af[mf * 4],
                                       &bf[(nf >> 1) * 4 + (nf & 1) * 2]);
                }
            }
            if (lane == 0) mbar_arrive(mempty + s * 8);
            c++;
        }

        // ---------------- direct epilogue (overlaps producer's next-tile fills) ------
        if (!skipw) {
            #pragma unroll
            for (int mf = 0; mf < 4; mf++)
                #pragma unroll
                for (int nf = 0; nf < 4; nf++) {
                    const float* cc = acc[mf][nf];
                    const int rbase = wm * 64 + mf * 16 + (lane >> 2);
                    const int ncol = nt * 128 + wn * 32 + nf * 8 + (lane & 3) * 2;
                    #pragma unroll
                    for (int hh = 0; hh < 2; hh++) {
                        const int rl = rbase + hh * 8;
                        if (PHASE == 1) {
                            float v0 = gelu_exact(cc[hh * 2]);
                            float v1 = gelu_exact(cc[hh * 2 + 1]);
                            const int kt2 = ncol >> 6, kl = ncol & 63;
                            char* blk = g_H + ((size_t)gt * KT2 + kt2) * BLKA;
                            uint32_t off = (uint32_t)(rl * 128)
                                         + (uint32_t)((((kl >> 3) ^ (rl & 7)) << 4)
                                                      + (kl & 7) * 2);
                            *(uint32_t*)(blk + off) = pack2h(v0, v1);
                        } else {
                            const int tk = mytok[mf * 2 + hh];
                            if (tk < 0) continue;
                            const float wv = mywv[mf * 2 + hh];
                            float2 o = make_float2(cc[hh * 2] * wv, cc[hh * 2 + 1] * wv);
                            *(float2*)(out + (size_t)tk * D_MODEL + ncol) = o;
                        }
                    }
                }
        }
    }
}

// ---------------- launch ----------------
extern "C" void kernel_launch(void* const* d_in, const int* in_sizes, int n_in,
                              void* d_out, int out_size) {
    const float* x  = (const float*)d_in[0];
    const float* Wr = (const float*)d_in[1];
    const float* W1 = (const float*)d_in[2];
    const float* W2 = (const float*)d_in[3];
    float* out = (float*)d_out;

    cudaFuncSetAttribute(moe_gemm<1>, cudaFuncAttributeMaxDynamicSharedMemorySize, SMEM_TOT);
    cudaFuncSetAttribute(moe_gemm<2>, cudaFuncAttributeMaxDynamicSharedMemorySize, SMEM_TOT);

    cudaStream_t s2;
    cudaEvent_t e1, e2;
    cudaStreamCreateWithFlags(&s2, cudaStreamNonBlocking);
    cudaEventCreateWithFlags(&e1, cudaEventDisableTiming);
    cudaEventCreateWithFlags(&e2, cudaEventDisableTiming);

    cudaEventRecord(e1, 0);
    cudaStreamWaitEvent(s2, e1, 0);
    transconv1_kernel<<<dim3(NT1, KT1, NE), 256, 0, s2>>>(W1);
    cudaEventRecord(e2, s2);

    router_kernel<<<T_TOK, 256>>>(x, Wr);
    bucket_kernel<<<1, 1024>>>();
    gather_a_kernel<<<dim3(PM, KT1), 256>>>(x);

    cudaStreamWaitEvent(0, e2, 0);
    moe_gemm<1><<<NBLK, 352, SMEM_TOT>>>(W2, nullptr);
    moe_gemm<2><<<NBLK, 352, SMEM_TOT>>>(W2, out);
}